// round 1
// baseline (speedup 1.0000x reference)
#include <cuda_runtime.h>
#include <cuda_bf16.h>
#include <math.h>

// ---------------------------------------------------------------------------
// TransformerBlock baseline: fp32 tiled SGEMM + materialized attention.
// B=2, S=2048, D=1024, H=16, Dh=64, FF=4096.
// ---------------------------------------------------------------------------

#define D_MODEL 1024
#define SEQ     2048
#define BATCH   2
#define NHEADS  16
#define HEADDIM 64
#define D_FF    4096
#define NROWS   (BATCH * SEQ)          // 4096
#define NBH     (BATCH * NHEADS)       // 32

// ------------------------- scratch (no allocations) ------------------------
__device__ float g_h   [NROWS * D_MODEL];                 // LN output (reused)
__device__ float g_q   [NROWS * D_MODEL];
__device__ float g_k   [NROWS * D_MODEL];
__device__ float g_v   [NROWS * D_MODEL];
__device__ float g_attn[NROWS * D_MODEL];
__device__ float g_x1  [NROWS * D_MODEL];
__device__ float g_ff  [NROWS * D_FF];
__device__ float g_scores[(size_t)NBH * SEQ * SEQ];       // 512 MB

// --------------------------------- LayerNorm --------------------------------
__global__ __launch_bounds__(256) void ln_kernel(
    const float* __restrict__ x, const float* __restrict__ scale,
    const float* __restrict__ bias, float* __restrict__ y)
{
    const int row = blockIdx.x;
    const int tid = threadIdx.x;
    const float* xr = x + (size_t)row * D_MODEL;
    float* yr = y + (size_t)row * D_MODEL;

    float4 v = *(const float4*)(xr + tid * 4);
    float s  = v.x + v.y + v.z + v.w;
    float sq = v.x*v.x + v.y*v.y + v.z*v.z + v.w*v.w;

    // warp reduce
    #pragma unroll
    for (int o = 16; o > 0; o >>= 1) {
        s  += __shfl_xor_sync(0xffffffffu, s,  o);
        sq += __shfl_xor_sync(0xffffffffu, sq, o);
    }
    __shared__ float rs[8], rq[8];
    int w = tid >> 5, l = tid & 31;
    if (l == 0) { rs[w] = s; rq[w] = sq; }
    __syncthreads();
    float ts = 0.f, tq = 0.f;
    #pragma unroll
    for (int i = 0; i < 8; i++) { ts += rs[i]; tq += rq[i]; }
    float mean = ts * (1.0f / D_MODEL);
    float var  = tq * (1.0f / D_MODEL) - mean * mean;
    float inv  = rsqrtf(var + 1e-6f);

    int c = tid * 4;
    float4 o;
    o.x = (v.x - mean) * inv * scale[c+0] + bias[c+0];
    o.y = (v.y - mean) * inv * scale[c+1] + bias[c+1];
    o.z = (v.z - mean) * inv * scale[c+2] + bias[c+2];
    o.w = (v.w - mean) * inv * scale[c+3] + bias[c+3];
    *(float4*)(yr + c) = o;
}

// --------------------------------- SGEMM ------------------------------------
// C[M,N] = A[M,K] @ B[K,N] + bias, EPI: 0 = bias, 1 = bias+relu, 2 = bias+res
template<int EPI>
__global__ __launch_bounds__(256) void sgemm_kernel(
    const float* __restrict__ A, const float* __restrict__ B,
    const float* __restrict__ bias, const float* __restrict__ res,
    float* __restrict__ C, int M, int N, int K)
{
    __shared__ float As[8][128];
    __shared__ float Bs[8][128];

    const int tid = threadIdx.x;
    const int bm = blockIdx.y * 128;
    const int bn = blockIdx.x * 128;

    const int arow = tid >> 1;
    const int acol = (tid & 1) * 4;
    const int brow = tid >> 5;
    const int bcol = (tid & 31) * 4;

    const int w = tid >> 5, l = tid & 31;
    const int ty = (w >> 1) * 32 + (l >> 3) * 8;
    const int tx = (w & 1) * 64 + (l & 7) * 8;

    float acc[8][8] = {};
    float ra[8], rb[8];

    for (int k0 = 0; k0 < K; k0 += 8) {
        float4 a4 = *(const float4*)(A + (size_t)(bm + arow) * K + k0 + acol);
        As[acol+0][arow] = a4.x;
        As[acol+1][arow] = a4.y;
        As[acol+2][arow] = a4.z;
        As[acol+3][arow] = a4.w;
        float4 b4 = *(const float4*)(B + (size_t)(k0 + brow) * N + bn + bcol);
        *(float4*)&Bs[brow][bcol] = b4;
        __syncthreads();
        #pragma unroll
        for (int kk = 0; kk < 8; kk++) {
            #pragma unroll
            for (int i = 0; i < 8; i += 4) *(float4*)&ra[i] = *(const float4*)&As[kk][ty + i];
            #pragma unroll
            for (int j = 0; j < 8; j += 4) *(float4*)&rb[j] = *(const float4*)&Bs[kk][tx + j];
            #pragma unroll
            for (int i = 0; i < 8; i++)
                #pragma unroll
                for (int j = 0; j < 8; j++)
                    acc[i][j] = fmaf(ra[i], rb[j], acc[i][j]);
        }
        __syncthreads();
    }

    #pragma unroll
    for (int i = 0; i < 8; i++) {
        const int row = bm + ty + i;
        #pragma unroll
        for (int j = 0; j < 8; j += 4) {
            const int col = bn + tx + j;
            float4 c4;
            c4.x = acc[i][j+0] + bias[col+0];
            c4.y = acc[i][j+1] + bias[col+1];
            c4.z = acc[i][j+2] + bias[col+2];
            c4.w = acc[i][j+3] + bias[col+3];
            if (EPI == 1) {
                c4.x = fmaxf(c4.x, 0.f); c4.y = fmaxf(c4.y, 0.f);
                c4.z = fmaxf(c4.z, 0.f); c4.w = fmaxf(c4.w, 0.f);
            }
            if (EPI == 2) {
                float4 r4 = *(const float4*)(res + (size_t)row * N + col);
                c4.x += r4.x; c4.y += r4.y; c4.z += r4.z; c4.w += r4.w;
            }
            *(float4*)(C + (size_t)row * N + col) = c4;
        }
    }
}

// --------------------------- scores = Q @ K^T (per bh) -----------------------
__global__ __launch_bounds__(256) void scores_kernel(
    const float* __restrict__ q, const float* __restrict__ kk,
    float* __restrict__ s)
{
    const int bh = blockIdx.z;
    const int b = bh >> 4, h = bh & 15;
    const float* Q = q + (size_t)b * SEQ * D_MODEL + h * HEADDIM;
    const float* K = kk + (size_t)b * SEQ * D_MODEL + h * HEADDIM;
    float* C = s + (size_t)bh * SEQ * SEQ;

    const int tid = threadIdx.x;
    const int bm = blockIdx.y * 128;
    const int bn = blockIdx.x * 128;

    __shared__ float As[8][128];
    __shared__ float Bs[8][128];

    const int lrow = tid >> 1;
    const int lcol = (tid & 1) * 4;
    const int w = tid >> 5, l = tid & 31;
    const int ty = (w >> 1) * 32 + (l >> 3) * 8;
    const int tx = (w & 1) * 64 + (l & 7) * 8;

    float acc[8][8] = {};
    float ra[8], rb[8];

    for (int k0 = 0; k0 < HEADDIM; k0 += 8) {
        float4 a4 = *(const float4*)(Q + (size_t)(bm + lrow) * D_MODEL + k0 + lcol);
        As[lcol+0][lrow] = a4.x; As[lcol+1][lrow] = a4.y;
        As[lcol+2][lrow] = a4.z; As[lcol+3][lrow] = a4.w;
        float4 b4 = *(const float4*)(K + (size_t)(bn + lrow) * D_MODEL + k0 + lcol);
        Bs[lcol+0][lrow] = b4.x; Bs[lcol+1][lrow] = b4.y;
        Bs[lcol+2][lrow] = b4.z; Bs[lcol+3][lrow] = b4.w;
        __syncthreads();
        #pragma unroll
        for (int kq = 0; kq < 8; kq++) {
            #pragma unroll
            for (int i = 0; i < 8; i += 4) *(float4*)&ra[i] = *(const float4*)&As[kq][ty + i];
            #pragma unroll
            for (int j = 0; j < 8; j += 4) *(float4*)&rb[j] = *(const float4*)&Bs[kq][tx + j];
            #pragma unroll
            for (int i = 0; i < 8; i++)
                #pragma unroll
                for (int j = 0; j < 8; j++)
                    acc[i][j] = fmaf(ra[i], rb[j], acc[i][j]);
        }
        __syncthreads();
    }

    #pragma unroll
    for (int i = 0; i < 8; i++) {
        #pragma unroll
        for (int j = 0; j < 8; j += 4) {
            float4 c4 = { acc[i][j+0], acc[i][j+1], acc[i][j+2], acc[i][j+3] };
            *(float4*)(C + (size_t)(bm + ty + i) * SEQ + bn + tx + j) = c4;
        }
    }
}

// ------------------------------ row softmax ---------------------------------
__global__ __launch_bounds__(256) void softmax_kernel(float* __restrict__ s)
{
    float* p = s + (size_t)blockIdx.x * SEQ;
    const int tid = threadIdx.x;
    const float sc = 0.125f;   // 1/sqrt(64)

    float4 a = *(const float4*)(p + tid * 4);
    float4 b = *(const float4*)(p + 1024 + tid * 4);
    a.x *= sc; a.y *= sc; a.z *= sc; a.w *= sc;
    b.x *= sc; b.y *= sc; b.z *= sc; b.w *= sc;

    float m = fmaxf(fmaxf(fmaxf(a.x, a.y), fmaxf(a.z, a.w)),
                    fmaxf(fmaxf(b.x, b.y), fmaxf(b.z, b.w)));
    #pragma unroll
    for (int o = 16; o > 0; o >>= 1) m = fmaxf(m, __shfl_xor_sync(0xffffffffu, m, o));
    __shared__ float red[8];
    int w = tid >> 5, l = tid & 31;
    if (l == 0) red[w] = m;
    __syncthreads();
    float bm = red[0];
    #pragma unroll
    for (int i = 1; i < 8; i++) bm = fmaxf(bm, red[i]);

    a.x = __expf(a.x - bm); a.y = __expf(a.y - bm);
    a.z = __expf(a.z - bm); a.w = __expf(a.w - bm);
    b.x = __expf(b.x - bm); b.y = __expf(b.y - bm);
    b.z = __expf(b.z - bm); b.w = __expf(b.w - bm);

    float sum = a.x + a.y + a.z + a.w + b.x + b.y + b.z + b.w;
    #pragma unroll
    for (int o = 16; o > 0; o >>= 1) sum += __shfl_xor_sync(0xffffffffu, sum, o);
    __syncthreads();
    if (l == 0) red[w] = sum;
    __syncthreads();
    float tot = 0.f;
    #pragma unroll
    for (int i = 0; i < 8; i++) tot += red[i];
    float inv = 1.0f / tot;

    a.x *= inv; a.y *= inv; a.z *= inv; a.w *= inv;
    b.x *= inv; b.y *= inv; b.z *= inv; b.w *= inv;
    *(float4*)(p + tid * 4) = a;
    *(float4*)(p + 1024 + tid * 4) = b;
}

// ----------------------- out = P @ V (per bh, N=64) --------------------------
__global__ __launch_bounds__(256) void av_kernel(
    const float* __restrict__ pm, const float* __restrict__ v,
    float* __restrict__ o)
{
    const int bh = blockIdx.z;
    const int b = bh >> 4, h = bh & 15;
    const float* P = pm + (size_t)bh * SEQ * SEQ;
    const float* V = v + (size_t)b * SEQ * D_MODEL + h * HEADDIM;
    float* O = o + (size_t)b * SEQ * D_MODEL + h * HEADDIM;

    const int tid = threadIdx.x;
    const int bm = blockIdx.y * 128;

    __shared__ float Ps[16][128];
    __shared__ float Vs[16][64];

    const int w = tid >> 5, l = tid & 31;
    const int ty = (w >> 1) * 32 + (l >> 3) * 8;   // 0..120
    const int tx = (w & 1) * 32 + (l & 7) * 4;     // 0..60

    float acc[8][4] = {};
    float ra[8], rb[4];

    for (int k0 = 0; k0 < SEQ; k0 += 16) {
        // P tile: 128 rows x 16 cols, store transposed
        #pragma unroll
        for (int it = 0; it < 2; it++) {
            int idx = tid + it * 256;            // float4 index
            int row = idx >> 2;
            int col = (idx & 3) * 4;
            float4 p4 = *(const float4*)(P + (size_t)(bm + row) * SEQ + k0 + col);
            Ps[col+0][row] = p4.x; Ps[col+1][row] = p4.y;
            Ps[col+2][row] = p4.z; Ps[col+3][row] = p4.w;
        }
        // V tile: 16 rows x 64 cols
        {
            int row = tid >> 4;
            int col = (tid & 15) * 4;
            *(float4*)&Vs[row][col] =
                *(const float4*)(V + (size_t)(k0 + row) * D_MODEL + col);
        }
        __syncthreads();
        #pragma unroll
        for (int kq = 0; kq < 16; kq++) {
            #pragma unroll
            for (int i = 0; i < 8; i += 4) *(float4*)&ra[i] = *(const float4*)&Ps[kq][ty + i];
            *(float4*)&rb[0] = *(const float4*)&Vs[kq][tx];
            #pragma unroll
            for (int i = 0; i < 8; i++)
                #pragma unroll
                for (int j = 0; j < 4; j++)
                    acc[i][j] = fmaf(ra[i], rb[j], acc[i][j]);
        }
        __syncthreads();
    }

    #pragma unroll
    for (int i = 0; i < 8; i++) {
        float4 c4 = { acc[i][0], acc[i][1], acc[i][2], acc[i][3] };
        *(float4*)(O + (size_t)(bm + ty + i) * D_MODEL + tx) = c4;
    }
}

// --------------------------------- launch -----------------------------------
extern "C" void kernel_launch(void* const* d_in, const int* in_sizes, int n_in,
                              void* d_out, int out_size)
{
    const float* x   = (const float*)d_in[0];
    const float* Wq  = (const float*)d_in[1];
    const float* bq  = (const float*)d_in[2];
    const float* Wk  = (const float*)d_in[3];
    const float* bk  = (const float*)d_in[4];
    const float* Wv  = (const float*)d_in[5];
    const float* bv  = (const float*)d_in[6];
    const float* Wo  = (const float*)d_in[7];
    const float* bo  = (const float*)d_in[8];
    const float* W1  = (const float*)d_in[9];
    const float* b1  = (const float*)d_in[10];
    const float* W2  = (const float*)d_in[11];
    const float* b2  = (const float*)d_in[12];
    const float* ln1s = (const float*)d_in[13];
    const float* ln1b = (const float*)d_in[14];
    const float* ln2s = (const float*)d_in[15];
    const float* ln2b = (const float*)d_in[16];
    float* out = (float*)d_out;

    float *h, *q, *k, *v, *attn, *x1, *ff, *scores;
    cudaGetSymbolAddress((void**)&h,     g_h);
    cudaGetSymbolAddress((void**)&q,     g_q);
    cudaGetSymbolAddress((void**)&k,     g_k);
    cudaGetSymbolAddress((void**)&v,     g_v);
    cudaGetSymbolAddress((void**)&attn,  g_attn);
    cudaGetSymbolAddress((void**)&x1,    g_x1);
    cudaGetSymbolAddress((void**)&ff,    g_ff);
    cudaGetSymbolAddress((void**)&scores,g_scores);

    // 1) LN1
    ln_kernel<<<NROWS, 256>>>(x, ln1s, ln1b, h);

    // 2) Q, K, V projections
    dim3 gproj(D_MODEL / 128, NROWS / 128);
    sgemm_kernel<0><<<gproj, 256>>>(h, Wq, bq, nullptr, q, NROWS, D_MODEL, D_MODEL);
    sgemm_kernel<0><<<gproj, 256>>>(h, Wk, bk, nullptr, k, NROWS, D_MODEL, D_MODEL);
    sgemm_kernel<0><<<gproj, 256>>>(h, Wv, bv, nullptr, v, NROWS, D_MODEL, D_MODEL);

    // 3) scores = Q K^T
    scores_kernel<<<dim3(SEQ/128, SEQ/128, NBH), 256>>>(q, k, scores);

    // 4) softmax (with 1/sqrt(Dh) scale)
    softmax_kernel<<<NBH * SEQ, 256>>>(scores);

    // 5) attn_out = P V
    av_kernel<<<dim3(1, SEQ/128, NBH), 256>>>(scores, v, attn);

    // 6) x1 = x + attn @ Wo + bo
    sgemm_kernel<2><<<gproj, 256>>>(attn, Wo, bo, x, x1, NROWS, D_MODEL, D_MODEL);

    // 7) LN2
    ln_kernel<<<NROWS, 256>>>(x1, ln2s, ln2b, h);

    // 8) ff = relu(h @ W1 + b1)
    sgemm_kernel<1><<<dim3(D_FF/128, NROWS/128), 256>>>(h, W1, b1, nullptr, ff, NROWS, D_FF, D_MODEL);

    // 9) out = x1 + ff @ W2 + b2
    sgemm_kernel<2><<<dim3(D_MODEL/128, NROWS/128), 256>>>(ff, W2, b2, x1, out, NROWS, D_MODEL, D_FF);
}

// round 4
// speedup vs baseline: 1.8144x; 1.8144x over previous
#include <cuda_runtime.h>
#include <cuda_bf16.h>
#include <cstdint>
#include <math.h>

// ---------------------------------------------------------------------------
// TransformerBlock: mma.sync bf16-split GEMMs (HMMA) + fp32 attention.
// B=2, S=2048, D=1024, H=16, Dh=64, FF=4096.
// ---------------------------------------------------------------------------

#define D_MODEL 1024
#define SEQ     2048
#define BATCH   2
#define NHEADS  16
#define HEADDIM 64
#define D_FF    4096
#define NROWS   (BATCH * SEQ)          // 4096
#define NBH     (BATCH * NHEADS)       // 32

// ------------------------- scratch (no allocations) ------------------------
__device__ float g_h   [NROWS * D_MODEL];
__device__ float g_q   [NROWS * D_MODEL];
__device__ float g_k   [NROWS * D_MODEL];
__device__ float g_v   [NROWS * D_MODEL];
__device__ float g_attn[NROWS * D_MODEL];
__device__ float g_x1  [NROWS * D_MODEL];
__device__ float g_ff  [NROWS * D_FF];
__device__ float g_scores[(size_t)NBH * SEQ * SEQ];       // 512 MB

// bf16 hi/lo split buffers
__device__ __nv_bfloat16 g_wqT_hi[D_MODEL * D_MODEL];
__device__ __nv_bfloat16 g_wqT_lo[D_MODEL * D_MODEL];
__device__ __nv_bfloat16 g_wkT_hi[D_MODEL * D_MODEL];
__device__ __nv_bfloat16 g_wkT_lo[D_MODEL * D_MODEL];
__device__ __nv_bfloat16 g_wvT_hi[D_MODEL * D_MODEL];
__device__ __nv_bfloat16 g_wvT_lo[D_MODEL * D_MODEL];
__device__ __nv_bfloat16 g_woT_hi[D_MODEL * D_MODEL];
__device__ __nv_bfloat16 g_woT_lo[D_MODEL * D_MODEL];
__device__ __nv_bfloat16 g_w1T_hi[D_FF * D_MODEL];
__device__ __nv_bfloat16 g_w1T_lo[D_FF * D_MODEL];
__device__ __nv_bfloat16 g_w2T_hi[D_MODEL * D_FF];
__device__ __nv_bfloat16 g_w2T_lo[D_MODEL * D_FF];
__device__ __nv_bfloat16 g_act_hi[(size_t)NROWS * D_FF];
__device__ __nv_bfloat16 g_act_lo[(size_t)NROWS * D_FF];

// ------------------------------- PTX helpers --------------------------------
__device__ __forceinline__ uint32_t smem_u32(const void* p) {
    uint32_t a;
    asm("{ .reg .u64 t; cvta.to.shared.u64 t, %1; cvt.u32.u64 %0, t; }"
        : "=r"(a) : "l"(p));
    return a;
}

#define SMEM_SWZ128(off) ((off) ^ (((off) >> 3) & 0x70))

__device__ __forceinline__ void cp_async16(uint32_t dst, const void* src) {
    asm volatile("cp.async.cg.shared.global [%0], [%1], 16;"
                 :: "r"(dst), "l"(__cvta_generic_to_global(src)) : "memory");
}
#define CP_COMMIT() asm volatile("cp.async.commit_group;" ::: "memory")
#define CP_WAIT2()  asm volatile("cp.async.wait_group 2;" ::: "memory")

__device__ __forceinline__ void ldmatrix_x4(uint32_t* r, uint32_t addr) {
    asm volatile("ldmatrix.sync.aligned.m8n8.x4.shared.b16 {%0,%1,%2,%3}, [%4];"
                 : "=r"(r[0]), "=r"(r[1]), "=r"(r[2]), "=r"(r[3]) : "r"(addr));
}

__device__ __forceinline__ void mma_bf16(float* c, const uint32_t* a, const uint32_t* b) {
    asm volatile(
        "mma.sync.aligned.m16n8k16.row.col.f32.bf16.bf16.f32 "
        "{%0,%1,%2,%3}, {%4,%5,%6,%7}, {%8,%9}, {%0,%1,%2,%3};"
        : "+f"(c[0]), "+f"(c[1]), "+f"(c[2]), "+f"(c[3])
        : "r"(a[0]), "r"(a[1]), "r"(a[2]), "r"(a[3]), "r"(b[0]), "r"(b[1]));
}

// ----------------------------- HMMA GEMM ------------------------------------
// C[M,N] = A[M,K] @ B^T[N,K] (hi/lo split) + bias, EPI: 0=bias 1=bias+relu 2=bias+res
#define STAGES      3
#define KC          64
#define TILE_BYTES  16384            // 128 rows x 128B (64 bf16 K-chunk)
#define STAGE_BYTES (4 * TILE_BYTES) // Ahi, Alo, Bhi, Blo
#define SMEM_BYTES  (STAGES * STAGE_BYTES + 1024)

__device__ __forceinline__ void load_stage(
    uint32_t st_base,
    const __nv_bfloat16* __restrict__ Ahi, const __nv_bfloat16* __restrict__ Alo,
    const __nv_bfloat16* __restrict__ Bhi, const __nv_bfloat16* __restrict__ Blo,
    int bm, int bn, int k0, int K, int tid)
{
    #pragma unroll
    for (int i = 0; i < 16; i++) {
        int id  = tid + i * 256;          // 0..4095
        int mat = id >> 10;               // constant per i
        int r   = (id & 1023) >> 3;
        int c   = id & 7;
        uint32_t off = SMEM_SWZ128((uint32_t)(r * 128 + c * 16));
        uint32_t dst = st_base + mat * TILE_BYTES + off;
        const __nv_bfloat16* src;
        if (mat == 0)      src = Ahi + (size_t)(bm + r) * K + k0 + c * 8;
        else if (mat == 1) src = Alo + (size_t)(bm + r) * K + k0 + c * 8;
        else if (mat == 2) src = Bhi + (size_t)(bn + r) * K + k0 + c * 8;
        else               src = Blo + (size_t)(bn + r) * K + k0 + c * 8;
        cp_async16(dst, src);
    }
}

// one (A-tile, B-tile) pass over a KC=64 chunk: 4 k-steps of 16
__device__ __forceinline__ void mma_pass(
    float acc[2][8][4], uint32_t Abase, uint32_t Bbase, int wm, int wn, int l)
{
    const int a_row  = wm * 32 + (l & 7) + ((l >> 3) & 1) * 8;   // + mt*16
    const int a_kblk = ((l >> 4) & 1) * 8;                       // halves
    const int b_row  = wn * 64 + ((l >> 4) & 1) * 8 + (l & 7);   // + np*16
    const int b_kblk = ((l >> 3) & 1) * 8;

    #pragma unroll
    for (int ks = 0; ks < 4; ks++) {
        const int k0 = ks * 16;
        uint32_t a[2][4];
        #pragma unroll
        for (int mt = 0; mt < 2; mt++) {
            uint32_t off = SMEM_SWZ128((uint32_t)((a_row + mt * 16) * 128 + (k0 + a_kblk) * 2));
            ldmatrix_x4(a[mt], Abase + off);
        }
        uint32_t b[8][2];
        #pragma unroll
        for (int np = 0; np < 4; np++) {
            uint32_t r[4];
            uint32_t off = SMEM_SWZ128((uint32_t)((b_row + np * 16) * 128 + (k0 + b_kblk) * 2));
            ldmatrix_x4(r, Bbase + off);
            b[np * 2 + 0][0] = r[0]; b[np * 2 + 0][1] = r[1];
            b[np * 2 + 1][0] = r[2]; b[np * 2 + 1][1] = r[3];
        }
        #pragma unroll
        for (int mt = 0; mt < 2; mt++)
            #pragma unroll
            for (int nt = 0; nt < 8; nt++)
                mma_bf16(acc[mt][nt], a[mt], b[nt]);
    }
}

template<int EPI>
__global__ __launch_bounds__(256, 1) void mma_gemm(
    const __nv_bfloat16* __restrict__ Ahi, const __nv_bfloat16* __restrict__ Alo,
    const __nv_bfloat16* __restrict__ Bhi, const __nv_bfloat16* __restrict__ Blo,
    const float* __restrict__ bias, const float* __restrict__ res,
    float* __restrict__ C, int M, int N, int K)
{
    extern __shared__ char dsm[];
    const uint32_t smbase = (smem_u32(dsm) + 1023u) & ~1023u;

    const int tid = threadIdx.x;
    const int wid = tid >> 5;
    const int l   = tid & 31;
    const int wm  = wid & 3;          // 4 warps along M (32 rows each)
    const int wn  = wid >> 2;         // 2 warps along N (64 cols each)
    const int bm  = blockIdx.y * 128;
    const int bn  = blockIdx.x * 128;
    const int NK  = K / KC;

    float acc[2][8][4] = {};

    // prologue: fill the pipeline
    #pragma unroll
    for (int kc = 0; kc < STAGES; kc++) {
        load_stage(smbase + kc * STAGE_BYTES, Ahi, Alo, Bhi, Blo, bm, bn, kc * KC, K, tid);
        CP_COMMIT();
    }

    for (int kc = 0; kc < NK; kc++) {
        const int s = kc % STAGES;
        const uint32_t st = smbase + s * STAGE_BYTES;
        CP_WAIT2();
        __syncthreads();

        const uint32_t Ahi_s = st;
        const uint32_t Alo_s = st + TILE_BYTES;
        const uint32_t Bhi_s = st + 2 * TILE_BYTES;
        const uint32_t Blo_s = st + 3 * TILE_BYTES;
        mma_pass(acc, Ahi_s, Bhi_s, wm, wn, l);
        mma_pass(acc, Ahi_s, Blo_s, wm, wn, l);
        mma_pass(acc, Alo_s, Bhi_s, wm, wn, l);

        __syncthreads();
        if (kc + STAGES < NK)
            load_stage(st, Ahi, Alo, Bhi, Blo, bm, bn, (kc + STAGES) * KC, K, tid);
        CP_COMMIT();
    }

    // epilogue: C fragment m16n8 -> (row g / g+8, col 2t)
    const int g = l >> 2;
    const int t2 = (l & 3) * 2;
    #pragma unroll
    for (int mt = 0; mt < 2; mt++) {
        const int r0 = bm + wm * 32 + mt * 16 + g;
        #pragma unroll
        for (int nt = 0; nt < 8; nt++) {
            const int col = bn + wn * 64 + nt * 8 + t2;
            float2 p0 = { acc[mt][nt][0] + bias[col], acc[mt][nt][1] + bias[col + 1] };
            float2 p1 = { acc[mt][nt][2] + bias[col], acc[mt][nt][3] + bias[col + 1] };
            if (EPI == 1) {
                p0.x = fmaxf(p0.x, 0.f); p0.y = fmaxf(p0.y, 0.f);
                p1.x = fmaxf(p1.x, 0.f); p1.y = fmaxf(p1.y, 0.f);
            }
            if (EPI == 2) {
                float2 q0 = *(const float2*)(res + (size_t)r0 * N + col);
                float2 q1 = *(const float2*)(res + (size_t)(r0 + 8) * N + col);
                p0.x += q0.x; p0.y += q0.y;
                p1.x += q1.x; p1.y += q1.y;
            }
            *(float2*)(C + (size_t)r0 * N + col) = p0;
            *(float2*)(C + (size_t)(r0 + 8) * N + col) = p1;
        }
    }
}

// --------------------------- conversion kernels ------------------------------
__device__ __forceinline__ uint32_t pack_bf2(__nv_bfloat16 a, __nv_bfloat16 b) {
    return (uint32_t)__bfloat16_as_ushort(a) | ((uint32_t)__bfloat16_as_ushort(b) << 16);
}

__global__ __launch_bounds__(256) void conv_act(
    const float4* __restrict__ x, uint2* __restrict__ hi, uint2* __restrict__ lo, int n4)
{
    int i = blockIdx.x * 256 + threadIdx.x;
    if (i >= n4) return;
    float4 v = x[i];
    __nv_bfloat16 h0 = __float2bfloat16(v.x);
    __nv_bfloat16 h1 = __float2bfloat16(v.y);
    __nv_bfloat16 h2 = __float2bfloat16(v.z);
    __nv_bfloat16 h3 = __float2bfloat16(v.w);
    __nv_bfloat16 l0 = __float2bfloat16(v.x - __bfloat162float(h0));
    __nv_bfloat16 l1 = __float2bfloat16(v.y - __bfloat162float(h1));
    __nv_bfloat16 l2 = __float2bfloat16(v.z - __bfloat162float(h2));
    __nv_bfloat16 l3 = __float2bfloat16(v.w - __bfloat162float(h3));
    uint2 ph = { pack_bf2(h0, h1), pack_bf2(h2, h3) };
    uint2 pl = { pack_bf2(l0, l1), pack_bf2(l2, l3) };
    hi[i] = ph;
    lo[i] = pl;
}

// W [K,N] fp32 -> T [N,K] bf16 hi/lo
__global__ __launch_bounds__(256) void conv_wT(
    const float* __restrict__ W, __nv_bfloat16* __restrict__ Thi,
    __nv_bfloat16* __restrict__ Tlo, int K, int N)
{
    __shared__ float t[32][33];
    const int n0 = blockIdx.x * 32, k0 = blockIdx.y * 32;
    const int tx = threadIdx.x & 31, ty8 = threadIdx.x >> 5;
    #pragma unroll
    for (int j = 0; j < 4; j++) {
        int ky = ty8 + j * 8;
        t[ky][tx] = W[(size_t)(k0 + ky) * N + n0 + tx];
    }
    __syncthreads();
    #pragma unroll
    for (int j = 0; j < 4; j++) {
        int ny = ty8 + j * 8;
        float x = t[tx][ny];
        __nv_bfloat16 h = __float2bfloat16(x);
        Thi[(size_t)(n0 + ny) * K + k0 + tx] = h;
        Tlo[(size_t)(n0 + ny) * K + k0 + tx] = __float2bfloat16(x - __bfloat162float(h));
    }
}

// --------------------------------- LayerNorm --------------------------------
__global__ __launch_bounds__(256) void ln_kernel(
    const float* __restrict__ x, const float* __restrict__ scale,
    const float* __restrict__ bias, float* __restrict__ y)
{
    const int row = blockIdx.x;
    const int tid = threadIdx.x;
    const float* xr = x + (size_t)row * D_MODEL;
    float* yr = y + (size_t)row * D_MODEL;

    float4 v = *(const float4*)(xr + tid * 4);
    float s  = v.x + v.y + v.z + v.w;
    float sq = v.x*v.x + v.y*v.y + v.z*v.z + v.w*v.w;

    #pragma unroll
    for (int o = 16; o > 0; o >>= 1) {
        s  += __shfl_xor_sync(0xffffffffu, s,  o);
        sq += __shfl_xor_sync(0xffffffffu, sq, o);
    }
    __shared__ float rs[8], rq[8];
    int w = tid >> 5, l = tid & 31;
    if (l == 0) { rs[w] = s; rq[w] = sq; }
    __syncthreads();
    float ts = 0.f, tq = 0.f;
    #pragma unroll
    for (int i = 0; i < 8; i++) { ts += rs[i]; tq += rq[i]; }
    float mean = ts * (1.0f / D_MODEL);
    float var  = tq * (1.0f / D_MODEL) - mean * mean;
    float inv  = rsqrtf(var + 1e-6f);

    int c = tid * 4;
    float4 o;
    o.x = (v.x - mean) * inv * scale[c+0] + bias[c+0];
    o.y = (v.y - mean) * inv * scale[c+1] + bias[c+1];
    o.z = (v.z - mean) * inv * scale[c+2] + bias[c+2];
    o.w = (v.w - mean) * inv * scale[c+3] + bias[c+3];
    *(float4*)(yr + c) = o;
}

// --------------------------- scores = Q @ K^T (per bh) -----------------------
__global__ __launch_bounds__(256) void scores_kernel(
    const float* __restrict__ q, const float* __restrict__ kk,
    float* __restrict__ s)
{
    const int bh = blockIdx.z;
    const int b = bh >> 4, h = bh & 15;
    const float* Q = q + (size_t)b * SEQ * D_MODEL + h * HEADDIM;
    const float* K = kk + (size_t)b * SEQ * D_MODEL + h * HEADDIM;
    float* C = s + (size_t)bh * SEQ * SEQ;

    const int tid = threadIdx.x;
    const int bm = blockIdx.y * 128;
    const int bn = blockIdx.x * 128;

    __shared__ float As[8][128];
    __shared__ float Bs[8][128];

    const int lrow = tid >> 1;
    const int lcol = (tid & 1) * 4;
    const int w = tid >> 5, l = tid & 31;
    const int ty = (w >> 1) * 32 + (l >> 3) * 8;
    const int tx = (w & 1) * 64 + (l & 7) * 8;

    float acc[8][8] = {};
    float ra[8], rb[8];

    for (int k0 = 0; k0 < HEADDIM; k0 += 8) {
        float4 a4 = *(const float4*)(Q + (size_t)(bm + lrow) * D_MODEL + k0 + lcol);
        As[lcol+0][lrow] = a4.x; As[lcol+1][lrow] = a4.y;
        As[lcol+2][lrow] = a4.z; As[lcol+3][lrow] = a4.w;
        float4 b4 = *(const float4*)(K + (size_t)(bn + lrow) * D_MODEL + k0 + lcol);
        Bs[lcol+0][lrow] = b4.x; Bs[lcol+1][lrow] = b4.y;
        Bs[lcol+2][lrow] = b4.z; Bs[lcol+3][lrow] = b4.w;
        __syncthreads();
        #pragma unroll
        for (int kq = 0; kq < 8; kq++) {
            #pragma unroll
            for (int i = 0; i < 8; i += 4) *(float4*)&ra[i] = *(const float4*)&As[kq][ty + i];
            #pragma unroll
            for (int j = 0; j < 8; j += 4) *(float4*)&rb[j] = *(const float4*)&Bs[kq][tx + j];
            #pragma unroll
            for (int i = 0; i < 8; i++)
                #pragma unroll
                for (int j = 0; j < 8; j++)
                    acc[i][j] = fmaf(ra[i], rb[j], acc[i][j]);
        }
        __syncthreads();
    }

    #pragma unroll
    for (int i = 0; i < 8; i++) {
        #pragma unroll
        for (int j = 0; j < 8; j += 4) {
            float4 c4 = { acc[i][j+0], acc[i][j+1], acc[i][j+2], acc[i][j+3] };
            *(float4*)(C + (size_t)(bm + ty + i) * SEQ + bn + tx + j) = c4;
        }
    }
}

// ------------------------------ row softmax ---------------------------------
__global__ __launch_bounds__(256) void softmax_kernel(float* __restrict__ s)
{
    float* p = s + (size_t)blockIdx.x * SEQ;
    const int tid = threadIdx.x;
    const float sc = 0.125f;

    float4 a = *(const float4*)(p + tid * 4);
    float4 b = *(const float4*)(p + 1024 + tid * 4);
    a.x *= sc; a.y *= sc; a.z *= sc; a.w *= sc;
    b.x *= sc; b.y *= sc; b.z *= sc; b.w *= sc;

    float m = fmaxf(fmaxf(fmaxf(a.x, a.y), fmaxf(a.z, a.w)),
                    fmaxf(fmaxf(b.x, b.y), fmaxf(b.z, b.w)));
    #pragma unroll
    for (int o = 16; o > 0; o >>= 1) m = fmaxf(m, __shfl_xor_sync(0xffffffffu, m, o));
    __shared__ float red[8];
    int w = tid >> 5, l = tid & 31;
    if (l == 0) red[w] = m;
    __syncthreads();
    float bm = red[0];
    #pragma unroll
    for (int i = 1; i < 8; i++) bm = fmaxf(bm, red[i]);

    a.x = __expf(a.x - bm); a.y = __expf(a.y - bm);
    a.z = __expf(a.z - bm); a.w = __expf(a.w - bm);
    b.x = __expf(b.x - bm); b.y = __expf(b.y - bm);
    b.z = __expf(b.z - bm); b.w = __expf(b.w - bm);

    float sum = a.x + a.y + a.z + a.w + b.x + b.y + b.z + b.w;
    #pragma unroll
    for (int o = 16; o > 0; o >>= 1) sum += __shfl_xor_sync(0xffffffffu, sum, o);
    __syncthreads();
    if (l == 0) red[w] = sum;
    __syncthreads();
    float tot = 0.f;
    #pragma unroll
    for (int i = 0; i < 8; i++) tot += red[i];
    float inv = 1.0f / tot;

    a.x *= inv; a.y *= inv; a.z *= inv; a.w *= inv;
    b.x *= inv; b.y *= inv; b.z *= inv; b.w *= inv;
    *(float4*)(p + tid * 4) = a;
    *(float4*)(p + 1024 + tid * 4) = b;
}

// ----------------------- out = P @ V (per bh, N=64) --------------------------
__global__ __launch_bounds__(256) void av_kernel(
    const float* __restrict__ pm, const float* __restrict__ v,
    float* __restrict__ o)
{
    const int bh = blockIdx.z;
    const int b = bh >> 4, h = bh & 15;
    const float* P = pm + (size_t)bh * SEQ * SEQ;
    const float* V = v + (size_t)b * SEQ * D_MODEL + h * HEADDIM;
    float* O = o + (size_t)b * SEQ * D_MODEL + h * HEADDIM;

    const int tid = threadIdx.x;
    const int bm = blockIdx.y * 128;

    __shared__ float Ps[16][128];
    __shared__ float Vs[16][64];

    const int w = tid >> 5, l = tid & 31;
    const int ty = (w >> 1) * 32 + (l >> 3) * 8;
    const int tx = (w & 1) * 32 + (l & 7) * 4;

    float acc[8][4] = {};
    float ra[8], rb[4];

    for (int k0 = 0; k0 < SEQ; k0 += 16) {
        #pragma unroll
        for (int it = 0; it < 2; it++) {
            int idx = tid + it * 256;
            int row = idx >> 2;
            int col = (idx & 3) * 4;
            float4 p4 = *(const float4*)(P + (size_t)(bm + row) * SEQ + k0 + col);
            Ps[col+0][row] = p4.x; Ps[col+1][row] = p4.y;
            Ps[col+2][row] = p4.z; Ps[col+3][row] = p4.w;
        }
        {
            int row = tid >> 4;
            int col = (tid & 15) * 4;
            *(float4*)&Vs[row][col] =
                *(const float4*)(V + (size_t)(k0 + row) * D_MODEL + col);
        }
        __syncthreads();
        #pragma unroll
        for (int kq = 0; kq < 16; kq++) {
            #pragma unroll
            for (int i = 0; i < 8; i += 4) *(float4*)&ra[i] = *(const float4*)&Ps[kq][ty + i];
            *(float4*)&rb[0] = *(const float4*)&Vs[kq][tx];
            #pragma unroll
            for (int i = 0; i < 8; i++)
                #pragma unroll
                for (int j = 0; j < 4; j++)
                    acc[i][j] = fmaf(ra[i], rb[j], acc[i][j]);
        }
        __syncthreads();
    }

    #pragma unroll
    for (int i = 0; i < 8; i++) {
        float4 c4 = { acc[i][0], acc[i][1], acc[i][2], acc[i][3] };
        *(float4*)(O + (size_t)(bm + ty + i) * D_MODEL + tx) = c4;
    }
}

// --------------------------------- launch -----------------------------------
extern "C" void kernel_launch(void* const* d_in, const int* in_sizes, int n_in,
                              void* d_out, int out_size)
{
    const float* x   = (const float*)d_in[0];
    const float* Wq  = (const float*)d_in[1];
    const float* bq  = (const float*)d_in[2];
    const float* Wk  = (const float*)d_in[3];
    const float* bk  = (const float*)d_in[4];
    const float* Wv  = (const float*)d_in[5];
    const float* bv  = (const float*)d_in[6];
    const float* Wo  = (const float*)d_in[7];
    const float* bo  = (const float*)d_in[8];
    const float* W1  = (const float*)d_in[9];
    const float* b1  = (const float*)d_in[10];
    const float* W2  = (const float*)d_in[11];
    const float* b2  = (const float*)d_in[12];
    const float* ln1s = (const float*)d_in[13];
    const float* ln1b = (const float*)d_in[14];
    const float* ln2s = (const float*)d_in[15];
    const float* ln2b = (const float*)d_in[16];
    float* out = (float*)d_out;

    float *h, *q, *k, *v, *attn, *x1, *ff, *scores;
    cudaGetSymbolAddress((void**)&h,     g_h);
    cudaGetSymbolAddress((void**)&q,     g_q);
    cudaGetSymbolAddress((void**)&k,     g_k);
    cudaGetSymbolAddress((void**)&v,     g_v);
    cudaGetSymbolAddress((void**)&attn,  g_attn);
    cudaGetSymbolAddress((void**)&x1,    g_x1);
    cudaGetSymbolAddress((void**)&ff,    g_ff);
    cudaGetSymbolAddress((void**)&scores,g_scores);

    __nv_bfloat16 *wqh,*wql,*wkh,*wkl,*wvh,*wvl,*woh,*wol,*w1h,*w1l,*w2h,*w2l,*ah,*al;
    cudaGetSymbolAddress((void**)&wqh, g_wqT_hi); cudaGetSymbolAddress((void**)&wql, g_wqT_lo);
    cudaGetSymbolAddress((void**)&wkh, g_wkT_hi); cudaGetSymbolAddress((void**)&wkl, g_wkT_lo);
    cudaGetSymbolAddress((void**)&wvh, g_wvT_hi); cudaGetSymbolAddress((void**)&wvl, g_wvT_lo);
    cudaGetSymbolAddress((void**)&woh, g_woT_hi); cudaGetSymbolAddress((void**)&wol, g_woT_lo);
    cudaGetSymbolAddress((void**)&w1h, g_w1T_hi); cudaGetSymbolAddress((void**)&w1l, g_w1T_lo);
    cudaGetSymbolAddress((void**)&w2h, g_w2T_hi); cudaGetSymbolAddress((void**)&w2l, g_w2T_lo);
    cudaGetSymbolAddress((void**)&ah,  g_act_hi); cudaGetSymbolAddress((void**)&al,  g_act_lo);

    cudaFuncSetAttribute(mma_gemm<0>, cudaFuncAttributeMaxDynamicSharedMemorySize, SMEM_BYTES);
    cudaFuncSetAttribute(mma_gemm<1>, cudaFuncAttributeMaxDynamicSharedMemorySize, SMEM_BYTES);
    cudaFuncSetAttribute(mma_gemm<2>, cudaFuncAttributeMaxDynamicSharedMemorySize, SMEM_BYTES);

    // weight conversions (transpose + split)
    conv_wT<<<dim3(D_MODEL/32, D_MODEL/32), 256>>>(Wq, wqh, wql, D_MODEL, D_MODEL);
    conv_wT<<<dim3(D_MODEL/32, D_MODEL/32), 256>>>(Wk, wkh, wkl, D_MODEL, D_MODEL);
    conv_wT<<<dim3(D_MODEL/32, D_MODEL/32), 256>>>(Wv, wvh, wvl, D_MODEL, D_MODEL);
    conv_wT<<<dim3(D_MODEL/32, D_MODEL/32), 256>>>(Wo, woh, wol, D_MODEL, D_MODEL);
    conv_wT<<<dim3(D_FF/32,    D_MODEL/32), 256>>>(W1, w1h, w1l, D_MODEL, D_FF);
    conv_wT<<<dim3(D_MODEL/32, D_FF/32),    256>>>(W2, w2h, w2l, D_FF, D_MODEL);

    // 1) LN1
    ln_kernel<<<NROWS, 256>>>(x, ln1s, ln1b, h);

    // 2) split h; Q/K/V projections on tensor cores
    conv_act<<<(NROWS * D_MODEL / 4 + 255) / 256, 256>>>((const float4*)h, (uint2*)ah, (uint2*)al, NROWS * D_MODEL / 4);
    dim3 gproj(D_MODEL / 128, NROWS / 128);
    mma_gemm<0><<<gproj, 256, SMEM_BYTES>>>(ah, al, wqh, wql, bq, nullptr, q, NROWS, D_MODEL, D_MODEL);
    mma_gemm<0><<<gproj, 256, SMEM_BYTES>>>(ah, al, wkh, wkl, bk, nullptr, k, NROWS, D_MODEL, D_MODEL);
    mma_gemm<0><<<gproj, 256, SMEM_BYTES>>>(ah, al, wvh, wvl, bv, nullptr, v, NROWS, D_MODEL, D_MODEL);

    // 3-5) attention (fp32)
    scores_kernel<<<dim3(SEQ/128, SEQ/128, NBH), 256>>>(q, k, scores);
    softmax_kernel<<<NBH * SEQ, 256>>>(scores);
    av_kernel<<<dim3(1, SEQ/128, NBH), 256>>>(scores, v, attn);

    // 6) x1 = x + attn @ Wo + bo
    conv_act<<<(NROWS * D_MODEL / 4 + 255) / 256, 256>>>((const float4*)attn, (uint2*)ah, (uint2*)al, NROWS * D_MODEL / 4);
    mma_gemm<2><<<gproj, 256, SMEM_BYTES>>>(ah, al, woh, wol, bo, x, x1, NROWS, D_MODEL, D_MODEL);

    // 7) LN2
    ln_kernel<<<NROWS, 256>>>(x1, ln2s, ln2b, h);

    // 8) ff = relu(h @ W1 + b1)
    conv_act<<<(NROWS * D_MODEL / 4 + 255) / 256, 256>>>((const float4*)h, (uint2*)ah, (uint2*)al, NROWS * D_MODEL / 4);
    mma_gemm<1><<<dim3(D_FF/128, NROWS/128), 256, SMEM_BYTES>>>(ah, al, w1h, w1l, b1, nullptr, ff, NROWS, D_FF, D_MODEL);

    // 9) out = x1 + ff @ W2 + b2
    conv_act<<<(NROWS * D_FF / 4 + 255) / 256, 256>>>((const float4*)ff, (uint2*)ah, (uint2*)al, NROWS * D_FF / 4);
    mma_gemm<2><<<dim3(D_MODEL/128, NROWS/128), 256, SMEM_BYTES>>>(ah, al, w2h, w2l, b2, x1, out, NROWS, D_MODEL, D_FF);
}

// round 5
// speedup vs baseline: 2.9935x; 1.6499x over previous
#include <cuda_runtime.h>
#include <cuda_bf16.h>
#include <cstdint>
#include <math.h>

// ---------------------------------------------------------------------------
// TransformerBlock: HMMA bf16-split GEMMs + fused flash attention (hi/lo).
// B=2, S=2048, D=1024, H=16, Dh=64, FF=4096.
// ---------------------------------------------------------------------------

#define D_MODEL 1024
#define SEQ     2048
#define BATCH   2
#define NHEADS  16
#define HEADDIM 64
#define D_FF    4096
#define NROWS   (BATCH * SEQ)          // 4096
#define NBH     (BATCH * NHEADS)       // 32

// ------------------------- scratch (no allocations) ------------------------
__device__ float g_h   [NROWS * D_MODEL];
__device__ float g_attn[NROWS * D_MODEL];
__device__ float g_x1  [NROWS * D_MODEL];
__device__ float g_ff  [NROWS * D_FF];

// bf16 hi/lo split buffers
__device__ __nv_bfloat16 g_wqT_hi[D_MODEL * D_MODEL];
__device__ __nv_bfloat16 g_wqT_lo[D_MODEL * D_MODEL];
__device__ __nv_bfloat16 g_wkT_hi[D_MODEL * D_MODEL];
__device__ __nv_bfloat16 g_wkT_lo[D_MODEL * D_MODEL];
__device__ __nv_bfloat16 g_wvT_hi[D_MODEL * D_MODEL];
__device__ __nv_bfloat16 g_wvT_lo[D_MODEL * D_MODEL];
__device__ __nv_bfloat16 g_woT_hi[D_MODEL * D_MODEL];
__device__ __nv_bfloat16 g_woT_lo[D_MODEL * D_MODEL];
__device__ __nv_bfloat16 g_w1T_hi[D_FF * D_MODEL];
__device__ __nv_bfloat16 g_w1T_lo[D_FF * D_MODEL];
__device__ __nv_bfloat16 g_w2T_hi[D_MODEL * D_FF];
__device__ __nv_bfloat16 g_w2T_lo[D_MODEL * D_FF];
__device__ __nv_bfloat16 g_act_hi[(size_t)NROWS * D_FF];
__device__ __nv_bfloat16 g_act_lo[(size_t)NROWS * D_FF];
// q/k/v hi/lo (written directly by projection GEMMs)
__device__ __nv_bfloat16 g_q_hi[NROWS * D_MODEL];
__device__ __nv_bfloat16 g_q_lo[NROWS * D_MODEL];
__device__ __nv_bfloat16 g_k_hi[NROWS * D_MODEL];
__device__ __nv_bfloat16 g_k_lo[NROWS * D_MODEL];
__device__ __nv_bfloat16 g_v_hi[NROWS * D_MODEL];
__device__ __nv_bfloat16 g_v_lo[NROWS * D_MODEL];

// ------------------------------- PTX helpers --------------------------------
__device__ __forceinline__ uint32_t smem_u32(const void* p) {
    uint32_t a;
    asm("{ .reg .u64 t; cvta.to.shared.u64 t, %1; cvt.u32.u64 %0, t; }"
        : "=r"(a) : "l"(p));
    return a;
}

#define SMEM_SWZ128(off) ((off) ^ (((off) >> 3) & 0x70))

__device__ __forceinline__ void cp_async16(uint32_t dst, const void* src) {
    asm volatile("cp.async.cg.shared.global [%0], [%1], 16;"
                 :: "r"(dst), "l"(__cvta_generic_to_global(src)) : "memory");
}
#define CP_COMMIT() asm volatile("cp.async.commit_group;" ::: "memory")
#define CP_WAIT2()  asm volatile("cp.async.wait_group 2;" ::: "memory")
#define CP_WAIT1()  asm volatile("cp.async.wait_group 1;" ::: "memory")
#define CP_WAIT0()  asm volatile("cp.async.wait_group 0;" ::: "memory")

__device__ __forceinline__ void ldmatrix_x4(uint32_t* r, uint32_t addr) {
    asm volatile("ldmatrix.sync.aligned.m8n8.x4.shared.b16 {%0,%1,%2,%3}, [%4];"
                 : "=r"(r[0]), "=r"(r[1]), "=r"(r[2]), "=r"(r[3]) : "r"(addr));
}
__device__ __forceinline__ void ldmatrix_x4_t(uint32_t* r, uint32_t addr) {
    asm volatile("ldmatrix.sync.aligned.m8n8.x4.trans.shared.b16 {%0,%1,%2,%3}, [%4];"
                 : "=r"(r[0]), "=r"(r[1]), "=r"(r[2]), "=r"(r[3]) : "r"(addr));
}

__device__ __forceinline__ void mma_bf16(float* c, const uint32_t* a, const uint32_t* b) {
    asm volatile(
        "mma.sync.aligned.m16n8k16.row.col.f32.bf16.bf16.f32 "
        "{%0,%1,%2,%3}, {%4,%5,%6,%7}, {%8,%9}, {%0,%1,%2,%3};"
        : "+f"(c[0]), "+f"(c[1]), "+f"(c[2]), "+f"(c[3])
        : "r"(a[0]), "r"(a[1]), "r"(a[2]), "r"(a[3]), "r"(b[0]), "r"(b[1]));
}

__device__ __forceinline__ uint32_t pack_bf2(__nv_bfloat16 a, __nv_bfloat16 b) {
    return (uint32_t)__bfloat16_as_ushort(a) | ((uint32_t)__bfloat16_as_ushort(b) << 16);
}

// ----------------------------- HMMA GEMM ------------------------------------
// C[M,N] = A[M,K] @ B^T[N,K] (hi/lo split) + bias
// EPI: 0=bias->fp32  1=bias+relu->fp32  2=bias+res->fp32  3=bias->bf16 hi/lo
#define STAGES      3
#define KC          64
#define TILE_BYTES  16384            // 128 rows x 128B (64 bf16 K-chunk)
#define STAGE_BYTES (4 * TILE_BYTES) // Ahi, Alo, Bhi, Blo
#define SMEM_BYTES  (STAGES * STAGE_BYTES + 1024)

__device__ __forceinline__ void load_stage(
    uint32_t st_base,
    const __nv_bfloat16* __restrict__ Ahi, const __nv_bfloat16* __restrict__ Alo,
    const __nv_bfloat16* __restrict__ Bhi, const __nv_bfloat16* __restrict__ Blo,
    int bm, int bn, int k0, int K, int tid)
{
    #pragma unroll
    for (int i = 0; i < 16; i++) {
        int id  = tid + i * 256;
        int mat = id >> 10;
        int r   = (id & 1023) >> 3;
        int c   = id & 7;
        uint32_t off = SMEM_SWZ128((uint32_t)(r * 128 + c * 16));
        uint32_t dst = st_base + mat * TILE_BYTES + off;
        const __nv_bfloat16* src;
        if (mat == 0)      src = Ahi + (size_t)(bm + r) * K + k0 + c * 8;
        else if (mat == 1) src = Alo + (size_t)(bm + r) * K + k0 + c * 8;
        else if (mat == 2) src = Bhi + (size_t)(bn + r) * K + k0 + c * 8;
        else               src = Blo + (size_t)(bn + r) * K + k0 + c * 8;
        cp_async16(dst, src);
    }
}

__device__ __forceinline__ void mma_pass(
    float acc[2][8][4], uint32_t Abase, uint32_t Bbase, int wm, int wn, int l)
{
    const int a_row  = wm * 32 + (l & 7) + ((l >> 3) & 1) * 8;
    const int a_kblk = ((l >> 4) & 1) * 8;
    const int b_row  = wn * 64 + ((l >> 4) & 1) * 8 + (l & 7);
    const int b_kblk = ((l >> 3) & 1) * 8;

    #pragma unroll
    for (int ks = 0; ks < 4; ks++) {
        const int k0 = ks * 16;
        uint32_t a[2][4];
        #pragma unroll
        for (int mt = 0; mt < 2; mt++) {
            uint32_t off = SMEM_SWZ128((uint32_t)((a_row + mt * 16) * 128 + (k0 + a_kblk) * 2));
            ldmatrix_x4(a[mt], Abase + off);
        }
        uint32_t b[8][2];
        #pragma unroll
        for (int np = 0; np < 4; np++) {
            uint32_t r[4];
            uint32_t off = SMEM_SWZ128((uint32_t)((b_row + np * 16) * 128 + (k0 + b_kblk) * 2));
            ldmatrix_x4(r, Bbase + off);
            b[np * 2 + 0][0] = r[0]; b[np * 2 + 0][1] = r[1];
            b[np * 2 + 1][0] = r[2]; b[np * 2 + 1][1] = r[3];
        }
        #pragma unroll
        for (int mt = 0; mt < 2; mt++)
            #pragma unroll
            for (int nt = 0; nt < 8; nt++)
                mma_bf16(acc[mt][nt], a[mt], b[nt]);
    }
}

template<int EPI>
__global__ __launch_bounds__(256, 1) void mma_gemm(
    const __nv_bfloat16* __restrict__ Ahi, const __nv_bfloat16* __restrict__ Alo,
    const __nv_bfloat16* __restrict__ Bhi, const __nv_bfloat16* __restrict__ Blo,
    const float* __restrict__ bias, const float* __restrict__ res,
    float* __restrict__ C,
    __nv_bfloat16* __restrict__ Chi, __nv_bfloat16* __restrict__ Clo,
    int M, int N, int K)
{
    extern __shared__ char dsm[];
    const uint32_t smbase = (smem_u32(dsm) + 1023u) & ~1023u;

    const int tid = threadIdx.x;
    const int wid = tid >> 5;
    const int l   = tid & 31;
    const int wm  = wid & 3;
    const int wn  = wid >> 2;
    const int bm  = blockIdx.y * 128;
    const int bn  = blockIdx.x * 128;
    const int NK  = K / KC;

    float acc[2][8][4] = {};

    #pragma unroll
    for (int kc = 0; kc < STAGES; kc++) {
        load_stage(smbase + kc * STAGE_BYTES, Ahi, Alo, Bhi, Blo, bm, bn, kc * KC, K, tid);
        CP_COMMIT();
    }

    for (int kc = 0; kc < NK; kc++) {
        const int s = kc % STAGES;
        const uint32_t st = smbase + s * STAGE_BYTES;
        CP_WAIT2();
        __syncthreads();

        mma_pass(acc, st,              st + 2 * TILE_BYTES, wm, wn, l);
        mma_pass(acc, st,              st + 3 * TILE_BYTES, wm, wn, l);
        mma_pass(acc, st + TILE_BYTES, st + 2 * TILE_BYTES, wm, wn, l);

        __syncthreads();
        if (kc + STAGES < NK)
            load_stage(st, Ahi, Alo, Bhi, Blo, bm, bn, (kc + STAGES) * KC, K, tid);
        CP_COMMIT();
    }

    const int g = l >> 2;
    const int t2 = (l & 3) * 2;
    #pragma unroll
    for (int mt = 0; mt < 2; mt++) {
        const int r0 = bm + wm * 32 + mt * 16 + g;
        #pragma unroll
        for (int nt = 0; nt < 8; nt++) {
            const int col = bn + wn * 64 + nt * 8 + t2;
            float2 p0 = { acc[mt][nt][0] + bias[col], acc[mt][nt][1] + bias[col + 1] };
            float2 p1 = { acc[mt][nt][2] + bias[col], acc[mt][nt][3] + bias[col + 1] };
            if (EPI == 1) {
                p0.x = fmaxf(p0.x, 0.f); p0.y = fmaxf(p0.y, 0.f);
                p1.x = fmaxf(p1.x, 0.f); p1.y = fmaxf(p1.y, 0.f);
            }
            if (EPI == 2) {
                float2 q0 = *(const float2*)(res + (size_t)r0 * N + col);
                float2 q1 = *(const float2*)(res + (size_t)(r0 + 8) * N + col);
                p0.x += q0.x; p0.y += q0.y;
                p1.x += q1.x; p1.y += q1.y;
            }
            if (EPI == 3) {
                __nv_bfloat16 h0 = __float2bfloat16(p0.x), h1 = __float2bfloat16(p0.y);
                __nv_bfloat16 h2 = __float2bfloat16(p1.x), h3 = __float2bfloat16(p1.y);
                *(uint32_t*)(Chi + (size_t)r0 * N + col)       = pack_bf2(h0, h1);
                *(uint32_t*)(Chi + (size_t)(r0 + 8) * N + col) = pack_bf2(h2, h3);
                *(uint32_t*)(Clo + (size_t)r0 * N + col) =
                    pack_bf2(__float2bfloat16(p0.x - __bfloat162float(h0)),
                             __float2bfloat16(p0.y - __bfloat162float(h1)));
                *(uint32_t*)(Clo + (size_t)(r0 + 8) * N + col) =
                    pack_bf2(__float2bfloat16(p1.x - __bfloat162float(h2)),
                             __float2bfloat16(p1.y - __bfloat162float(h3)));
            } else {
                *(float2*)(C + (size_t)r0 * N + col) = p0;
                *(float2*)(C + (size_t)(r0 + 8) * N + col) = p1;
            }
        }
    }
}

// --------------------------- flash attention ---------------------------------
// grid (SEQ/128, NBH); 256 threads; Bq=128, Bk=64.
// smem: Qhi[128][64] @0, Qlo @16384; stages @32768: per stage 32768 bytes:
//   Khi @+0, Klo @+8192, Vhi @+16384, Vlo @+24576.
#define FL_SMEM (32768 + 2 * 32768 + 1024)
#define FL_TILES (SEQ / 64)

__device__ __forceinline__ void fl_load_kv(
    uint32_t st, const __nv_bfloat16* kh, const __nv_bfloat16* kl,
    const __nv_bfloat16* vh, const __nv_bfloat16* vl,
    size_t rowbase, int colbase, int kv0, int tid)
{
    #pragma unroll
    for (int i = 0; i < 8; i++) {
        int id  = tid + i * 256;          // 0..2047
        int mat = id >> 9;                // constant per i
        int r   = (id >> 3) & 63;
        int c   = id & 7;
        uint32_t off = SMEM_SWZ128((uint32_t)(r * 128 + c * 16));
        const __nv_bfloat16* base = (mat == 0) ? kh : (mat == 1) ? kl : (mat == 2) ? vh : vl;
        cp_async16(st + mat * 8192 + off,
                   base + (rowbase + kv0 + r) * D_MODEL + colbase + c * 8);
    }
}

__device__ __forceinline__ void fl_qk_pass(
    float sa[8][4], uint32_t Qb, uint32_t Kb, int a_row, int a_kb, int b_row, int b_kb)
{
    #pragma unroll
    for (int ks = 0; ks < 4; ks++) {
        uint32_t a[4];
        ldmatrix_x4(a, Qb + SMEM_SWZ128((uint32_t)(a_row * 128 + (ks * 16 + a_kb) * 2)));
        #pragma unroll
        for (int nt2 = 0; nt2 < 4; nt2++) {
            uint32_t r[4];
            ldmatrix_x4(r, Kb + SMEM_SWZ128((uint32_t)((nt2 * 16 + b_row) * 128 + (ks * 16 + b_kb) * 2)));
            mma_bf16(sa[nt2 * 2 + 0], a, &r[0]);
            mma_bf16(sa[nt2 * 2 + 1], a, &r[2]);
        }
    }
}

__device__ __forceinline__ void fl_pv_pass(
    float ao[8][4], const uint32_t pf[4][4], uint32_t Vb, int v_row, int v_cb)
{
    #pragma unroll
    for (int ks = 0; ks < 4; ks++) {
        #pragma unroll
        for (int nd2 = 0; nd2 < 4; nd2++) {
            uint32_t r[4];
            ldmatrix_x4_t(r, Vb + SMEM_SWZ128((uint32_t)((ks * 16 + v_row) * 128 + (nd2 * 16 + v_cb) * 2)));
            mma_bf16(ao[nd2 * 2 + 0], pf[ks], &r[0]);
            mma_bf16(ao[nd2 * 2 + 1], pf[ks], &r[2]);
        }
    }
}

__global__ __launch_bounds__(256, 1) void flash_kernel(
    const __nv_bfloat16* __restrict__ qh, const __nv_bfloat16* __restrict__ ql,
    const __nv_bfloat16* __restrict__ kh, const __nv_bfloat16* __restrict__ kl,
    const __nv_bfloat16* __restrict__ vh, const __nv_bfloat16* __restrict__ vl,
    float* __restrict__ out)
{
    extern __shared__ char dsm[];
    const uint32_t sm = (smem_u32(dsm) + 1023u) & ~1023u;

    const int tid = threadIdx.x;
    const int w = tid >> 5, l = tid & 31;
    const int qt = blockIdx.x, bh = blockIdx.y;
    const int b = bh >> 4, h = bh & 15;
    const size_t rowbase = (size_t)b * SEQ;
    const int colbase = h * HEADDIM;
    const int q0 = qt * 128;

    // load Q hi/lo (128 rows x 128B each)
    #pragma unroll
    for (int i = 0; i < 8; i++) {
        int id  = tid + i * 256;
        int mat = id >> 10;
        int r   = (id >> 3) & 127;
        int c   = id & 7;
        uint32_t off = SMEM_SWZ128((uint32_t)(r * 128 + c * 16));
        const __nv_bfloat16* src = ((mat == 0) ? qh : ql) + (rowbase + q0 + r) * D_MODEL + colbase + c * 8;
        cp_async16(sm + mat * 16384 + off, src);
    }
    CP_COMMIT();
    fl_load_kv(sm + 32768, kh, kl, vh, vl, rowbase, colbase, 0, tid);
    CP_COMMIT();

    const uint32_t Qhi_s = sm, Qlo_s = sm + 16384;
    const int a_row = w * 16 + (l & 7) + ((l >> 3) & 1) * 8;
    const int a_kb  = ((l >> 4) & 1) * 8;
    const int b_row = ((l >> 4) & 1) * 8 + (l & 7);
    const int b_kb  = ((l >> 3) & 1) * 8;
    const int v_row = (l & 15);
    const int v_cb  = ((l >> 4) & 1) * 8;

    float m0 = -1e30f, m1 = -1e30f, l0 = 0.f, l1 = 0.f;
    float ao[8][4] = {};
    const float SC2 = 0.18033688011112042f;  // (1/8) * log2(e)

    for (int t = 0; t < FL_TILES; t++) {
        const uint32_t st = sm + 32768 + (uint32_t)(t & 1) * 32768;
        if (t + 1 < FL_TILES) {
            fl_load_kv(sm + 32768 + (uint32_t)((t + 1) & 1) * 32768,
                       kh, kl, vh, vl, rowbase, colbase, (t + 1) * 64, tid);
            CP_COMMIT();
            CP_WAIT1();
        } else {
            CP_WAIT0();
        }
        __syncthreads();

        // S = Q K^T  (3 hi/lo passes)
        float sa[8][4] = {};
        fl_qk_pass(sa, Qhi_s, st,        a_row, a_kb, b_row, b_kb);
        fl_qk_pass(sa, Qhi_s, st + 8192, a_row, a_kb, b_row, b_kb);
        fl_qk_pass(sa, Qlo_s, st,        a_row, a_kb, b_row, b_kb);

        // online softmax
        float tm0 = -1e30f, tm1 = -1e30f;
        #pragma unroll
        for (int nt = 0; nt < 8; nt++) {
            tm0 = fmaxf(tm0, fmaxf(sa[nt][0], sa[nt][1]));
            tm1 = fmaxf(tm1, fmaxf(sa[nt][2], sa[nt][3]));
        }
        tm0 = fmaxf(tm0, __shfl_xor_sync(0xffffffffu, tm0, 1));
        tm0 = fmaxf(tm0, __shfl_xor_sync(0xffffffffu, tm0, 2));
        tm1 = fmaxf(tm1, __shfl_xor_sync(0xffffffffu, tm1, 1));
        tm1 = fmaxf(tm1, __shfl_xor_sync(0xffffffffu, tm1, 2));
        const float nm0 = fmaxf(m0, tm0), nm1 = fmaxf(m1, tm1);
        const float al0 = exp2f((m0 - nm0) * SC2);
        const float al1 = exp2f((m1 - nm1) * SC2);
        m0 = nm0; m1 = nm1;

        float rs0 = 0.f, rs1 = 0.f;
        #pragma unroll
        for (int nt = 0; nt < 8; nt++) {
            sa[nt][0] = exp2f((sa[nt][0] - m0) * SC2);
            sa[nt][1] = exp2f((sa[nt][1] - m0) * SC2);
            sa[nt][2] = exp2f((sa[nt][2] - m1) * SC2);
            sa[nt][3] = exp2f((sa[nt][3] - m1) * SC2);
            rs0 += sa[nt][0] + sa[nt][1];
            rs1 += sa[nt][2] + sa[nt][3];
        }
        rs0 += __shfl_xor_sync(0xffffffffu, rs0, 1);
        rs0 += __shfl_xor_sync(0xffffffffu, rs0, 2);
        rs1 += __shfl_xor_sync(0xffffffffu, rs1, 1);
        rs1 += __shfl_xor_sync(0xffffffffu, rs1, 2);
        l0 = l0 * al0 + rs0;
        l1 = l1 * al1 + rs1;

        #pragma unroll
        for (int nd = 0; nd < 8; nd++) {
            ao[nd][0] *= al0; ao[nd][1] *= al0;
            ao[nd][2] *= al1; ao[nd][3] *= al1;
        }

        // P -> bf16 hi/lo A-fragments
        uint32_t ph[4][4], pl[4][4];
        #pragma unroll
        for (int ks = 0; ks < 4; ks++) {
            #pragma unroll
            for (int half = 0; half < 2; half++) {   // tiles 2ks, 2ks+1
                const float* s2 = sa[2 * ks + half];
                __nv_bfloat16 h0 = __float2bfloat16(s2[0]);
                __nv_bfloat16 h1 = __float2bfloat16(s2[1]);
                __nv_bfloat16 h2 = __float2bfloat16(s2[2]);
                __nv_bfloat16 h3 = __float2bfloat16(s2[3]);
                ph[ks][half * 1 + 0 + (half ? 1 : 0)] = 0; // placeholder (overwritten below)
                ph[ks][0 + 2 * half] = pack_bf2(h0, h1);
                ph[ks][1 + 2 * half] = pack_bf2(h2, h3);
                pl[ks][0 + 2 * half] = pack_bf2(__float2bfloat16(s2[0] - __bfloat162float(h0)),
                                                __float2bfloat16(s2[1] - __bfloat162float(h1)));
                pl[ks][1 + 2 * half] = pack_bf2(__float2bfloat16(s2[2] - __bfloat162float(h2)),
                                                __float2bfloat16(s2[3] - __bfloat162float(h3)));
            }
        }

        // O += P V  (3 hi/lo passes)
        fl_pv_pass(ao, ph, st + 16384, v_row, v_cb);   // Phi * Vhi
        fl_pv_pass(ao, ph, st + 24576, v_row, v_cb);   // Phi * Vlo
        fl_pv_pass(ao, pl, st + 16384, v_row, v_cb);   // Plo * Vhi

        __syncthreads();
    }

    // write O / l
    const float inv0 = 1.0f / l0, inv1 = 1.0f / l1;
    const int g = l >> 2, t2 = (l & 3) * 2;
    const size_t row0 = rowbase + q0 + w * 16 + g;
    #pragma unroll
    for (int nd = 0; nd < 8; nd++) {
        const int col = colbase + nd * 8 + t2;
        float2 o0 = { ao[nd][0] * inv0, ao[nd][1] * inv0 };
        float2 o1 = { ao[nd][2] * inv1, ao[nd][3] * inv1 };
        *(float2*)(out + row0 * D_MODEL + col) = o0;
        *(float2*)(out + (row0 + 8) * D_MODEL + col) = o1;
    }
}

// --------------------------- conversion kernels ------------------------------
__global__ __launch_bounds__(256) void conv_act(
    const float4* __restrict__ x, uint2* __restrict__ hi, uint2* __restrict__ lo, int n4)
{
    int i = blockIdx.x * 256 + threadIdx.x;
    if (i >= n4) return;
    float4 v = x[i];
    __nv_bfloat16 h0 = __float2bfloat16(v.x);
    __nv_bfloat16 h1 = __float2bfloat16(v.y);
    __nv_bfloat16 h2 = __float2bfloat16(v.z);
    __nv_bfloat16 h3 = __float2bfloat16(v.w);
    __nv_bfloat16 l0 = __float2bfloat16(v.x - __bfloat162float(h0));
    __nv_bfloat16 l1 = __float2bfloat16(v.y - __bfloat162float(h1));
    __nv_bfloat16 l2 = __float2bfloat16(v.z - __bfloat162float(h2));
    __nv_bfloat16 l3 = __float2bfloat16(v.w - __bfloat162float(h3));
    uint2 ph = { pack_bf2(h0, h1), pack_bf2(h2, h3) };
    uint2 pl = { pack_bf2(l0, l1), pack_bf2(l2, l3) };
    hi[i] = ph;
    lo[i] = pl;
}

// W [K,N] fp32 -> T [N,K] bf16 hi/lo
__global__ __launch_bounds__(256) void conv_wT(
    const float* __restrict__ W, __nv_bfloat16* __restrict__ Thi,
    __nv_bfloat16* __restrict__ Tlo, int K, int N)
{
    __shared__ float t[32][33];
    const int n0 = blockIdx.x * 32, k0 = blockIdx.y * 32;
    const int tx = threadIdx.x & 31, ty8 = threadIdx.x >> 5;
    #pragma unroll
    for (int j = 0; j < 4; j++) {
        int ky = ty8 + j * 8;
        t[ky][tx] = W[(size_t)(k0 + ky) * N + n0 + tx];
    }
    __syncthreads();
    #pragma unroll
    for (int j = 0; j < 4; j++) {
        int ny = ty8 + j * 8;
        float x = t[tx][ny];
        __nv_bfloat16 h = __float2bfloat16(x);
        Thi[(size_t)(n0 + ny) * K + k0 + tx] = h;
        Tlo[(size_t)(n0 + ny) * K + k0 + tx] = __float2bfloat16(x - __bfloat162float(h));
    }
}

// --------------------------------- LayerNorm --------------------------------
__global__ __launch_bounds__(256) void ln_kernel(
    const float* __restrict__ x, const float* __restrict__ scale,
    const float* __restrict__ bias, float* __restrict__ y)
{
    const int row = blockIdx.x;
    const int tid = threadIdx.x;
    const float* xr = x + (size_t)row * D_MODEL;
    float* yr = y + (size_t)row * D_MODEL;

    float4 v = *(const float4*)(xr + tid * 4);
    float s  = v.x + v.y + v.z + v.w;
    float sq = v.x*v.x + v.y*v.y + v.z*v.z + v.w*v.w;

    #pragma unroll
    for (int o = 16; o > 0; o >>= 1) {
        s  += __shfl_xor_sync(0xffffffffu, s,  o);
        sq += __shfl_xor_sync(0xffffffffu, sq, o);
    }
    __shared__ float rs[8], rq[8];
    int w = tid >> 5, l = tid & 31;
    if (l == 0) { rs[w] = s; rq[w] = sq; }
    __syncthreads();
    float ts = 0.f, tq = 0.f;
    #pragma unroll
    for (int i = 0; i < 8; i++) { ts += rs[i]; tq += rq[i]; }
    float mean = ts * (1.0f / D_MODEL);
    float var  = tq * (1.0f / D_MODEL) - mean * mean;
    float inv  = rsqrtf(var + 1e-6f);

    int c = tid * 4;
    float4 o;
    o.x = (v.x - mean) * inv * scale[c+0] + bias[c+0];
    o.y = (v.y - mean) * inv * scale[c+1] + bias[c+1];
    o.z = (v.z - mean) * inv * scale[c+2] + bias[c+2];
    o.w = (v.w - mean) * inv * scale[c+3] + bias[c+3];
    *(float4*)(yr + c) = o;
}

// --------------------------------- launch -----------------------------------
extern "C" void kernel_launch(void* const* d_in, const int* in_sizes, int n_in,
                              void* d_out, int out_size)
{
    const float* x   = (const float*)d_in[0];
    const float* Wq  = (const float*)d_in[1];
    const float* bq  = (const float*)d_in[2];
    const float* Wk  = (const float*)d_in[3];
    const float* bk  = (const float*)d_in[4];
    const float* Wv  = (const float*)d_in[5];
    const float* bv  = (const float*)d_in[6];
    const float* Wo  = (const float*)d_in[7];
    const float* bo  = (const float*)d_in[8];
    const float* W1  = (const float*)d_in[9];
    const float* b1  = (const float*)d_in[10];
    const float* W2  = (const float*)d_in[11];
    const float* b2  = (const float*)d_in[12];
    const float* ln1s = (const float*)d_in[13];
    const float* ln1b = (const float*)d_in[14];
    const float* ln2s = (const float*)d_in[15];
    const float* ln2b = (const float*)d_in[16];
    float* out = (float*)d_out;

    float *h, *attn, *x1, *ff;
    cudaGetSymbolAddress((void**)&h,    g_h);
    cudaGetSymbolAddress((void**)&attn, g_attn);
    cudaGetSymbolAddress((void**)&x1,   g_x1);
    cudaGetSymbolAddress((void**)&ff,   g_ff);

    __nv_bfloat16 *wqh,*wql,*wkh,*wkl,*wvh,*wvl,*woh,*wol,*w1h,*w1l,*w2h,*w2l,*ah,*al;
    __nv_bfloat16 *qhp,*qlp,*khp,*klp,*vhp,*vlp;
    cudaGetSymbolAddress((void**)&wqh, g_wqT_hi); cudaGetSymbolAddress((void**)&wql, g_wqT_lo);
    cudaGetSymbolAddress((void**)&wkh, g_wkT_hi); cudaGetSymbolAddress((void**)&wkl, g_wkT_lo);
    cudaGetSymbolAddress((void**)&wvh, g_wvT_hi); cudaGetSymbolAddress((void**)&wvl, g_wvT_lo);
    cudaGetSymbolAddress((void**)&woh, g_woT_hi); cudaGetSymbolAddress((void**)&wol, g_woT_lo);
    cudaGetSymbolAddress((void**)&w1h, g_w1T_hi); cudaGetSymbolAddress((void**)&w1l, g_w1T_lo);
    cudaGetSymbolAddress((void**)&w2h, g_w2T_hi); cudaGetSymbolAddress((void**)&w2l, g_w2T_lo);
    cudaGetSymbolAddress((void**)&ah,  g_act_hi); cudaGetSymbolAddress((void**)&al,  g_act_lo);
    cudaGetSymbolAddress((void**)&qhp, g_q_hi);   cudaGetSymbolAddress((void**)&qlp, g_q_lo);
    cudaGetSymbolAddress((void**)&khp, g_k_hi);   cudaGetSymbolAddress((void**)&klp, g_k_lo);
    cudaGetSymbolAddress((void**)&vhp, g_v_hi);   cudaGetSymbolAddress((void**)&vlp, g_v_lo);

    cudaFuncSetAttribute(mma_gemm<0>, cudaFuncAttributeMaxDynamicSharedMemorySize, SMEM_BYTES);
    cudaFuncSetAttribute(mma_gemm<1>, cudaFuncAttributeMaxDynamicSharedMemorySize, SMEM_BYTES);
    cudaFuncSetAttribute(mma_gemm<2>, cudaFuncAttributeMaxDynamicSharedMemorySize, SMEM_BYTES);
    cudaFuncSetAttribute(mma_gemm<3>, cudaFuncAttributeMaxDynamicSharedMemorySize, SMEM_BYTES);
    cudaFuncSetAttribute(flash_kernel, cudaFuncAttributeMaxDynamicSharedMemorySize, FL_SMEM);

    // weight conversions (transpose + split)
    conv_wT<<<dim3(D_MODEL/32, D_MODEL/32), 256>>>(Wq, wqh, wql, D_MODEL, D_MODEL);
    conv_wT<<<dim3(D_MODEL/32, D_MODEL/32), 256>>>(Wk, wkh, wkl, D_MODEL, D_MODEL);
    conv_wT<<<dim3(D_MODEL/32, D_MODEL/32), 256>>>(Wv, wvh, wvl, D_MODEL, D_MODEL);
    conv_wT<<<dim3(D_MODEL/32, D_MODEL/32), 256>>>(Wo, woh, wol, D_MODEL, D_MODEL);
    conv_wT<<<dim3(D_FF/32,    D_MODEL/32), 256>>>(W1, w1h, w1l, D_MODEL, D_FF);
    conv_wT<<<dim3(D_MODEL/32, D_FF/32),    256>>>(W2, w2h, w2l, D_FF, D_MODEL);

    // 1) LN1 + split
    ln_kernel<<<NROWS, 256>>>(x, ln1s, ln1b, h);
    conv_act<<<(NROWS * D_MODEL / 4 + 255) / 256, 256>>>((const float4*)h, (uint2*)ah, (uint2*)al, NROWS * D_MODEL / 4);

    // 2) Q/K/V projections -> bf16 hi/lo directly
    dim3 gproj(D_MODEL / 128, NROWS / 128);
    mma_gemm<3><<<gproj, 256, SMEM_BYTES>>>(ah, al, wqh, wql, bq, nullptr, nullptr, qhp, qlp, NROWS, D_MODEL, D_MODEL);
    mma_gemm<3><<<gproj, 256, SMEM_BYTES>>>(ah, al, wkh, wkl, bk, nullptr, nullptr, khp, klp, NROWS, D_MODEL, D_MODEL);
    mma_gemm<3><<<gproj, 256, SMEM_BYTES>>>(ah, al, wvh, wvl, bv, nullptr, nullptr, vhp, vlp, NROWS, D_MODEL, D_MODEL);

    // 3) fused flash attention
    flash_kernel<<<dim3(SEQ/128, NBH), 256, FL_SMEM>>>(qhp, qlp, khp, klp, vhp, vlp, attn);

    // 4) x1 = x + attn @ Wo + bo
    conv_act<<<(NROWS * D_MODEL / 4 + 255) / 256, 256>>>((const float4*)attn, (uint2*)ah, (uint2*)al, NROWS * D_MODEL / 4);
    mma_gemm<2><<<gproj, 256, SMEM_BYTES>>>(ah, al, woh, wol, bo, x, x1, nullptr, nullptr, NROWS, D_MODEL, D_MODEL);

    // 5) LN2 + split
    ln_kernel<<<NROWS, 256>>>(x1, ln2s, ln2b, h);
    conv_act<<<(NROWS * D_MODEL / 4 + 255) / 256, 256>>>((const float4*)h, (uint2*)ah, (uint2*)al, NROWS * D_MODEL / 4);

    // 6) ff = relu(h @ W1 + b1)
    mma_gemm<1><<<dim3(D_FF/128, NROWS/128), 256, SMEM_BYTES>>>(ah, al, w1h, w1l, b1, nullptr, ff, nullptr, nullptr, NROWS, D_FF, D_MODEL);

    // 7) out = x1 + ff @ W2 + b2
    conv_act<<<(NROWS * D_FF / 4 + 255) / 256, 256>>>((const float4*)ff, (uint2*)ah, (uint2*)al, NROWS * D_FF / 4);
    mma_gemm<2><<<dim3(D_MODEL/128, NROWS/128), 256, SMEM_BYTES>>>(ah, al, w2h, w2l, b2, x1, out, nullptr, nullptr, NROWS, D_MODEL, D_FF);
}

// round 8
// speedup vs baseline: 3.0400x; 1.0155x over previous
#include <cuda_runtime.h>
#include <cuda_bf16.h>
#include <cstdint>
#include <math.h>

// ---------------------------------------------------------------------------
// TransformerBlock: HMMA bf16-split GEMMs (fused epilogues) + flash attention.
// B=2, S=2048, D=1024, H=16, Dh=64, FF=4096.
// ---------------------------------------------------------------------------

#define D_MODEL 1024
#define SEQ     2048
#define BATCH   2
#define NHEADS  16
#define HEADDIM 64
#define D_FF    4096
#define NROWS   (BATCH * SEQ)          // 4096
#define NBH     (BATCH * NHEADS)       // 32
#define NQKV    3072
#define QKVLD   3072

// ------------------------- scratch (no allocations) ------------------------
__device__ float g_x1[NROWS * D_MODEL];

// activations bf16 hi/lo
__device__ __nv_bfloat16 g_xs_hi[NROWS * D_MODEL];   // LN out / flash out (reused)
__device__ __nv_bfloat16 g_xs_lo[NROWS * D_MODEL];
__device__ __nv_bfloat16 g_ff_hi[(size_t)NROWS * D_FF];
__device__ __nv_bfloat16 g_ff_lo[(size_t)NROWS * D_FF];
__device__ __nv_bfloat16 g_qkv_hi[(size_t)NROWS * NQKV];
__device__ __nv_bfloat16 g_qkv_lo[(size_t)NROWS * NQKV];

// weights bf16 hi/lo (transposed [N,K])
__device__ __nv_bfloat16 g_wqkvT_hi[NQKV * D_MODEL];
__device__ __nv_bfloat16 g_wqkvT_lo[NQKV * D_MODEL];
__device__ __nv_bfloat16 g_woT_hi[D_MODEL * D_MODEL];
__device__ __nv_bfloat16 g_woT_lo[D_MODEL * D_MODEL];
__device__ __nv_bfloat16 g_w1T_hi[D_FF * D_MODEL];
__device__ __nv_bfloat16 g_w1T_lo[D_FF * D_MODEL];
__device__ __nv_bfloat16 g_w2T_hi[D_MODEL * D_FF];
__device__ __nv_bfloat16 g_w2T_lo[D_MODEL * D_FF];
__device__ float g_bqkv[NQKV];

// ------------------------------- PTX helpers --------------------------------
__device__ __forceinline__ uint32_t smem_u32(const void* p) {
    uint32_t a;
    asm("{ .reg .u64 t; cvta.to.shared.u64 t, %1; cvt.u32.u64 %0, t; }"
        : "=r"(a) : "l"(p));
    return a;
}

#define SMEM_SWZ128(off) ((off) ^ (((off) >> 3) & 0x70))

__device__ __forceinline__ void cp_async16(uint32_t dst, const void* src) {
    asm volatile("cp.async.cg.shared.global [%0], [%1], 16;"
                 :: "r"(dst), "l"(__cvta_generic_to_global(src)) : "memory");
}
#define CP_COMMIT() asm volatile("cp.async.commit_group;" ::: "memory")
#define CP_WAIT2()  asm volatile("cp.async.wait_group 2;" ::: "memory")
#define CP_WAIT1()  asm volatile("cp.async.wait_group 1;" ::: "memory")
#define CP_WAIT0()  asm volatile("cp.async.wait_group 0;" ::: "memory")

__device__ __forceinline__ void ldmatrix_x4(uint32_t* r, uint32_t addr) {
    asm volatile("ldmatrix.sync.aligned.m8n8.x4.shared.b16 {%0,%1,%2,%3}, [%4];"
                 : "=r"(r[0]), "=r"(r[1]), "=r"(r[2]), "=r"(r[3]) : "r"(addr));
}
__device__ __forceinline__ void ldmatrix_x4_t(uint32_t* r, uint32_t addr) {
    asm volatile("ldmatrix.sync.aligned.m8n8.x4.trans.shared.b16 {%0,%1,%2,%3}, [%4];"
                 : "=r"(r[0]), "=r"(r[1]), "=r"(r[2]), "=r"(r[3]) : "r"(addr));
}

__device__ __forceinline__ void mma_bf16(float* c, const uint32_t* a, const uint32_t* b) {
    asm volatile(
        "mma.sync.aligned.m16n8k16.row.col.f32.bf16.bf16.f32 "
        "{%0,%1,%2,%3}, {%4,%5,%6,%7}, {%8,%9}, {%0,%1,%2,%3};"
        : "+f"(c[0]), "+f"(c[1]), "+f"(c[2]), "+f"(c[3])
        : "r"(a[0]), "r"(a[1]), "r"(a[2]), "r"(a[3]), "r"(b[0]), "r"(b[1]));
}

__device__ __forceinline__ uint32_t pack_bf2(__nv_bfloat16 a, __nv_bfloat16 b) {
    return (uint32_t)__bfloat16_as_ushort(a) | ((uint32_t)__bfloat16_as_ushort(b) << 16);
}
__device__ __forceinline__ void split_store2(
    __nv_bfloat16* hi, __nv_bfloat16* lo, size_t idx, float a, float b)
{
    __nv_bfloat16 h0 = __float2bfloat16(a), h1 = __float2bfloat16(b);
    *(uint32_t*)(hi + idx) = pack_bf2(h0, h1);
    *(uint32_t*)(lo + idx) = pack_bf2(__float2bfloat16(a - __bfloat162float(h0)),
                                      __float2bfloat16(b - __bfloat162float(h1)));
}

// ----------------------------- HMMA GEMM ------------------------------------
// C[M,N] = A[M,K] @ B^T[N,K] (hi/lo split) + bias
// EPI: 1=bias+relu->bf16 hi/lo  2=bias+res->fp32  3=bias->bf16 hi/lo
#define STAGES      3
#define KC          64
#define TILE_BYTES  16384            // 128 rows x 128B (64 bf16 K-chunk)
#define STAGE_BYTES (4 * TILE_BYTES) // Ahi, Alo, Bhi, Blo
#define SMEM_BYTES  (STAGES * STAGE_BYTES + 1024)

__device__ __forceinline__ void load_stage(
    uint32_t st_base,
    const __nv_bfloat16* __restrict__ Ahi, const __nv_bfloat16* __restrict__ Alo,
    const __nv_bfloat16* __restrict__ Bhi, const __nv_bfloat16* __restrict__ Blo,
    int bm, int bn, int k0, int K, int tid)
{
    #pragma unroll
    for (int i = 0; i < 16; i++) {
        int id  = tid + i * 256;
        int mat = id >> 10;
        int r   = (id & 1023) >> 3;
        int c   = id & 7;
        uint32_t off = SMEM_SWZ128((uint32_t)(r * 128 + c * 16));
        uint32_t dst = st_base + mat * TILE_BYTES + off;
        const __nv_bfloat16* src;
        if (mat == 0)      src = Ahi + (size_t)(bm + r) * K + k0 + c * 8;
        else if (mat == 1) src = Alo + (size_t)(bm + r) * K + k0 + c * 8;
        else if (mat == 2) src = Bhi + (size_t)(bn + r) * K + k0 + c * 8;
        else               src = Blo + (size_t)(bn + r) * K + k0 + c * 8;
        cp_async16(dst, src);
    }
}

__device__ __forceinline__ void mma_pass(
    float acc[2][8][4], uint32_t Abase, uint32_t Bbase, int wm, int wn, int l)
{
    const int a_row  = wm * 32 + (l & 7) + ((l >> 3) & 1) * 8;
    const int a_kblk = ((l >> 4) & 1) * 8;
    const int b_row  = wn * 64 + ((l >> 4) & 1) * 8 + (l & 7);
    const int b_kblk = ((l >> 3) & 1) * 8;

    #pragma unroll
    for (int ks = 0; ks < 4; ks++) {
        const int k0 = ks * 16;
        uint32_t a[2][4];
        #pragma unroll
        for (int mt = 0; mt < 2; mt++) {
            uint32_t off = SMEM_SWZ128((uint32_t)((a_row + mt * 16) * 128 + (k0 + a_kblk) * 2));
            ldmatrix_x4(a[mt], Abase + off);
        }
        uint32_t b[8][2];
        #pragma unroll
        for (int np = 0; np < 4; np++) {
            uint32_t r[4];
            uint32_t off = SMEM_SWZ128((uint32_t)((b_row + np * 16) * 128 + (k0 + b_kblk) * 2));
            ldmatrix_x4(r, Bbase + off);
            b[np * 2 + 0][0] = r[0]; b[np * 2 + 0][1] = r[1];
            b[np * 2 + 1][0] = r[2]; b[np * 2 + 1][1] = r[3];
        }
        #pragma unroll
        for (int mt = 0; mt < 2; mt++)
            #pragma unroll
            for (int nt = 0; nt < 8; nt++)
                mma_bf16(acc[mt][nt], a[mt], b[nt]);
    }
}

template<int EPI>
__global__ __launch_bounds__(256, 1) void mma_gemm(
    const __nv_bfloat16* __restrict__ Ahi, const __nv_bfloat16* __restrict__ Alo,
    const __nv_bfloat16* __restrict__ Bhi, const __nv_bfloat16* __restrict__ Blo,
    const float* __restrict__ bias, const float* __restrict__ res,
    float* __restrict__ C,
    __nv_bfloat16* __restrict__ Chi, __nv_bfloat16* __restrict__ Clo,
    int M, int N, int K)
{
    extern __shared__ char dsm[];
    const uint32_t smbase = (smem_u32(dsm) + 1023u) & ~1023u;

    const int tid = threadIdx.x;
    const int wid = tid >> 5;
    const int l   = tid & 31;
    const int wm  = wid & 3;
    const int wn  = wid >> 2;
    const int bm  = blockIdx.y * 128;
    const int bn  = blockIdx.x * 128;
    const int NK  = K / KC;

    float acc[2][8][4] = {};

    #pragma unroll
    for (int kc = 0; kc < STAGES; kc++) {
        load_stage(smbase + kc * STAGE_BYTES, Ahi, Alo, Bhi, Blo, bm, bn, kc * KC, K, tid);
        CP_COMMIT();
    }

    for (int kc = 0; kc < NK; kc++) {
        const int s = kc % STAGES;
        const uint32_t st = smbase + s * STAGE_BYTES;
        CP_WAIT2();
        __syncthreads();

        mma_pass(acc, st,              st + 2 * TILE_BYTES, wm, wn, l);
        mma_pass(acc, st,              st + 3 * TILE_BYTES, wm, wn, l);
        mma_pass(acc, st + TILE_BYTES, st + 2 * TILE_BYTES, wm, wn, l);

        __syncthreads();
        if (kc + STAGES < NK)
            load_stage(st, Ahi, Alo, Bhi, Blo, bm, bn, (kc + STAGES) * KC, K, tid);
        CP_COMMIT();
    }

    const int g = l >> 2;
    const int t2 = (l & 3) * 2;
    #pragma unroll
    for (int mt = 0; mt < 2; mt++) {
        const int r0 = bm + wm * 32 + mt * 16 + g;
        #pragma unroll
        for (int nt = 0; nt < 8; nt++) {
            const int col = bn + wn * 64 + nt * 8 + t2;
            float2 p0 = { acc[mt][nt][0] + bias[col], acc[mt][nt][1] + bias[col + 1] };
            float2 p1 = { acc[mt][nt][2] + bias[col], acc[mt][nt][3] + bias[col + 1] };
            if (EPI == 1) {
                p0.x = fmaxf(p0.x, 0.f); p0.y = fmaxf(p0.y, 0.f);
                p1.x = fmaxf(p1.x, 0.f); p1.y = fmaxf(p1.y, 0.f);
            }
            if (EPI == 2) {
                float2 q0 = *(const float2*)(res + (size_t)r0 * N + col);
                float2 q1 = *(const float2*)(res + (size_t)(r0 + 8) * N + col);
                p0.x += q0.x; p0.y += q0.y;
                p1.x += q1.x; p1.y += q1.y;
                *(float2*)(C + (size_t)r0 * N + col) = p0;
                *(float2*)(C + (size_t)(r0 + 8) * N + col) = p1;
            }
            if (EPI == 1 || EPI == 3) {
                split_store2(Chi, Clo, (size_t)r0 * N + col, p0.x, p0.y);
                split_store2(Chi, Clo, (size_t)(r0 + 8) * N + col, p1.x, p1.y);
            }
        }
    }
}

// --------------------------- flash attention ---------------------------------
// grid (SEQ/128, NBH); 256 threads; Bq=128, Bk=64. qkv packed [row][3072].
#define FL_SMEM (32768 + 2 * 32768 + 1024)
#define FL_TILES (SEQ / 64)

__device__ __forceinline__ void fl_load_kv(
    uint32_t st, const __nv_bfloat16* qkvh, const __nv_bfloat16* qkvl,
    size_t rowbase, int colbase, int kv0, int tid)
{
    #pragma unroll
    for (int i = 0; i < 8; i++) {
        int id  = tid + i * 256;          // 0..2047
        int mat = id >> 9;                // 0=Khi 1=Klo 2=Vhi 3=Vlo
        int r   = (id >> 3) & 63;
        int c   = id & 7;
        uint32_t off = SMEM_SWZ128((uint32_t)(r * 128 + c * 16));
        const __nv_bfloat16* base = ((mat & 1) ? qkvl : qkvh);
        int colb = colbase + ((mat < 2) ? 1024 : 2048);   // K block / V block
        cp_async16(st + mat * 8192 + off,
                   base + (rowbase + kv0 + r) * QKVLD + colb + c * 8);
    }
}

__device__ __forceinline__ void fl_qk_pass(
    float sa[8][4], uint32_t Qb, uint32_t Kb, int a_row, int a_kb, int b_row, int b_kb)
{
    #pragma unroll
    for (int ks = 0; ks < 4; ks++) {
        uint32_t a[4];
        ldmatrix_x4(a, Qb + SMEM_SWZ128((uint32_t)(a_row * 128 + (ks * 16 + a_kb) * 2)));
        #pragma unroll
        for (int nt2 = 0; nt2 < 4; nt2++) {
            uint32_t r[4];
            ldmatrix_x4(r, Kb + SMEM_SWZ128((uint32_t)((nt2 * 16 + b_row) * 128 + (ks * 16 + b_kb) * 2)));
            mma_bf16(sa[nt2 * 2 + 0], a, &r[0]);
            mma_bf16(sa[nt2 * 2 + 1], a, &r[2]);
        }
    }
}

__device__ __forceinline__ void fl_pv_pass(
    float ao[8][4], const uint32_t pf[4][4], uint32_t Vb, int v_row, int v_cb)
{
    #pragma unroll
    for (int ks = 0; ks < 4; ks++) {
        #pragma unroll
        for (int nd2 = 0; nd2 < 4; nd2++) {
            uint32_t r[4];
            ldmatrix_x4_t(r, Vb + SMEM_SWZ128((uint32_t)((ks * 16 + v_row) * 128 + (nd2 * 16 + v_cb) * 2)));
            mma_bf16(ao[nd2 * 2 + 0], pf[ks], &r[0]);
            mma_bf16(ao[nd2 * 2 + 1], pf[ks], &r[2]);
        }
    }
}

__global__ __launch_bounds__(256, 1) void flash_kernel(
    const __nv_bfloat16* __restrict__ qkvh, const __nv_bfloat16* __restrict__ qkvl,
    __nv_bfloat16* __restrict__ outh, __nv_bfloat16* __restrict__ outl)
{
    extern __shared__ char dsm[];
    const uint32_t sm = (smem_u32(dsm) + 1023u) & ~1023u;

    const int tid = threadIdx.x;
    const int w = tid >> 5, l = tid & 31;
    const int qt = blockIdx.x, bh = blockIdx.y;
    const int b = bh >> 4, h = bh & 15;
    const size_t rowbase = (size_t)b * SEQ;
    const int colbase = h * HEADDIM;
    const int q0 = qt * 128;

    // load Q hi/lo (128 rows x 128B each)
    #pragma unroll
    for (int i = 0; i < 8; i++) {
        int id  = tid + i * 256;
        int mat = id >> 10;
        int r   = (id >> 3) & 127;
        int c   = id & 7;
        uint32_t off = SMEM_SWZ128((uint32_t)(r * 128 + c * 16));
        const __nv_bfloat16* src = ((mat == 0) ? qkvh : qkvl)
            + (rowbase + q0 + r) * QKVLD + colbase + c * 8;
        cp_async16(sm + mat * 16384 + off, src);
    }
    CP_COMMIT();
    fl_load_kv(sm + 32768, qkvh, qkvl, rowbase, colbase, 0, tid);
    CP_COMMIT();

    const uint32_t Qhi_s = sm, Qlo_s = sm + 16384;
    const int a_row = w * 16 + (l & 7) + ((l >> 3) & 1) * 8;
    const int a_kb  = ((l >> 4) & 1) * 8;
    const int b_row = ((l >> 4) & 1) * 8 + (l & 7);
    const int b_kb  = ((l >> 3) & 1) * 8;
    const int v_row = (l & 15);
    const int v_cb  = ((l >> 4) & 1) * 8;

    float m0 = -1e30f, m1 = -1e30f, l0 = 0.f, l1 = 0.f;
    float ao[8][4] = {};
    const float SC2 = 0.18033688011112042f;  // (1/8) * log2(e)

    for (int t = 0; t < FL_TILES; t++) {
        const uint32_t st = sm + 32768 + (uint32_t)(t & 1) * 32768;
        if (t + 1 < FL_TILES) {
            fl_load_kv(sm + 32768 + (uint32_t)((t + 1) & 1) * 32768,
                       qkvh, qkvl, rowbase, colbase, (t + 1) * 64, tid);
            CP_COMMIT();
            CP_WAIT1();
        } else {
            CP_WAIT0();
        }
        __syncthreads();

        // S = Q K^T  (3 hi/lo passes)
        float sa[8][4] = {};
        fl_qk_pass(sa, Qhi_s, st,        a_row, a_kb, b_row, b_kb);
        fl_qk_pass(sa, Qhi_s, st + 8192, a_row, a_kb, b_row, b_kb);
        fl_qk_pass(sa, Qlo_s, st,        a_row, a_kb, b_row, b_kb);

        // online softmax
        float tm0 = -1e30f, tm1 = -1e30f;
        #pragma unroll
        for (int nt = 0; nt < 8; nt++) {
            tm0 = fmaxf(tm0, fmaxf(sa[nt][0], sa[nt][1]));
            tm1 = fmaxf(tm1, fmaxf(sa[nt][2], sa[nt][3]));
        }
        tm0 = fmaxf(tm0, __shfl_xor_sync(0xffffffffu, tm0, 1));
        tm0 = fmaxf(tm0, __shfl_xor_sync(0xffffffffu, tm0, 2));
        tm1 = fmaxf(tm1, __shfl_xor_sync(0xffffffffu, tm1, 1));
        tm1 = fmaxf(tm1, __shfl_xor_sync(0xffffffffu, tm1, 2));
        const float nm0 = fmaxf(m0, tm0), nm1 = fmaxf(m1, tm1);
        const float al0 = exp2f((m0 - nm0) * SC2);
        const float al1 = exp2f((m1 - nm1) * SC2);
        m0 = nm0; m1 = nm1;

        float rs0 = 0.f, rs1 = 0.f;
        #pragma unroll
        for (int nt = 0; nt < 8; nt++) {
            sa[nt][0] = exp2f((sa[nt][0] - m0) * SC2);
            sa[nt][1] = exp2f((sa[nt][1] - m0) * SC2);
            sa[nt][2] = exp2f((sa[nt][2] - m1) * SC2);
            sa[nt][3] = exp2f((sa[nt][3] - m1) * SC2);
            rs0 += sa[nt][0] + sa[nt][1];
            rs1 += sa[nt][2] + sa[nt][3];
        }
        rs0 += __shfl_xor_sync(0xffffffffu, rs0, 1);
        rs0 += __shfl_xor_sync(0xffffffffu, rs0, 2);
        rs1 += __shfl_xor_sync(0xffffffffu, rs1, 1);
        rs1 += __shfl_xor_sync(0xffffffffu, rs1, 2);
        l0 = l0 * al0 + rs0;
        l1 = l1 * al1 + rs1;

        #pragma unroll
        for (int nd = 0; nd < 8; nd++) {
            ao[nd][0] *= al0; ao[nd][1] *= al0;
            ao[nd][2] *= al1; ao[nd][3] *= al1;
        }

        // P -> bf16 hi/lo A-fragments
        uint32_t ph[4][4], pl[4][4];
        #pragma unroll
        for (int ks = 0; ks < 4; ks++) {
            #pragma unroll
            for (int half = 0; half < 2; half++) {
                const float* s2 = sa[2 * ks + half];
                __nv_bfloat16 h0 = __float2bfloat16(s2[0]);
                __nv_bfloat16 h1 = __float2bfloat16(s2[1]);
                __nv_bfloat16 h2 = __float2bfloat16(s2[2]);
                __nv_bfloat16 h3 = __float2bfloat16(s2[3]);
                ph[ks][0 + 2 * half] = pack_bf2(h0, h1);
                ph[ks][1 + 2 * half] = pack_bf2(h2, h3);
                pl[ks][0 + 2 * half] = pack_bf2(__float2bfloat16(s2[0] - __bfloat162float(h0)),
                                                __float2bfloat16(s2[1] - __bfloat162float(h1)));
                pl[ks][1 + 2 * half] = pack_bf2(__float2bfloat16(s2[2] - __bfloat162float(h2)),
                                                __float2bfloat16(s2[3] - __bfloat162float(h3)));
            }
        }

        // O += P V  (3 hi/lo passes)
        fl_pv_pass(ao, ph, st + 16384, v_row, v_cb);   // Phi * Vhi
        fl_pv_pass(ao, ph, st + 24576, v_row, v_cb);   // Phi * Vlo
        fl_pv_pass(ao, pl, st + 16384, v_row, v_cb);   // Plo * Vhi

        __syncthreads();
    }

    // write O (bf16 hi/lo, stride D_MODEL)
    const float inv0 = 1.0f / l0, inv1 = 1.0f / l1;
    const int g = l >> 2, t2 = (l & 3) * 2;
    const size_t row0 = rowbase + q0 + w * 16 + g;
    #pragma unroll
    for (int nd = 0; nd < 8; nd++) {
        const int col = colbase + nd * 8 + t2;
        split_store2(outh, outl, row0 * D_MODEL + col, ao[nd][0] * inv0, ao[nd][1] * inv0);
        split_store2(outh, outl, (row0 + 8) * D_MODEL + col, ao[nd][2] * inv1, ao[nd][3] * inv1);
    }
}

// --------------------------- conversion kernels ------------------------------
// W [K,N] fp32 -> T [N,K] bf16 hi/lo
__global__ __launch_bounds__(256) void conv_wT(
    const float* __restrict__ W, __nv_bfloat16* __restrict__ Thi,
    __nv_bfloat16* __restrict__ Tlo, int K, int N)
{
    __shared__ float t[32][33];
    const int n0 = blockIdx.x * 32, k0 = blockIdx.y * 32;
    const int tx = threadIdx.x & 31, ty8 = threadIdx.x >> 5;
    #pragma unroll
    for (int j = 0; j < 4; j++) {
        int ky = ty8 + j * 8;
        t[ky][tx] = W[(size_t)(k0 + ky) * N + n0 + tx];
    }
    __syncthreads();
    #pragma unroll
    for (int j = 0; j < 4; j++) {
        int ny = ty8 + j * 8;
        float x = t[tx][ny];
        __nv_bfloat16 h = __float2bfloat16(x);
        Thi[(size_t)(n0 + ny) * K + k0 + tx] = h;
        Tlo[(size_t)(n0 + ny) * K + k0 + tx] = __float2bfloat16(x - __bfloat162float(h));
    }
}

__global__ __launch_bounds__(256) void concat_bias(
    const float* __restrict__ a, const float* __restrict__ b,
    const float* __restrict__ c, float* __restrict__ o)
{
    int i = blockIdx.x * 256 + threadIdx.x;
    if (i >= NQKV) return;
    o[i] = (i < 1024) ? a[i] : (i < 2048) ? b[i - 1024] : c[i - 2048];
}

// ---------------------------- LayerNorm -> hi/lo -----------------------------
__global__ __launch_bounds__(256) void ln_kernel(
    const float* __restrict__ x, const float* __restrict__ scale,
    const float* __restrict__ bias,
    __nv_bfloat16* __restrict__ yh, __nv_bfloat16* __restrict__ yl)
{
    const int row = blockIdx.x;
    const int tid = threadIdx.x;
    const float* xr = x + (size_t)row * D_MODEL;

    float4 v = *(const float4*)(xr + tid * 4);
    float s  = v.x + v.y + v.z + v.w;
    float sq = v.x*v.x + v.y*v.y + v.z*v.z + v.w*v.w;

    #pragma unroll
    for (int o = 16; o > 0; o >>= 1) {
        s  += __shfl_xor_sync(0xffffffffu, s,  o);
        sq += __shfl_xor_sync(0xffffffffu, sq, o);
    }
    __shared__ float rs[8], rq[8];
    int w = tid >> 5, l = tid & 31;
    if (l == 0) { rs[w] = s; rq[w] = sq; }
    __syncthreads();
    float ts = 0.f, tq = 0.f;
    #pragma unroll
    for (int i = 0; i < 8; i++) { ts += rs[i]; tq += rq[i]; }
    float mean = ts * (1.0f / D_MODEL);
    float var  = tq * (1.0f / D_MODEL) - mean * mean;
    float inv  = rsqrtf(var + 1e-6f);

    int c = tid * 4;
    float o0 = (v.x - mean) * inv * scale[c+0] + bias[c+0];
    float o1 = (v.y - mean) * inv * scale[c+1] + bias[c+1];
    float o2 = (v.z - mean) * inv * scale[c+2] + bias[c+2];
    float o3 = (v.w - mean) * inv * scale[c+3] + bias[c+3];
    size_t idx = (size_t)row * D_MODEL + c;
    split_store2(yh, yl, idx, o0, o1);
    split_store2(yh, yl, idx + 2, o2, o3);
}

// --------------------------------- launch -----------------------------------
extern "C" void kernel_launch(void* const* d_in, const int* in_sizes, int n_in,
                              void* d_out, int out_size)
{
    const float* x   = (const float*)d_in[0];
    const float* Wq  = (const float*)d_in[1];
    const float* bq  = (const float*)d_in[2];
    const float* Wk  = (const float*)d_in[3];
    const float* bk  = (const float*)d_in[4];
    const float* Wv  = (const float*)d_in[5];
    const float* bv  = (const float*)d_in[6];
    const float* Wo  = (const float*)d_in[7];
    const float* bo  = (const float*)d_in[8];
    const float* W1  = (const float*)d_in[9];
    const float* b1  = (const float*)d_in[10];
    const float* W2  = (const float*)d_in[11];
    const float* b2  = (const float*)d_in[12];
    const float* ln1s = (const float*)d_in[13];
    const float* ln1b = (const float*)d_in[14];
    const float* ln2s = (const float*)d_in[15];
    const float* ln2b = (const float*)d_in[16];
    float* out = (float*)d_out;

    float *x1, *bqkv;
    cudaGetSymbolAddress((void**)&x1,   g_x1);
    cudaGetSymbolAddress((void**)&bqkv, g_bqkv);

    __nv_bfloat16 *wqkvh,*wqkvl,*woh,*wol,*w1h,*w1l,*w2h,*w2l;
    __nv_bfloat16 *xsh,*xsl,*ffh,*ffl,*qkvh,*qkvl;
    cudaGetSymbolAddress((void**)&wqkvh, g_wqkvT_hi); cudaGetSymbolAddress((void**)&wqkvl, g_wqkvT_lo);
    cudaGetSymbolAddress((void**)&woh, g_woT_hi); cudaGetSymbolAddress((void**)&wol, g_woT_lo);
    cudaGetSymbolAddress((void**)&w1h, g_w1T_hi); cudaGetSymbolAddress((void**)&w1l, g_w1T_lo);
    cudaGetSymbolAddress((void**)&w2h, g_w2T_hi); cudaGetSymbolAddress((void**)&w2l, g_w2T_lo);
    cudaGetSymbolAddress((void**)&xsh, g_xs_hi);  cudaGetSymbolAddress((void**)&xsl, g_xs_lo);
    cudaGetSymbolAddress((void**)&ffh, g_ff_hi);  cudaGetSymbolAddress((void**)&ffl, g_ff_lo);
    cudaGetSymbolAddress((void**)&qkvh, g_qkv_hi); cudaGetSymbolAddress((void**)&qkvl, g_qkv_lo);

    cudaFuncSetAttribute(mma_gemm<1>, cudaFuncAttributeMaxDynamicSharedMemorySize, SMEM_BYTES);
    cudaFuncSetAttribute(mma_gemm<2>, cudaFuncAttributeMaxDynamicSharedMemorySize, SMEM_BYTES);
    cudaFuncSetAttribute(mma_gemm<3>, cudaFuncAttributeMaxDynamicSharedMemorySize, SMEM_BYTES);
    cudaFuncSetAttribute(flash_kernel, cudaFuncAttributeMaxDynamicSharedMemorySize, FL_SMEM);

    // weight conversions (transpose + split); QKV concatenated [3072,1024]
    conv_wT<<<dim3(D_MODEL/32, D_MODEL/32), 256>>>(Wq, wqkvh,                       wqkvl,                       D_MODEL, D_MODEL);
    conv_wT<<<dim3(D_MODEL/32, D_MODEL/32), 256>>>(Wk, wqkvh + 1024 * D_MODEL,      wqkvl + 1024 * D_MODEL,      D_MODEL, D_MODEL);
    conv_wT<<<dim3(D_MODEL/32, D_MODEL/32), 256>>>(Wv, wqkvh + 2048 * D_MODEL,      wqkvl + 2048 * D_MODEL,      D_MODEL, D_MODEL);
    conv_wT<<<dim3(D_MODEL/32, D_MODEL/32), 256>>>(Wo, woh, wol, D_MODEL, D_MODEL);
    conv_wT<<<dim3(D_FF/32,    D_MODEL/32), 256>>>(W1, w1h, w1l, D_MODEL, D_FF);
    conv_wT<<<dim3(D_MODEL/32, D_FF/32),    256>>>(W2, w2h, w2l, D_FF, D_MODEL);
    concat_bias<<<NQKV / 256, 256>>>(bq, bk, bv, bqkv);

    // 1) LN1 -> bf16 hi/lo
    ln_kernel<<<NROWS, 256>>>(x, ln1s, ln1b, xsh, xsl);

    // 2) fused QKV projection -> qkv hi/lo [row][3072]
    mma_gemm<3><<<dim3(NQKV/128, NROWS/128), 256, SMEM_BYTES>>>(
        xsh, xsl, wqkvh, wqkvl, bqkv, nullptr, nullptr, qkvh, qkvl, NROWS, NQKV, D_MODEL);

    // 3) flash attention -> xs hi/lo
    flash_kernel<<<dim3(SEQ/128, NBH), 256, FL_SMEM>>>(qkvh, qkvl, xsh, xsl);

    // 4) x1 = x + attn @ Wo + bo (fp32)
    mma_gemm<2><<<dim3(D_MODEL/128, NROWS/128), 256, SMEM_BYTES>>>(
        xsh, xsl, woh, wol, bo, x, x1, nullptr, nullptr, NROWS, D_MODEL, D_MODEL);

    // 5) LN2 -> xs hi/lo
    ln_kernel<<<NROWS, 256>>>(x1, ln2s, ln2b, xsh, xsl);

    // 6) ff = relu(h @ W1 + b1) -> ff hi/lo
    mma_gemm<1><<<dim3(D_FF/128, NROWS/128), 256, SMEM_BYTES>>>(
        xsh, xsl, w1h, w1l, b1, nullptr, nullptr, ffh, ffl, NROWS, D_FF, D_MODEL);

    // 7) out = x1 + ff @ W2 + b2 (fp32)
    mma_gemm<2><<<dim3(D_MODEL/128, NROWS/128), 256, SMEM_BYTES>>>(
        ffh, ffl, w2h, w2l, b2, x1, out, nullptr, nullptr, NROWS, D_MODEL, D_FF);
}

// round 9
// speedup vs baseline: 4.0877x; 1.3446x over previous
#include <cuda_runtime.h>
#include <cuda_fp16.h>
#include <cstdint>
#include <math.h>

// ---------------------------------------------------------------------------
// TransformerBlock: fp16 2-pass HMMA GEMMs (A full-precision via hi/lo, B fp16)
// + fused flash attention. B=2, S=2048, D=1024, H=16, Dh=64, FF=4096.
// ---------------------------------------------------------------------------

#define D_MODEL 1024
#define SEQ     2048
#define BATCH   2
#define NHEADS  16
#define HEADDIM 64
#define D_FF    4096
#define NROWS   (BATCH * SEQ)          // 4096
#define NBH     (BATCH * NHEADS)       // 32
#define NQKV    3072
#define QKVLD   3072

// ------------------------- scratch (no allocations) ------------------------
__device__ float g_x1[NROWS * D_MODEL];

// activations fp16 hi/lo
__device__ __half g_xs_hi[NROWS * D_MODEL];
__device__ __half g_xs_lo[NROWS * D_MODEL];
__device__ __half g_ff_hi[(size_t)NROWS * D_FF];
__device__ __half g_ff_lo[(size_t)NROWS * D_FF];
__device__ __half g_qkv_hi[(size_t)NROWS * NQKV];
__device__ __half g_qkv_lo[(size_t)NROWS * NQKV];

// weights fp16 (transposed [N,K]) — hi only (2-pass scheme)
__device__ __half g_wqkvT[NQKV * D_MODEL];
__device__ __half g_woT[D_MODEL * D_MODEL];
__device__ __half g_w1T[D_FF * D_MODEL];
__device__ __half g_w2T[D_MODEL * D_FF];
__device__ float g_bqkv[NQKV];

// ------------------------------- PTX helpers --------------------------------
__device__ __forceinline__ uint32_t smem_u32(const void* p) {
    uint32_t a;
    asm("{ .reg .u64 t; cvta.to.shared.u64 t, %1; cvt.u32.u64 %0, t; }"
        : "=r"(a) : "l"(p));
    return a;
}

#define SMEM_SWZ128(off) ((off) ^ (((off) >> 3) & 0x70))

__device__ __forceinline__ void cp_async16(uint32_t dst, const void* src) {
    asm volatile("cp.async.cg.shared.global [%0], [%1], 16;"
                 :: "r"(dst), "l"(__cvta_generic_to_global(src)) : "memory");
}
#define CP_COMMIT() asm volatile("cp.async.commit_group;" ::: "memory")
#define CP_WAIT2()  asm volatile("cp.async.wait_group 2;" ::: "memory")
#define CP_WAIT1()  asm volatile("cp.async.wait_group 1;" ::: "memory")
#define CP_WAIT0()  asm volatile("cp.async.wait_group 0;" ::: "memory")

__device__ __forceinline__ void ldmatrix_x4(uint32_t* r, uint32_t addr) {
    asm volatile("ldmatrix.sync.aligned.m8n8.x4.shared.b16 {%0,%1,%2,%3}, [%4];"
                 : "=r"(r[0]), "=r"(r[1]), "=r"(r[2]), "=r"(r[3]) : "r"(addr));
}
__device__ __forceinline__ void ldmatrix_x4_t(uint32_t* r, uint32_t addr) {
    asm volatile("ldmatrix.sync.aligned.m8n8.x4.trans.shared.b16 {%0,%1,%2,%3}, [%4];"
                 : "=r"(r[0]), "=r"(r[1]), "=r"(r[2]), "=r"(r[3]) : "r"(addr));
}

__device__ __forceinline__ void mma_f16(float* c, const uint32_t* a, const uint32_t* b) {
    asm volatile(
        "mma.sync.aligned.m16n8k16.row.col.f32.f16.f16.f32 "
        "{%0,%1,%2,%3}, {%4,%5,%6,%7}, {%8,%9}, {%0,%1,%2,%3};"
        : "+f"(c[0]), "+f"(c[1]), "+f"(c[2]), "+f"(c[3])
        : "r"(a[0]), "r"(a[1]), "r"(a[2]), "r"(a[3]), "r"(b[0]), "r"(b[1]));
}

__device__ __forceinline__ uint32_t pack_h2(__half a, __half b) {
    return (uint32_t)__half_as_ushort(a) | ((uint32_t)__half_as_ushort(b) << 16);
}
__device__ __forceinline__ void split_store2(
    __half* hi, __half* lo, size_t idx, float a, float b)
{
    __half h0 = __float2half(a), h1 = __float2half(b);
    *(uint32_t*)(hi + idx) = pack_h2(h0, h1);
    *(uint32_t*)(lo + idx) = pack_h2(__float2half(a - __half2float(h0)),
                                     __float2half(b - __half2float(h1)));
}

// ----------------------------- HMMA GEMM ------------------------------------
// C[M,N] = A[M,K] @ B^T[N,K], A = Ahi+Alo (fp16 pair), B = fp16. 2 MMA passes.
// EPI: 1=bias+relu->fp16 hi/lo  2=bias+res->fp32  3=bias->fp16 hi/lo
#define STAGES      3
#define KC          64
#define TILE_BYTES  16384            // 128 rows x 128B (64 fp16 K-chunk)
#define STAGE_BYTES (3 * TILE_BYTES) // Ahi, Alo, B
#define SMEM_BYTES  (STAGES * STAGE_BYTES + 1024)

__device__ __forceinline__ void load_stage(
    uint32_t st_base,
    const __half* __restrict__ Ahi, const __half* __restrict__ Alo,
    const __half* __restrict__ B,
    int bm, int bn, int k0, int K, int tid)
{
    #pragma unroll
    for (int i = 0; i < 12; i++) {
        int id  = tid + i * 256;          // 0..3071
        int mat = id >> 10;               // 0=Ahi 1=Alo 2=B
        int r   = (id & 1023) >> 3;
        int c   = id & 7;
        uint32_t off = SMEM_SWZ128((uint32_t)(r * 128 + c * 16));
        uint32_t dst = st_base + mat * TILE_BYTES + off;
        const __half* src;
        if (mat == 0)      src = Ahi + (size_t)(bm + r) * K + k0 + c * 8;
        else if (mat == 1) src = Alo + (size_t)(bm + r) * K + k0 + c * 8;
        else               src = B   + (size_t)(bn + r) * K + k0 + c * 8;
        cp_async16(dst, src);
    }
}

__device__ __forceinline__ void mma_pass(
    float acc[2][8][4], uint32_t Abase, uint32_t Bbase, int wm, int wn, int l)
{
    const int a_row  = wm * 32 + (l & 7) + ((l >> 3) & 1) * 8;
    const int a_kblk = ((l >> 4) & 1) * 8;
    const int b_row  = wn * 64 + ((l >> 4) & 1) * 8 + (l & 7);
    const int b_kblk = ((l >> 3) & 1) * 8;

    #pragma unroll
    for (int ks = 0; ks < 4; ks++) {
        const int k0 = ks * 16;
        uint32_t a[2][4];
        #pragma unroll
        for (int mt = 0; mt < 2; mt++) {
            uint32_t off = SMEM_SWZ128((uint32_t)((a_row + mt * 16) * 128 + (k0 + a_kblk) * 2));
            ldmatrix_x4(a[mt], Abase + off);
        }
        uint32_t b[8][2];
        #pragma unroll
        for (int np = 0; np < 4; np++) {
            uint32_t r[4];
            uint32_t off = SMEM_SWZ128((uint32_t)((b_row + np * 16) * 128 + (k0 + b_kblk) * 2));
            ldmatrix_x4(r, Bbase + off);
            b[np * 2 + 0][0] = r[0]; b[np * 2 + 0][1] = r[1];
            b[np * 2 + 1][0] = r[2]; b[np * 2 + 1][1] = r[3];
        }
        #pragma unroll
        for (int mt = 0; mt < 2; mt++)
            #pragma unroll
            for (int nt = 0; nt < 8; nt++)
                mma_f16(acc[mt][nt], a[mt], b[nt]);
    }
}

template<int EPI>
__global__ __launch_bounds__(256, 1) void mma_gemm(
    const __half* __restrict__ Ahi, const __half* __restrict__ Alo,
    const __half* __restrict__ B,
    const float* __restrict__ bias, const float* __restrict__ res,
    float* __restrict__ C,
    __half* __restrict__ Chi, __half* __restrict__ Clo,
    int M, int N, int K)
{
    extern __shared__ char dsm[];
    const uint32_t smbase = (smem_u32(dsm) + 1023u) & ~1023u;

    const int tid = threadIdx.x;
    const int wid = tid >> 5;
    const int l   = tid & 31;
    const int wm  = wid & 3;
    const int wn  = wid >> 2;
    const int bm  = blockIdx.y * 128;
    const int bn  = blockIdx.x * 128;
    const int NK  = K / KC;

    float acc[2][8][4] = {};

    #pragma unroll
    for (int kc = 0; kc < STAGES; kc++) {
        load_stage(smbase + kc * STAGE_BYTES, Ahi, Alo, B, bm, bn, kc * KC, K, tid);
        CP_COMMIT();
    }

    for (int kc = 0; kc < NK; kc++) {
        const int s = kc % STAGES;
        const uint32_t st = smbase + s * STAGE_BYTES;
        CP_WAIT2();
        __syncthreads();

        mma_pass(acc, st,              st + 2 * TILE_BYTES, wm, wn, l);
        mma_pass(acc, st + TILE_BYTES, st + 2 * TILE_BYTES, wm, wn, l);

        __syncthreads();
        if (kc + STAGES < NK)
            load_stage(st, Ahi, Alo, B, bm, bn, (kc + STAGES) * KC, K, tid);
        CP_COMMIT();
    }

    const int g = l >> 2;
    const int t2 = (l & 3) * 2;
    #pragma unroll
    for (int mt = 0; mt < 2; mt++) {
        const int r0 = bm + wm * 32 + mt * 16 + g;
        #pragma unroll
        for (int nt = 0; nt < 8; nt++) {
            const int col = bn + wn * 64 + nt * 8 + t2;
            float2 p0 = { acc[mt][nt][0] + bias[col], acc[mt][nt][1] + bias[col + 1] };
            float2 p1 = { acc[mt][nt][2] + bias[col], acc[mt][nt][3] + bias[col + 1] };
            if (EPI == 1) {
                p0.x = fmaxf(p0.x, 0.f); p0.y = fmaxf(p0.y, 0.f);
                p1.x = fmaxf(p1.x, 0.f); p1.y = fmaxf(p1.y, 0.f);
            }
            if (EPI == 2) {
                float2 q0 = *(const float2*)(res + (size_t)r0 * N + col);
                float2 q1 = *(const float2*)(res + (size_t)(r0 + 8) * N + col);
                p0.x += q0.x; p0.y += q0.y;
                p1.x += q1.x; p1.y += q1.y;
                *(float2*)(C + (size_t)r0 * N + col) = p0;
                *(float2*)(C + (size_t)(r0 + 8) * N + col) = p1;
            }
            if (EPI == 1 || EPI == 3) {
                split_store2(Chi, Clo, (size_t)r0 * N + col, p0.x, p0.y);
                split_store2(Chi, Clo, (size_t)(r0 + 8) * N + col, p1.x, p1.y);
            }
        }
    }
}

// --------------------------- flash attention ---------------------------------
// grid (SEQ/128, NBH); 256 threads; Bq=128, Bk=64. qkv packed [row][3072].
// smem: Qhi @0 (16K), Qlo @16K; KV stages @32K: each 16K = Kh(8K) + Vh(8K).
#define FL_STAGE 16384
#define FL_SMEM (32768 + 2 * FL_STAGE + 1024)
#define FL_TILES (SEQ / 64)

__device__ __forceinline__ void fl_load_kv(
    uint32_t st, const __half* qkvh, size_t rowbase, int colbase, int kv0, int tid)
{
    #pragma unroll
    for (int i = 0; i < 4; i++) {
        int id  = tid + i * 256;          // 0..1023
        int mat = id >> 9;                // 0=Kh 1=Vh
        int r   = (id >> 3) & 63;
        int c   = id & 7;
        uint32_t off = SMEM_SWZ128((uint32_t)(r * 128 + c * 16));
        int colb = colbase + ((mat == 0) ? 1024 : 2048);
        cp_async16(st + mat * 8192 + off,
                   qkvh + (rowbase + kv0 + r) * QKVLD + colb + c * 8);
    }
}

__device__ __forceinline__ void fl_qk_pass(
    float sa[8][4], uint32_t Qb, uint32_t Kb, int a_row, int a_kb, int b_row, int b_kb)
{
    #pragma unroll
    for (int ks = 0; ks < 4; ks++) {
        uint32_t a[4];
        ldmatrix_x4(a, Qb + SMEM_SWZ128((uint32_t)(a_row * 128 + (ks * 16 + a_kb) * 2)));
        #pragma unroll
        for (int nt2 = 0; nt2 < 4; nt2++) {
            uint32_t r[4];
            ldmatrix_x4(r, Kb + SMEM_SWZ128((uint32_t)((nt2 * 16 + b_row) * 128 + (ks * 16 + b_kb) * 2)));
            mma_f16(sa[nt2 * 2 + 0], a, &r[0]);
            mma_f16(sa[nt2 * 2 + 1], a, &r[2]);
        }
    }
}

__device__ __forceinline__ void fl_pv_pass(
    float ao[8][4], const uint32_t pf[4][4], uint32_t Vb, int v_row, int v_cb)
{
    #pragma unroll
    for (int ks = 0; ks < 4; ks++) {
        #pragma unroll
        for (int nd2 = 0; nd2 < 4; nd2++) {
            uint32_t r[4];
            ldmatrix_x4_t(r, Vb + SMEM_SWZ128((uint32_t)((ks * 16 + v_row) * 128 + (nd2 * 16 + v_cb) * 2)));
            mma_f16(ao[nd2 * 2 + 0], pf[ks], &r[0]);
            mma_f16(ao[nd2 * 2 + 1], pf[ks], &r[2]);
        }
    }
}

__global__ __launch_bounds__(256, 1) void flash_kernel(
    const __half* __restrict__ qkvh, const __half* __restrict__ qkvl,
    __half* __restrict__ outh, __half* __restrict__ outl)
{
    extern __shared__ char dsm[];
    const uint32_t sm = (smem_u32(dsm) + 1023u) & ~1023u;

    const int tid = threadIdx.x;
    const int w = tid >> 5, l = tid & 31;
    const int qt = blockIdx.x, bh = blockIdx.y;
    const int b = bh >> 4, h = bh & 15;
    const size_t rowbase = (size_t)b * SEQ;
    const int colbase = h * HEADDIM;
    const int q0 = qt * 128;

    // load Q hi/lo (128 rows x 128B each)
    #pragma unroll
    for (int i = 0; i < 8; i++) {
        int id  = tid + i * 256;
        int mat = id >> 10;
        int r   = (id >> 3) & 127;
        int c   = id & 7;
        uint32_t off = SMEM_SWZ128((uint32_t)(r * 128 + c * 16));
        const __half* src = ((mat == 0) ? qkvh : qkvl)
            + (rowbase + q0 + r) * QKVLD + colbase + c * 8;
        cp_async16(sm + mat * 16384 + off, src);
    }
    CP_COMMIT();
    fl_load_kv(sm + 32768, qkvh, rowbase, colbase, 0, tid);
    CP_COMMIT();

    const uint32_t Qhi_s = sm, Qlo_s = sm + 16384;
    const int a_row = w * 16 + (l & 7) + ((l >> 3) & 1) * 8;
    const int a_kb  = ((l >> 4) & 1) * 8;
    const int b_row = ((l >> 4) & 1) * 8 + (l & 7);
    const int b_kb  = ((l >> 3) & 1) * 8;
    const int v_row = (l & 15);
    const int v_cb  = ((l >> 4) & 1) * 8;

    float m0 = -1e30f, m1 = -1e30f, l0 = 0.f, l1 = 0.f;
    float ao[8][4] = {};
    const float SC2 = 0.18033688011112042f;  // (1/8) * log2(e)

    for (int t = 0; t < FL_TILES; t++) {
        const uint32_t st = sm + 32768 + (uint32_t)(t & 1) * FL_STAGE;
        if (t + 1 < FL_TILES) {
            fl_load_kv(sm + 32768 + (uint32_t)((t + 1) & 1) * FL_STAGE,
                       qkvh, rowbase, colbase, (t + 1) * 64, tid);
            CP_COMMIT();
            CP_WAIT1();
        } else {
            CP_WAIT0();
        }
        __syncthreads();

        // S = Q K^T  (2 passes: Qhi*K + Qlo*K)
        float sa[8][4] = {};
        fl_qk_pass(sa, Qhi_s, st, a_row, a_kb, b_row, b_kb);
        fl_qk_pass(sa, Qlo_s, st, a_row, a_kb, b_row, b_kb);

        // online softmax
        float tm0 = -1e30f, tm1 = -1e30f;
        #pragma unroll
        for (int nt = 0; nt < 8; nt++) {
            tm0 = fmaxf(tm0, fmaxf(sa[nt][0], sa[nt][1]));
            tm1 = fmaxf(tm1, fmaxf(sa[nt][2], sa[nt][3]));
        }
        tm0 = fmaxf(tm0, __shfl_xor_sync(0xffffffffu, tm0, 1));
        tm0 = fmaxf(tm0, __shfl_xor_sync(0xffffffffu, tm0, 2));
        tm1 = fmaxf(tm1, __shfl_xor_sync(0xffffffffu, tm1, 1));
        tm1 = fmaxf(tm1, __shfl_xor_sync(0xffffffffu, tm1, 2));
        const float nm0 = fmaxf(m0, tm0), nm1 = fmaxf(m1, tm1);
        const float al0 = exp2f((m0 - nm0) * SC2);
        const float al1 = exp2f((m1 - nm1) * SC2);
        m0 = nm0; m1 = nm1;

        float rs0 = 0.f, rs1 = 0.f;
        #pragma unroll
        for (int nt = 0; nt < 8; nt++) {
            sa[nt][0] = exp2f((sa[nt][0] - m0) * SC2);
            sa[nt][1] = exp2f((sa[nt][1] - m0) * SC2);
            sa[nt][2] = exp2f((sa[nt][2] - m1) * SC2);
            sa[nt][3] = exp2f((sa[nt][3] - m1) * SC2);
            rs0 += sa[nt][0] + sa[nt][1];
            rs1 += sa[nt][2] + sa[nt][3];
        }
        rs0 += __shfl_xor_sync(0xffffffffu, rs0, 1);
        rs0 += __shfl_xor_sync(0xffffffffu, rs0, 2);
        rs1 += __shfl_xor_sync(0xffffffffu, rs1, 1);
        rs1 += __shfl_xor_sync(0xffffffffu, rs1, 2);
        l0 = l0 * al0 + rs0;
        l1 = l1 * al1 + rs1;

        #pragma unroll
        for (int nd = 0; nd < 8; nd++) {
            ao[nd][0] *= al0; ao[nd][1] *= al0;
            ao[nd][2] *= al1; ao[nd][3] *= al1;
        }

        // P -> fp16 hi/lo A-fragments
        uint32_t ph[4][4], pl[4][4];
        #pragma unroll
        for (int ks = 0; ks < 4; ks++) {
            #pragma unroll
            for (int half2i = 0; half2i < 2; half2i++) {
                const float* s2 = sa[2 * ks + half2i];
                __half h0 = __float2half(s2[0]);
                __half h1 = __float2half(s2[1]);
                __half h2 = __float2half(s2[2]);
                __half h3 = __float2half(s2[3]);
                ph[ks][0 + 2 * half2i] = pack_h2(h0, h1);
                ph[ks][1 + 2 * half2i] = pack_h2(h2, h3);
                pl[ks][0 + 2 * half2i] = pack_h2(__float2half(s2[0] - __half2float(h0)),
                                                 __float2half(s2[1] - __half2float(h1)));
                pl[ks][1 + 2 * half2i] = pack_h2(__float2half(s2[2] - __half2float(h2)),
                                                 __float2half(s2[3] - __half2float(h3)));
            }
        }

        // O += P V  (2 passes: Phi*Vh + Plo*Vh)
        fl_pv_pass(ao, ph, st + 8192, v_row, v_cb);
        fl_pv_pass(ao, pl, st + 8192, v_row, v_cb);

        __syncthreads();
    }

    // write O (fp16 hi/lo, stride D_MODEL)
    const float inv0 = 1.0f / l0, inv1 = 1.0f / l1;
    const int g = l >> 2, t2 = (l & 3) * 2;
    const size_t row0 = rowbase + q0 + w * 16 + g;
    #pragma unroll
    for (int nd = 0; nd < 8; nd++) {
        const int col = colbase + nd * 8 + t2;
        split_store2(outh, outl, row0 * D_MODEL + col, ao[nd][0] * inv0, ao[nd][1] * inv0);
        split_store2(outh, outl, (row0 + 8) * D_MODEL + col, ao[nd][2] * inv1, ao[nd][3] * inv1);
    }
}

// --------------------------- conversion kernels ------------------------------
// W [K,N] fp32 -> T [N,K] fp16
__global__ __launch_bounds__(256) void conv_wT(
    const float* __restrict__ W, __half* __restrict__ T, int K, int N)
{
    __shared__ float t[32][33];
    const int n0 = blockIdx.x * 32, k0 = blockIdx.y * 32;
    const int tx = threadIdx.x & 31, ty8 = threadIdx.x >> 5;
    #pragma unroll
    for (int j = 0; j < 4; j++) {
        int ky = ty8 + j * 8;
        t[ky][tx] = W[(size_t)(k0 + ky) * N + n0 + tx];
    }
    __syncthreads();
    #pragma unroll
    for (int j = 0; j < 4; j++) {
        int ny = ty8 + j * 8;
        T[(size_t)(n0 + ny) * K + k0 + tx] = __float2half(t[tx][ny]);
    }
}

__global__ __launch_bounds__(256) void concat_bias(
    const float* __restrict__ a, const float* __restrict__ b,
    const float* __restrict__ c, float* __restrict__ o)
{
    int i = blockIdx.x * 256 + threadIdx.x;
    if (i >= NQKV) return;
    o[i] = (i < 1024) ? a[i] : (i < 2048) ? b[i - 1024] : c[i - 2048];
}

// ---------------------------- LayerNorm -> hi/lo -----------------------------
__global__ __launch_bounds__(256) void ln_kernel(
    const float* __restrict__ x, const float* __restrict__ scale,
    const float* __restrict__ bias,
    __half* __restrict__ yh, __half* __restrict__ yl)
{
    const int row = blockIdx.x;
    const int tid = threadIdx.x;
    const float* xr = x + (size_t)row * D_MODEL;

    float4 v = *(const float4*)(xr + tid * 4);
    float s  = v.x + v.y + v.z + v.w;
    float sq = v.x*v.x + v.y*v.y + v.z*v.z + v.w*v.w;

    #pragma unroll
    for (int o = 16; o > 0; o >>= 1) {
        s  += __shfl_xor_sync(0xffffffffu, s,  o);
        sq += __shfl_xor_sync(0xffffffffu, sq, o);
    }
    __shared__ float rs[8], rq[8];
    int w = tid >> 5, l = tid & 31;
    if (l == 0) { rs[w] = s; rq[w] = sq; }
    __syncthreads();
    float ts = 0.f, tq = 0.f;
    #pragma unroll
    for (int i = 0; i < 8; i++) { ts += rs[i]; tq += rq[i]; }
    float mean = ts * (1.0f / D_MODEL);
    float var  = tq * (1.0f / D_MODEL) - mean * mean;
    float inv  = rsqrtf(var + 1e-6f);

    int c = tid * 4;
    float o0 = (v.x - mean) * inv * scale[c+0] + bias[c+0];
    float o1 = (v.y - mean) * inv * scale[c+1] + bias[c+1];
    float o2 = (v.z - mean) * inv * scale[c+2] + bias[c+2];
    float o3 = (v.w - mean) * inv * scale[c+3] + bias[c+3];
    size_t idx = (size_t)row * D_MODEL + c;
    split_store2(yh, yl, idx, o0, o1);
    split_store2(yh, yl, idx + 2, o2, o3);
}

// --------------------------------- launch -----------------------------------
extern "C" void kernel_launch(void* const* d_in, const int* in_sizes, int n_in,
                              void* d_out, int out_size)
{
    const float* x   = (const float*)d_in[0];
    const float* Wq  = (const float*)d_in[1];
    const float* bq  = (const float*)d_in[2];
    const float* Wk  = (const float*)d_in[3];
    const float* bk  = (const float*)d_in[4];
    const float* Wv  = (const float*)d_in[5];
    const float* bv  = (const float*)d_in[6];
    const float* Wo  = (const float*)d_in[7];
    const float* bo  = (const float*)d_in[8];
    const float* W1  = (const float*)d_in[9];
    const float* b1  = (const float*)d_in[10];
    const float* W2  = (const float*)d_in[11];
    const float* b2  = (const float*)d_in[12];
    const float* ln1s = (const float*)d_in[13];
    const float* ln1b = (const float*)d_in[14];
    const float* ln2s = (const float*)d_in[15];
    const float* ln2b = (const float*)d_in[16];
    float* out = (float*)d_out;

    float *x1, *bqkv;
    cudaGetSymbolAddress((void**)&x1,   g_x1);
    cudaGetSymbolAddress((void**)&bqkv, g_bqkv);

    __half *wqkv,*wo,*w1,*w2,*xsh,*xsl,*ffh,*ffl,*qkvh,*qkvl;
    cudaGetSymbolAddress((void**)&wqkv, g_wqkvT);
    cudaGetSymbolAddress((void**)&wo,   g_woT);
    cudaGetSymbolAddress((void**)&w1,   g_w1T);
    cudaGetSymbolAddress((void**)&w2,   g_w2T);
    cudaGetSymbolAddress((void**)&xsh,  g_xs_hi);  cudaGetSymbolAddress((void**)&xsl, g_xs_lo);
    cudaGetSymbolAddress((void**)&ffh,  g_ff_hi);  cudaGetSymbolAddress((void**)&ffl, g_ff_lo);
    cudaGetSymbolAddress((void**)&qkvh, g_qkv_hi); cudaGetSymbolAddress((void**)&qkvl, g_qkv_lo);

    cudaFuncSetAttribute(mma_gemm<1>, cudaFuncAttributeMaxDynamicSharedMemorySize, SMEM_BYTES);
    cudaFuncSetAttribute(mma_gemm<2>, cudaFuncAttributeMaxDynamicSharedMemorySize, SMEM_BYTES);
    cudaFuncSetAttribute(mma_gemm<3>, cudaFuncAttributeMaxDynamicSharedMemorySize, SMEM_BYTES);
    cudaFuncSetAttribute(flash_kernel, cudaFuncAttributeMaxDynamicSharedMemorySize, FL_SMEM);

    // weight conversions (transpose, fp16); QKV concatenated [3072,1024]
    conv_wT<<<dim3(D_MODEL/32, D_MODEL/32), 256>>>(Wq, wqkv,                  D_MODEL, D_MODEL);
    conv_wT<<<dim3(D_MODEL/32, D_MODEL/32), 256>>>(Wk, wqkv + 1024 * D_MODEL, D_MODEL, D_MODEL);
    conv_wT<<<dim3(D_MODEL/32, D_MODEL/32), 256>>>(Wv, wqkv + 2048 * D_MODEL, D_MODEL, D_MODEL);
    conv_wT<<<dim3(D_MODEL/32, D_MODEL/32), 256>>>(Wo, wo, D_MODEL, D_MODEL);
    conv_wT<<<dim3(D_FF/32,    D_MODEL/32), 256>>>(W1, w1, D_MODEL, D_FF);
    conv_wT<<<dim3(D_MODEL/32, D_FF/32),    256>>>(W2, w2, D_FF, D_MODEL);
    concat_bias<<<NQKV / 256, 256>>>(bq, bk, bv, bqkv);

    // 1) LN1 -> fp16 hi/lo
    ln_kernel<<<NROWS, 256>>>(x, ln1s, ln1b, xsh, xsl);

    // 2) fused QKV projection -> qkv hi/lo [row][3072]
    mma_gemm<3><<<dim3(NQKV/128, NROWS/128), 256, SMEM_BYTES>>>(
        xsh, xsl, wqkv, bqkv, nullptr, nullptr, qkvh, qkvl, NROWS, NQKV, D_MODEL);

    // 3) flash attention -> xs hi/lo
    flash_kernel<<<dim3(SEQ/128, NBH), 256, FL_SMEM>>>(qkvh, qkvl, xsh, xsl);

    // 4) x1 = x + attn @ Wo + bo (fp32)
    mma_gemm<2><<<dim3(D_MODEL/128, NROWS/128), 256, SMEM_BYTES>>>(
        xsh, xsl, wo, bo, x, x1, nullptr, nullptr, NROWS, D_MODEL, D_MODEL);

    // 5) LN2 -> xs hi/lo
    ln_kernel<<<NROWS, 256>>>(x1, ln2s, ln2b, xsh, xsl);

    // 6) ff = relu(h @ W1 + b1) -> ff hi/lo
    mma_gemm<1><<<dim3(D_FF/128, NROWS/128), 256, SMEM_BYTES>>>(
        xsh, xsl, w1, b1, nullptr, nullptr, ffh, ffl, NROWS, D_FF, D_MODEL);

    // 7) out = x1 + ff @ W2 + b2 (fp32)
    mma_gemm<2><<<dim3(D_MODEL/128, NROWS/128), 256, SMEM_BYTES>>>(
        ffh, ffl, w2, b2, x1, out, nullptr, nullptr, NROWS, D_MODEL, D_FF);
}

// round 11
// speedup vs baseline: 6.6341x; 1.6230x over previous
#include <cuda_runtime.h>
#include <cuda_fp16.h>
#include <cstdint>
#include <math.h>

// ---------------------------------------------------------------------------
// TransformerBlock: single-pass fp16 HMMA GEMMs + fused flash attention.
// B=2, S=2048, D=1024, H=16, Dh=64, FF=4096.
// ---------------------------------------------------------------------------

#define D_MODEL 1024
#define SEQ     2048
#define BATCH   2
#define NHEADS  16
#define HEADDIM 64
#define D_FF    4096
#define NROWS   (BATCH * SEQ)          // 4096
#define NBH     (BATCH * NHEADS)       // 32
#define NQKV    3072
#define QKVLD   3072

// ------------------------- scratch (no allocations) ------------------------
__device__ float g_x1[NROWS * D_MODEL];

// activations fp16
__device__ __half g_xs [NROWS * D_MODEL];
__device__ __half g_ff [(size_t)NROWS * D_FF];
__device__ __half g_qkv[(size_t)NROWS * NQKV];

// weights fp16 (transposed [N,K])
__device__ __half g_wqkvT[NQKV * D_MODEL];
__device__ __half g_woT[D_MODEL * D_MODEL];
__device__ __half g_w1T[D_FF * D_MODEL];
__device__ __half g_w2T[D_MODEL * D_FF];
__device__ float g_bqkv[NQKV];

// ------------------------------- PTX helpers --------------------------------
__device__ __forceinline__ uint32_t smem_u32(const void* p) {
    uint32_t a;
    asm("{ .reg .u64 t; cvta.to.shared.u64 t, %1; cvt.u32.u64 %0, t; }"
        : "=r"(a) : "l"(p));
    return a;
}

#define SMEM_SWZ128(off) ((off) ^ (((off) >> 3) & 0x70))

__device__ __forceinline__ void cp_async16(uint32_t dst, const void* src) {
    asm volatile("cp.async.cg.shared.global [%0], [%1], 16;"
                 :: "r"(dst), "l"(__cvta_generic_to_global(src)) : "memory");
}
#define CP_COMMIT() asm volatile("cp.async.commit_group;" ::: "memory")
#define CP_WAIT3()  asm volatile("cp.async.wait_group 3;" ::: "memory")
#define CP_WAIT1()  asm volatile("cp.async.wait_group 1;" ::: "memory")
#define CP_WAIT0()  asm volatile("cp.async.wait_group 0;" ::: "memory")

__device__ __forceinline__ void ldmatrix_x4(uint32_t* r, uint32_t addr) {
    asm volatile("ldmatrix.sync.aligned.m8n8.x4.shared.b16 {%0,%1,%2,%3}, [%4];"
                 : "=r"(r[0]), "=r"(r[1]), "=r"(r[2]), "=r"(r[3]) : "r"(addr));
}
__device__ __forceinline__ void ldmatrix_x4_t(uint32_t* r, uint32_t addr) {
    asm volatile("ldmatrix.sync.aligned.m8n8.x4.trans.shared.b16 {%0,%1,%2,%3}, [%4];"
                 : "=r"(r[0]), "=r"(r[1]), "=r"(r[2]), "=r"(r[3]) : "r"(addr));
}

__device__ __forceinline__ void mma_f16(float* c, const uint32_t* a, const uint32_t* b) {
    asm volatile(
        "mma.sync.aligned.m16n8k16.row.col.f32.f16.f16.f32 "
        "{%0,%1,%2,%3}, {%4,%5,%6,%7}, {%8,%9}, {%0,%1,%2,%3};"
        : "+f"(c[0]), "+f"(c[1]), "+f"(c[2]), "+f"(c[3])
        : "r"(a[0]), "r"(a[1]), "r"(a[2]), "r"(a[3]), "r"(b[0]), "r"(b[1]));
}

__device__ __forceinline__ uint32_t pack_h2(__half a, __half b) {
    return (uint32_t)__half_as_ushort(a) | ((uint32_t)__half_as_ushort(b) << 16);
}
__device__ __forceinline__ void store_h2(__half* dst, size_t idx, float a, float b) {
    *(uint32_t*)(dst + idx) = pack_h2(__float2half(a), __float2half(b));
}

// ----------------------------- HMMA GEMM ------------------------------------
// C[M,N] = A[M,K] @ B^T[N,K], fp16 single pass.
// EPI: 1=bias+relu->fp16  2=bias+res->fp32  3=bias->fp16
#define STAGES      4
#define KC          64
#define TILE_BYTES  16384            // 128 rows x 128B (64 fp16 K-chunk)
#define STAGE_BYTES (2 * TILE_BYTES) // A, B
#define SMEM_BYTES  (STAGES * STAGE_BYTES + 1024)

__device__ __forceinline__ void load_stage(
    uint32_t st_base,
    const __half* __restrict__ A, const __half* __restrict__ B,
    int bm, int bn, int k0, int K, int tid)
{
    #pragma unroll
    for (int i = 0; i < 8; i++) {
        int id  = tid + i * 256;          // 0..2047
        int mat = id >> 10;               // 0=A 1=B
        int r   = (id & 1023) >> 3;
        int c   = id & 7;
        uint32_t off = SMEM_SWZ128((uint32_t)(r * 128 + c * 16));
        uint32_t dst = st_base + mat * TILE_BYTES + off;
        const __half* src = (mat == 0) ? A + (size_t)(bm + r) * K + k0 + c * 8
                                       : B + (size_t)(bn + r) * K + k0 + c * 8;
        cp_async16(dst, src);
    }
}

__device__ __forceinline__ void mma_pass(
    float acc[2][8][4], uint32_t Abase, uint32_t Bbase, int wm, int wn, int l)
{
    const int a_row  = wm * 32 + (l & 7) + ((l >> 3) & 1) * 8;
    const int a_kblk = ((l >> 4) & 1) * 8;
    const int b_row  = wn * 64 + ((l >> 4) & 1) * 8 + (l & 7);
    const int b_kblk = ((l >> 3) & 1) * 8;

    #pragma unroll
    for (int ks = 0; ks < 4; ks++) {
        const int k0 = ks * 16;
        uint32_t a[2][4];
        #pragma unroll
        for (int mt = 0; mt < 2; mt++) {
            uint32_t off = SMEM_SWZ128((uint32_t)((a_row + mt * 16) * 128 + (k0 + a_kblk) * 2));
            ldmatrix_x4(a[mt], Abase + off);
        }
        uint32_t b[8][2];
        #pragma unroll
        for (int np = 0; np < 4; np++) {
            uint32_t r[4];
            uint32_t off = SMEM_SWZ128((uint32_t)((b_row + np * 16) * 128 + (k0 + b_kblk) * 2));
            ldmatrix_x4(r, Bbase + off);
            b[np * 2 + 0][0] = r[0]; b[np * 2 + 0][1] = r[1];
            b[np * 2 + 1][0] = r[2]; b[np * 2 + 1][1] = r[3];
        }
        #pragma unroll
        for (int mt = 0; mt < 2; mt++)
            #pragma unroll
            for (int nt = 0; nt < 8; nt++)
                mma_f16(acc[mt][nt], a[mt], b[nt]);
    }
}

template<int EPI>
__global__ __launch_bounds__(256, 1) void mma_gemm(
    const __half* __restrict__ A, const __half* __restrict__ B,
    const float* __restrict__ bias, const float* __restrict__ res,
    float* __restrict__ C, __half* __restrict__ Ch,
    int M, int N, int K)
{
    extern __shared__ char dsm[];
    const uint32_t smbase = (smem_u32(dsm) + 1023u) & ~1023u;

    const int tid = threadIdx.x;
    const int wid = tid >> 5;
    const int l   = tid & 31;
    const int wm  = wid & 3;
    const int wn  = wid >> 2;
    const int bm  = blockIdx.y * 128;
    const int bn  = blockIdx.x * 128;
    const int NK  = K / KC;

    float acc[2][8][4] = {};

    #pragma unroll
    for (int kc = 0; kc < STAGES; kc++) {
        if (kc < NK) load_stage(smbase + kc * STAGE_BYTES, A, B, bm, bn, kc * KC, K, tid);
        CP_COMMIT();
    }

    for (int kc = 0; kc < NK; kc++) {
        const int s = kc % STAGES;
        const uint32_t st = smbase + s * STAGE_BYTES;
        CP_WAIT3();
        __syncthreads();

        mma_pass(acc, st, st + TILE_BYTES, wm, wn, l);

        __syncthreads();
        if (kc + STAGES < NK)
            load_stage(st, A, B, bm, bn, (kc + STAGES) * KC, K, tid);
        CP_COMMIT();
    }

    const int g = l >> 2;
    const int t2 = (l & 3) * 2;
    #pragma unroll
    for (int mt = 0; mt < 2; mt++) {
        const int r0 = bm + wm * 32 + mt * 16 + g;
        #pragma unroll
        for (int nt = 0; nt < 8; nt++) {
            const int col = bn + wn * 64 + nt * 8 + t2;
            float2 p0 = { acc[mt][nt][0] + bias[col], acc[mt][nt][1] + bias[col + 1] };
            float2 p1 = { acc[mt][nt][2] + bias[col], acc[mt][nt][3] + bias[col + 1] };
            if (EPI == 1) {
                p0.x = fmaxf(p0.x, 0.f); p0.y = fmaxf(p0.y, 0.f);
                p1.x = fmaxf(p1.x, 0.f); p1.y = fmaxf(p1.y, 0.f);
            }
            if (EPI == 2) {
                float2 q0 = *(const float2*)(res + (size_t)r0 * N + col);
                float2 q1 = *(const float2*)(res + (size_t)(r0 + 8) * N + col);
                p0.x += q0.x; p0.y += q0.y;
                p1.x += q1.x; p1.y += q1.y;
                *(float2*)(C + (size_t)r0 * N + col) = p0;
                *(float2*)(C + (size_t)(r0 + 8) * N + col) = p1;
            }
            if (EPI == 1 || EPI == 3) {
                store_h2(Ch, (size_t)r0 * N + col, p0.x, p0.y);
                store_h2(Ch, (size_t)(r0 + 8) * N + col, p1.x, p1.y);
            }
        }
    }
}

// --------------------------- flash attention ---------------------------------
// grid (SEQ/128, NBH); 256 threads; Bq=128, Bk=64. qkv packed [row][3072].
// smem: Q @0 (16K); KV stages @16K: each 16K = K(8K) + V(8K).
#define FL_STAGE 16384
#define FL_SMEM (16384 + 2 * FL_STAGE + 1024)
#define FL_TILES (SEQ / 64)

__device__ __forceinline__ void fl_load_kv(
    uint32_t st, const __half* qkv, size_t rowbase, int colbase, int kv0, int tid)
{
    #pragma unroll
    for (int i = 0; i < 4; i++) {
        int id  = tid + i * 256;          // 0..1023
        int mat = id >> 9;                // 0=K 1=V
        int r   = (id >> 3) & 63;
        int c   = id & 7;
        uint32_t off = SMEM_SWZ128((uint32_t)(r * 128 + c * 16));
        int colb = colbase + ((mat == 0) ? 1024 : 2048);
        cp_async16(st + mat * 8192 + off,
                   qkv + (rowbase + kv0 + r) * QKVLD + colb + c * 8);
    }
}

__device__ __forceinline__ void fl_qk_pass(
    float sa[8][4], uint32_t Qb, uint32_t Kb, int a_row, int a_kb, int b_row, int b_kb)
{
    #pragma unroll
    for (int ks = 0; ks < 4; ks++) {
        uint32_t a[4];
        ldmatrix_x4(a, Qb + SMEM_SWZ128((uint32_t)(a_row * 128 + (ks * 16 + a_kb) * 2)));
        #pragma unroll
        for (int nt2 = 0; nt2 < 4; nt2++) {
            uint32_t r[4];
            ldmatrix_x4(r, Kb + SMEM_SWZ128((uint32_t)((nt2 * 16 + b_row) * 128 + (ks * 16 + b_kb) * 2)));
            mma_f16(sa[nt2 * 2 + 0], a, &r[0]);
            mma_f16(sa[nt2 * 2 + 1], a, &r[2]);
        }
    }
}

__device__ __forceinline__ void fl_pv_pass(
    float ao[8][4], const uint32_t pf[4][4], uint32_t Vb, int v_row, int v_cb)
{
    #pragma unroll
    for (int ks = 0; ks < 4; ks++) {
        #pragma unroll
        for (int nd2 = 0; nd2 < 4; nd2++) {
            uint32_t r[4];
            ldmatrix_x4_t(r, Vb + SMEM_SWZ128((uint32_t)((ks * 16 + v_row) * 128 + (nd2 * 16 + v_cb) * 2)));
            mma_f16(ao[nd2 * 2 + 0], pf[ks], &r[0]);
            mma_f16(ao[nd2 * 2 + 1], pf[ks], &r[2]);
        }
    }
}

__global__ __launch_bounds__(256, 1) void flash_kernel(
    const __half* __restrict__ qkv, __half* __restrict__ outh)
{
    extern __shared__ char dsm[];
    const uint32_t sm = (smem_u32(dsm) + 1023u) & ~1023u;

    const int tid = threadIdx.x;
    const int w = tid >> 5, l = tid & 31;
    const int qt = blockIdx.x, bh = blockIdx.y;
    const int b = bh >> 4, h = bh & 15;
    const size_t rowbase = (size_t)b * SEQ;
    const int colbase = h * HEADDIM;
    const int q0 = qt * 128;

    // load Q (128 rows x 128B)
    #pragma unroll
    for (int i = 0; i < 4; i++) {
        int id  = tid + i * 256;
        int r   = (id >> 3) & 127;
        int c   = id & 7;
        uint32_t off = SMEM_SWZ128((uint32_t)(r * 128 + c * 16));
        cp_async16(sm + off, qkv + (rowbase + q0 + r) * QKVLD + colbase + c * 8);
    }
    CP_COMMIT();
    fl_load_kv(sm + 16384, qkv, rowbase, colbase, 0, tid);
    CP_COMMIT();

    const uint32_t Q_s = sm;
    const int a_row = w * 16 + (l & 7) + ((l >> 3) & 1) * 8;
    const int a_kb  = ((l >> 4) & 1) * 8;
    const int b_row = ((l >> 4) & 1) * 8 + (l & 7);
    const int b_kb  = ((l >> 3) & 1) * 8;
    const int v_row = (l & 15);
    const int v_cb  = ((l >> 4) & 1) * 8;

    float m0 = -1e30f, m1 = -1e30f, l0 = 0.f, l1 = 0.f;
    float ao[8][4] = {};
    const float SC2 = 0.18033688011112042f;  // (1/8) * log2(e)

    for (int t = 0; t < FL_TILES; t++) {
        const uint32_t st = sm + 16384 + (uint32_t)(t & 1) * FL_STAGE;
        if (t + 1 < FL_TILES) {
            fl_load_kv(sm + 16384 + (uint32_t)((t + 1) & 1) * FL_STAGE,
                       qkv, rowbase, colbase, (t + 1) * 64, tid);
            CP_COMMIT();
            CP_WAIT1();
        } else {
            CP_WAIT0();
        }
        __syncthreads();

        // S = Q K^T
        float sa[8][4] = {};
        fl_qk_pass(sa, Q_s, st, a_row, a_kb, b_row, b_kb);

        // online softmax
        float tm0 = -1e30f, tm1 = -1e30f;
        #pragma unroll
        for (int nt = 0; nt < 8; nt++) {
            tm0 = fmaxf(tm0, fmaxf(sa[nt][0], sa[nt][1]));
            tm1 = fmaxf(tm1, fmaxf(sa[nt][2], sa[nt][3]));
        }
        tm0 = fmaxf(tm0, __shfl_xor_sync(0xffffffffu, tm0, 1));
        tm0 = fmaxf(tm0, __shfl_xor_sync(0xffffffffu, tm0, 2));
        tm1 = fmaxf(tm1, __shfl_xor_sync(0xffffffffu, tm1, 1));
        tm1 = fmaxf(tm1, __shfl_xor_sync(0xffffffffu, tm1, 2));
        const float nm0 = fmaxf(m0, tm0), nm1 = fmaxf(m1, tm1);
        const float al0 = exp2f((m0 - nm0) * SC2);
        const float al1 = exp2f((m1 - nm1) * SC2);
        m0 = nm0; m1 = nm1;

        float rs0 = 0.f, rs1 = 0.f;
        #pragma unroll
        for (int nt = 0; nt < 8; nt++) {
            sa[nt][0] = exp2f((sa[nt][0] - m0) * SC2);
            sa[nt][1] = exp2f((sa[nt][1] - m0) * SC2);
            sa[nt][2] = exp2f((sa[nt][2] - m1) * SC2);
            sa[nt][3] = exp2f((sa[nt][3] - m1) * SC2);
            rs0 += sa[nt][0] + sa[nt][1];
            rs1 += sa[nt][2] + sa[nt][3];
        }
        rs0 += __shfl_xor_sync(0xffffffffu, rs0, 1);
        rs0 += __shfl_xor_sync(0xffffffffu, rs0, 2);
        rs1 += __shfl_xor_sync(0xffffffffu, rs1, 1);
        rs1 += __shfl_xor_sync(0xffffffffu, rs1, 2);
        l0 = l0 * al0 + rs0;
        l1 = l1 * al1 + rs1;

        #pragma unroll
        for (int nd = 0; nd < 8; nd++) {
            ao[nd][0] *= al0; ao[nd][1] *= al0;
            ao[nd][2] *= al1; ao[nd][3] *= al1;
        }

        // P -> fp16 A-fragments
        uint32_t ph[4][4];
        #pragma unroll
        for (int ks = 0; ks < 4; ks++) {
            #pragma unroll
            for (int hf = 0; hf < 2; hf++) {
                const float* s2 = sa[2 * ks + hf];
                ph[ks][0 + 2 * hf] = pack_h2(__float2half(s2[0]), __float2half(s2[1]));
                ph[ks][1 + 2 * hf] = pack_h2(__float2half(s2[2]), __float2half(s2[3]));
            }
        }

        // O += P V
        fl_pv_pass(ao, ph, st + 8192, v_row, v_cb);

        __syncthreads();
    }

    // write O (fp16, stride D_MODEL)
    const float inv0 = 1.0f / l0, inv1 = 1.0f / l1;
    const int g = l >> 2, t2 = (l & 3) * 2;
    const size_t row0 = rowbase + q0 + w * 16 + g;
    #pragma unroll
    for (int nd = 0; nd < 8; nd++) {
        const int col = colbase + nd * 8 + t2;
        store_h2(outh, row0 * D_MODEL + col, ao[nd][0] * inv0, ao[nd][1] * inv0);
        store_h2(outh, (row0 + 8) * D_MODEL + col, ao[nd][2] * inv1, ao[nd][3] * inv1);
    }
}

// --------------------------- conversion kernels ------------------------------
// W [K,N] fp32 -> T [N,K] fp16
__global__ __launch_bounds__(256) void conv_wT(
    const float* __restrict__ W, __half* __restrict__ T, int K, int N)
{
    __shared__ float t[32][33];
    const int n0 = blockIdx.x * 32, k0 = blockIdx.y * 32;
    const int tx = threadIdx.x & 31, ty8 = threadIdx.x >> 5;
    #pragma unroll
    for (int j = 0; j < 4; j++) {
        int ky = ty8 + j * 8;
        t[ky][tx] = W[(size_t)(k0 + ky) * N + n0 + tx];
    }
    __syncthreads();
    #pragma unroll
    for (int j = 0; j < 4; j++) {
        int ny = ty8 + j * 8;
        T[(size_t)(n0 + ny) * K + k0 + tx] = __float2half(t[tx][ny]);
    }
}

__global__ __launch_bounds__(256) void concat_bias(
    const float* __restrict__ a, const float* __restrict__ b,
    const float* __restrict__ c, float* __restrict__ o)
{
    int i = blockIdx.x * 256 + threadIdx.x;
    if (i >= NQKV) return;
    o[i] = (i < 1024) ? a[i] : (i < 2048) ? b[i - 1024] : c[i - 2048];
}

// ---------------------------- LayerNorm -> fp16 ------------------------------
__global__ __launch_bounds__(256) void ln_kernel(
    const float* __restrict__ x, const float* __restrict__ scale,
    const float* __restrict__ bias, __half* __restrict__ y)
{
    const int row = blockIdx.x;
    const int tid = threadIdx.x;
    const float* xr = x + (size_t)row * D_MODEL;

    float4 v = *(const float4*)(xr + tid * 4);
    float s  = v.x + v.y + v.z + v.w;
    float sq = v.x*v.x + v.y*v.y + v.z*v.z + v.w*v.w;

    #pragma unroll
    for (int o = 16; o > 0; o >>= 1) {
        s  += __shfl_xor_sync(0xffffffffu, s,  o);
        sq += __shfl_xor_sync(0xffffffffu, sq, o);
    }
    __shared__ float rs[8], rq[8];
    int w = tid >> 5, l = tid & 31;
    if (l == 0) { rs[w] = s; rq[w] = sq; }
    __syncthreads();
    float ts = 0.f, tq = 0.f;
    #pragma unroll
    for (int i = 0; i < 8; i++) { ts += rs[i]; tq += rq[i]; }
    float mean = ts * (1.0f / D_MODEL);
    float var  = tq * (1.0f / D_MODEL) - mean * mean;
    float inv  = rsqrtf(var + 1e-6f);

    int c = tid * 4;
    float o0 = (v.x - mean) * inv * scale[c+0] + bias[c+0];
    float o1 = (v.y - mean) * inv * scale[c+1] + bias[c+1];
    float o2 = (v.z - mean) * inv * scale[c+2] + bias[c+2];
    float o3 = (v.w - mean) * inv * scale[c+3] + bias[c+3];
    size_t idx = (size_t)row * D_MODEL + c;
    store_h2(y, idx, o0, o1);
    store_h2(y, idx + 2, o2, o3);
}

// --------------------------------- launch -----------------------------------
extern "C" void kernel_launch(void* const* d_in, const int* in_sizes, int n_in,
                              void* d_out, int out_size)
{
    const float* x   = (const float*)d_in[0];
    const float* Wq  = (const float*)d_in[1];
    const float* bq  = (const float*)d_in[2];
    const float* Wk  = (const float*)d_in[3];
    const float* bk  = (const float*)d_in[4];
    const float* Wv  = (const float*)d_in[5];
    const float* bv  = (const float*)d_in[6];
    const float* Wo  = (const float*)d_in[7];
    const float* bo  = (const float*)d_in[8];
    const float* W1  = (const float*)d_in[9];
    const float* b1  = (const float*)d_in[10];
    const float* W2  = (const float*)d_in[11];
    const float* b2  = (const float*)d_in[12];
    const float* ln1s = (const float*)d_in[13];
    const float* ln1b = (const float*)d_in[14];
    const float* ln2s = (const float*)d_in[15];
    const float* ln2b = (const float*)d_in[16];
    float* out = (float*)d_out;

    float *x1, *bqkv;
    cudaGetSymbolAddress((void**)&x1,   g_x1);
    cudaGetSymbolAddress((void**)&bqkv, g_bqkv);

    __half *wqkv,*wo,*w1,*w2,*xs,*ff,*qkv;
    cudaGetSymbolAddress((void**)&wqkv, g_wqkvT);
    cudaGetSymbolAddress((void**)&wo,   g_woT);
    cudaGetSymbolAddress((void**)&w1,   g_w1T);
    cudaGetSymbolAddress((void**)&w2,   g_w2T);
    cudaGetSymbolAddress((void**)&xs,   g_xs);
    cudaGetSymbolAddress((void**)&ff,   g_ff);
    cudaGetSymbolAddress((void**)&qkv,  g_qkv);

    cudaFuncSetAttribute(mma_gemm<1>, cudaFuncAttributeMaxDynamicSharedMemorySize, SMEM_BYTES);
    cudaFuncSetAttribute(mma_gemm<2>, cudaFuncAttributeMaxDynamicSharedMemorySize, SMEM_BYTES);
    cudaFuncSetAttribute(mma_gemm<3>, cudaFuncAttributeMaxDynamicSharedMemorySize, SMEM_BYTES);
    cudaFuncSetAttribute(flash_kernel, cudaFuncAttributeMaxDynamicSharedMemorySize, FL_SMEM);

    // weight conversions (transpose, fp16); QKV concatenated [3072,1024]
    conv_wT<<<dim3(D_MODEL/32, D_MODEL/32), 256>>>(Wq, wqkv,                  D_MODEL, D_MODEL);
    conv_wT<<<dim3(D_MODEL/32, D_MODEL/32), 256>>>(Wk, wqkv + 1024 * D_MODEL, D_MODEL, D_MODEL);
    conv_wT<<<dim3(D_MODEL/32, D_MODEL/32), 256>>>(Wv, wqkv + 2048 * D_MODEL, D_MODEL, D_MODEL);
    conv_wT<<<dim3(D_MODEL/32, D_MODEL/32), 256>>>(Wo, wo, D_MODEL, D_MODEL);
    conv_wT<<<dim3(D_FF/32,    D_MODEL/32), 256>>>(W1, w1, D_MODEL, D_FF);
    conv_wT<<<dim3(D_MODEL/32, D_FF/32),    256>>>(W2, w2, D_FF, D_MODEL);
    concat_bias<<<NQKV / 256, 256>>>(bq, bk, bv, bqkv);

    // 1) LN1 -> fp16
    ln_kernel<<<NROWS, 256>>>(x, ln1s, ln1b, xs);

    // 2) fused QKV projection -> qkv [row][3072]
    mma_gemm<3><<<dim3(NQKV/128, NROWS/128), 256, SMEM_BYTES>>>(
        xs, wqkv, bqkv, nullptr, nullptr, qkv, NROWS, NQKV, D_MODEL);

    // 3) flash attention -> xs
    flash_kernel<<<dim3(SEQ/128, NBH), 256, FL_SMEM>>>(qkv, xs);

    // 4) x1 = x + attn @ Wo + bo (fp32)
    mma_gemm<2><<<dim3(D_MODEL/128, NROWS/128), 256, SMEM_BYTES>>>(
        xs, wo, bo, x, x1, nullptr, NROWS, D_MODEL, D_MODEL);

    // 5) LN2 -> fp16
    ln_kernel<<<NROWS, 256>>>(x1, ln2s, ln2b, xs);

    // 6) ff = relu(h @ W1 + b1) -> fp16
    mma_gemm<1><<<dim3(D_FF/128, NROWS/128), 256, SMEM_BYTES>>>(
        xs, w1, b1, nullptr, nullptr, ff, NROWS, D_FF, D_MODEL);

    // 7) out = x1 + ff @ W2 + b2 (fp32)
    mma_gemm<2><<<dim3(D_MODEL/128, NROWS/128), 256, SMEM_BYTES>>>(
        ff, w2, b2, x1, out, nullptr, NROWS, D_MODEL, D_FF);
}

// round 12
// speedup vs baseline: 6.9341x; 1.0452x over previous
#include <cuda_runtime.h>
#include <cuda_fp16.h>
#include <cstdint>
#include <math.h>

// ---------------------------------------------------------------------------
// TransformerBlock: single-pass fp16 HMMA GEMMs (wide tiles) + flash attention.
// B=2, S=2048, D=1024, H=16, Dh=64, FF=4096.
// ---------------------------------------------------------------------------

#define D_MODEL 1024
#define SEQ     2048
#define BATCH   2
#define NHEADS  16
#define HEADDIM 64
#define D_FF    4096
#define NROWS   (BATCH * SEQ)          // 4096
#define NBH     (BATCH * NHEADS)       // 32
#define NQKV    3072
#define QKVLD   3072

// ------------------------- scratch (no allocations) ------------------------
__device__ float g_x1[NROWS * D_MODEL];

// activations fp16
__device__ __half g_xs [NROWS * D_MODEL];
__device__ __half g_ff [(size_t)NROWS * D_FF];
__device__ __half g_qkv[(size_t)NROWS * NQKV];

// weights fp16 (transposed [N,K])
__device__ __half g_wqkvT[NQKV * D_MODEL];
__device__ __half g_woT[D_MODEL * D_MODEL];
__device__ __half g_w1T[D_FF * D_MODEL];
__device__ __half g_w2T[D_MODEL * D_FF];
__device__ float g_bqkv[NQKV];

// ------------------------------- PTX helpers --------------------------------
__device__ __forceinline__ uint32_t smem_u32(const void* p) {
    uint32_t a;
    asm("{ .reg .u64 t; cvta.to.shared.u64 t, %1; cvt.u32.u64 %0, t; }"
        : "=r"(a) : "l"(p));
    return a;
}

#define SMEM_SWZ128(off) ((off) ^ (((off) >> 3) & 0x70))

__device__ __forceinline__ void cp_async16(uint32_t dst, const void* src) {
    asm volatile("cp.async.cg.shared.global [%0], [%1], 16;"
                 :: "r"(dst), "l"(__cvta_generic_to_global(src)) : "memory");
}
#define CP_COMMIT() asm volatile("cp.async.commit_group;" ::: "memory")
#define CP_WAIT3()  asm volatile("cp.async.wait_group 3;" ::: "memory")
#define CP_WAIT1()  asm volatile("cp.async.wait_group 1;" ::: "memory")
#define CP_WAIT0()  asm volatile("cp.async.wait_group 0;" ::: "memory")

__device__ __forceinline__ void ldmatrix_x4(uint32_t* r, uint32_t addr) {
    asm volatile("ldmatrix.sync.aligned.m8n8.x4.shared.b16 {%0,%1,%2,%3}, [%4];"
                 : "=r"(r[0]), "=r"(r[1]), "=r"(r[2]), "=r"(r[3]) : "r"(addr));
}
__device__ __forceinline__ void ldmatrix_x4_t(uint32_t* r, uint32_t addr) {
    asm volatile("ldmatrix.sync.aligned.m8n8.x4.trans.shared.b16 {%0,%1,%2,%3}, [%4];"
                 : "=r"(r[0]), "=r"(r[1]), "=r"(r[2]), "=r"(r[3]) : "r"(addr));
}

__device__ __forceinline__ void mma_f16(float* c, const uint32_t* a, const uint32_t* b) {
    asm volatile(
        "mma.sync.aligned.m16n8k16.row.col.f32.f16.f16.f32 "
        "{%0,%1,%2,%3}, {%4,%5,%6,%7}, {%8,%9}, {%0,%1,%2,%3};"
        : "+f"(c[0]), "+f"(c[1]), "+f"(c[2]), "+f"(c[3])
        : "r"(a[0]), "r"(a[1]), "r"(a[2]), "r"(a[3]), "r"(b[0]), "r"(b[1]));
}

__device__ __forceinline__ uint32_t pack_h2(__half a, __half b) {
    return (uint32_t)__half_as_ushort(a) | ((uint32_t)__half_as_ushort(b) << 16);
}
__device__ __forceinline__ void store_h2(__half* dst, size_t idx, float a, float b) {
    *(uint32_t*)(dst + idx) = pack_h2(__float2half(a), __float2half(b));
}

// ----------------------------- HMMA GEMM ------------------------------------
// C[M,N] = A[M,K] @ B^T[N,K], fp16 single pass. Tile 128 x BN (BN = 128 | 256).
// EPI: 1=bias+relu->fp16  2=bias+res->fp32  3=bias->fp16
#define STAGES 4
#define KC     64
#define A_BYTES 16384                  // 128 rows x 128B

template<int BN>
__device__ __forceinline__ void load_stage(
    uint32_t st_base,
    const __half* __restrict__ A, const __half* __restrict__ B,
    int bm, int bn, int k0, int K, int tid)
{
    constexpr int TOT = (128 + BN) * 8;       // 16B units per stage
    #pragma unroll
    for (int i = 0; i < TOT / 256; i++) {
        int id = tid + i * 256;
        if (id < 1024) {
            int r = id >> 3, c = id & 7;
            cp_async16(st_base + SMEM_SWZ128((uint32_t)(r * 128 + c * 16)),
                       A + (size_t)(bm + r) * K + k0 + c * 8);
        } else {
            int j = id - 1024;
            int r = j >> 3, c = j & 7;
            cp_async16(st_base + A_BYTES + SMEM_SWZ128((uint32_t)(r * 128 + c * 16)),
                       B + (size_t)(bn + r) * K + k0 + c * 8);
        }
    }
}

template<int NTW>   // n8-tiles per warp (8 for BN=128, 16 for BN=256)
__device__ __forceinline__ void mma_pass(
    float acc[2][NTW][4], uint32_t Abase, uint32_t Bbase, int wm, int wn, int l)
{
    const int a_row  = wm * 32 + (l & 7) + ((l >> 3) & 1) * 8;
    const int a_kblk = ((l >> 4) & 1) * 8;
    const int b_row  = wn * (NTW * 8) + ((l >> 4) & 1) * 8 + (l & 7);
    const int b_kblk = ((l >> 3) & 1) * 8;

    #pragma unroll
    for (int ks = 0; ks < 4; ks++) {
        const int k0 = ks * 16;
        uint32_t a[2][4];
        #pragma unroll
        for (int mt = 0; mt < 2; mt++) {
            uint32_t off = SMEM_SWZ128((uint32_t)((a_row + mt * 16) * 128 + (k0 + a_kblk) * 2));
            ldmatrix_x4(a[mt], Abase + off);
        }
        #pragma unroll
        for (int np = 0; np < NTW / 2; np++) {
            uint32_t r[4];
            uint32_t off = SMEM_SWZ128((uint32_t)((b_row + np * 16) * 128 + (k0 + b_kblk) * 2));
            ldmatrix_x4(r, Bbase + off);
            #pragma unroll
            for (int mt = 0; mt < 2; mt++) {
                mma_f16(acc[mt][np * 2 + 0], a[mt], &r[0]);
                mma_f16(acc[mt][np * 2 + 1], a[mt], &r[2]);
            }
        }
    }
}

template<int EPI, int BN>
__global__ __launch_bounds__(256, 1) void mma_gemm(
    const __half* __restrict__ A, const __half* __restrict__ B,
    const float* __restrict__ bias, const float* __restrict__ res,
    float* __restrict__ C, __half* __restrict__ Ch,
    int M, int N, int K)
{
    extern __shared__ char dsm[];
    const uint32_t smbase = (smem_u32(dsm) + 1023u) & ~1023u;
    constexpr int NTW = BN / 16;
    constexpr int STAGE_BYTES = A_BYTES + BN * 128;

    const int tid = threadIdx.x;
    const int wid = tid >> 5;
    const int l   = tid & 31;
    const int wm  = wid & 3;
    const int wn  = wid >> 2;
    const int bm  = blockIdx.y * 128;
    const int bn  = blockIdx.x * BN;
    const int NK  = K / KC;

    float acc[2][NTW][4] = {};

    #pragma unroll
    for (int kc = 0; kc < STAGES; kc++) {
        if (kc < NK) load_stage<BN>(smbase + kc * STAGE_BYTES, A, B, bm, bn, kc * KC, K, tid);
        CP_COMMIT();
    }

    for (int kc = 0; kc < NK; kc++) {
        const int s = kc % STAGES;
        const uint32_t st = smbase + s * STAGE_BYTES;
        CP_WAIT3();
        __syncthreads();

        mma_pass<NTW>(acc, st, st + A_BYTES, wm, wn, l);

        __syncthreads();
        if (kc + STAGES < NK)
            load_stage<BN>(st, A, B, bm, bn, (kc + STAGES) * KC, K, tid);
        CP_COMMIT();
    }

    const int g = l >> 2;
    const int t2 = (l & 3) * 2;
    #pragma unroll
    for (int mt = 0; mt < 2; mt++) {
        const int r0 = bm + wm * 32 + mt * 16 + g;
        #pragma unroll
        for (int nt = 0; nt < NTW; nt++) {
            const int col = bn + wn * (NTW * 8) + nt * 8 + t2;
            float2 p0 = { acc[mt][nt][0] + bias[col], acc[mt][nt][1] + bias[col + 1] };
            float2 p1 = { acc[mt][nt][2] + bias[col], acc[mt][nt][3] + bias[col + 1] };
            if (EPI == 1) {
                p0.x = fmaxf(p0.x, 0.f); p0.y = fmaxf(p0.y, 0.f);
                p1.x = fmaxf(p1.x, 0.f); p1.y = fmaxf(p1.y, 0.f);
            }
            if (EPI == 2) {
                float2 q0 = *(const float2*)(res + (size_t)r0 * N + col);
                float2 q1 = *(const float2*)(res + (size_t)(r0 + 8) * N + col);
                p0.x += q0.x; p0.y += q0.y;
                p1.x += q1.x; p1.y += q1.y;
                *(float2*)(C + (size_t)r0 * N + col) = p0;
                *(float2*)(C + (size_t)(r0 + 8) * N + col) = p1;
            }
            if (EPI == 1 || EPI == 3) {
                store_h2(Ch, (size_t)r0 * N + col, p0.x, p0.y);
                store_h2(Ch, (size_t)(r0 + 8) * N + col, p1.x, p1.y);
            }
        }
    }
}

// --------------------------- flash attention ---------------------------------
// grid (SEQ/128, NBH); 256 threads; Bq=128, Bk=64. qkv packed [row][3072].
#define FL_STAGE 16384
#define FL_SMEM (16384 + 2 * FL_STAGE + 1024)
#define FL_TILES (SEQ / 64)

__device__ __forceinline__ void fl_load_kv(
    uint32_t st, const __half* qkv, size_t rowbase, int colbase, int kv0, int tid)
{
    #pragma unroll
    for (int i = 0; i < 4; i++) {
        int id  = tid + i * 256;          // 0..1023
        int mat = id >> 9;                // 0=K 1=V
        int r   = (id >> 3) & 63;
        int c   = id & 7;
        uint32_t off = SMEM_SWZ128((uint32_t)(r * 128 + c * 16));
        int colb = colbase + ((mat == 0) ? 1024 : 2048);
        cp_async16(st + mat * 8192 + off,
                   qkv + (rowbase + kv0 + r) * QKVLD + colb + c * 8);
    }
}

__device__ __forceinline__ void fl_qk_pass(
    float sa[8][4], uint32_t Qb, uint32_t Kb, int a_row, int a_kb, int b_row, int b_kb)
{
    #pragma unroll
    for (int ks = 0; ks < 4; ks++) {
        uint32_t a[4];
        ldmatrix_x4(a, Qb + SMEM_SWZ128((uint32_t)(a_row * 128 + (ks * 16 + a_kb) * 2)));
        #pragma unroll
        for (int nt2 = 0; nt2 < 4; nt2++) {
            uint32_t r[4];
            ldmatrix_x4(r, Kb + SMEM_SWZ128((uint32_t)((nt2 * 16 + b_row) * 128 + (ks * 16 + b_kb) * 2)));
            mma_f16(sa[nt2 * 2 + 0], a, &r[0]);
            mma_f16(sa[nt2 * 2 + 1], a, &r[2]);
        }
    }
}

__device__ __forceinline__ void fl_pv_pass(
    float ao[8][4], const uint32_t pf[4][4], uint32_t Vb, int v_row, int v_cb)
{
    #pragma unroll
    for (int ks = 0; ks < 4; ks++) {
        #pragma unroll
        for (int nd2 = 0; nd2 < 4; nd2++) {
            uint32_t r[4];
            ldmatrix_x4_t(r, Vb + SMEM_SWZ128((uint32_t)((ks * 16 + v_row) * 128 + (nd2 * 16 + v_cb) * 2)));
            mma_f16(ao[nd2 * 2 + 0], pf[ks], &r[0]);
            mma_f16(ao[nd2 * 2 + 1], pf[ks], &r[2]);
        }
    }
}

__global__ __launch_bounds__(256, 1) void flash_kernel(
    const __half* __restrict__ qkv, __half* __restrict__ outh)
{
    extern __shared__ char dsm[];
    const uint32_t sm = (smem_u32(dsm) + 1023u) & ~1023u;

    const int tid = threadIdx.x;
    const int w = tid >> 5, l = tid & 31;
    const int qt = blockIdx.x, bh = blockIdx.y;
    const int b = bh >> 4, h = bh & 15;
    const size_t rowbase = (size_t)b * SEQ;
    const int colbase = h * HEADDIM;
    const int q0 = qt * 128;

    // load Q (128 rows x 128B)
    #pragma unroll
    for (int i = 0; i < 4; i++) {
        int id  = tid + i * 256;
        int r   = (id >> 3) & 127;
        int c   = id & 7;
        uint32_t off = SMEM_SWZ128((uint32_t)(r * 128 + c * 16));
        cp_async16(sm + off, qkv + (rowbase + q0 + r) * QKVLD + colbase + c * 8);
    }
    CP_COMMIT();
    fl_load_kv(sm + 16384, qkv, rowbase, colbase, 0, tid);
    CP_COMMIT();

    const uint32_t Q_s = sm;
    const int a_row = w * 16 + (l & 7) + ((l >> 3) & 1) * 8;
    const int a_kb  = ((l >> 4) & 1) * 8;
    const int b_row = ((l >> 4) & 1) * 8 + (l & 7);
    const int b_kb  = ((l >> 3) & 1) * 8;
    const int v_row = (l & 15);
    const int v_cb  = ((l >> 4) & 1) * 8;

    float m0 = -1e30f, m1 = -1e30f, l0 = 0.f, l1 = 0.f;
    float ao[8][4] = {};
    const float SC2 = 0.18033688011112042f;  // (1/8) * log2(e)

    for (int t = 0; t < FL_TILES; t++) {
        const uint32_t st = sm + 16384 + (uint32_t)(t & 1) * FL_STAGE;
        if (t + 1 < FL_TILES) {
            fl_load_kv(sm + 16384 + (uint32_t)((t + 1) & 1) * FL_STAGE,
                       qkv, rowbase, colbase, (t + 1) * 64, tid);
            CP_COMMIT();
            CP_WAIT1();
        } else {
            CP_WAIT0();
        }
        __syncthreads();

        // S = Q K^T
        float sa[8][4] = {};
        fl_qk_pass(sa, Q_s, st, a_row, a_kb, b_row, b_kb);

        // online softmax
        float tm0 = -1e30f, tm1 = -1e30f;
        #pragma unroll
        for (int nt = 0; nt < 8; nt++) {
            tm0 = fmaxf(tm0, fmaxf(sa[nt][0], sa[nt][1]));
            tm1 = fmaxf(tm1, fmaxf(sa[nt][2], sa[nt][3]));
        }
        tm0 = fmaxf(tm0, __shfl_xor_sync(0xffffffffu, tm0, 1));
        tm0 = fmaxf(tm0, __shfl_xor_sync(0xffffffffu, tm0, 2));
        tm1 = fmaxf(tm1, __shfl_xor_sync(0xffffffffu, tm1, 1));
        tm1 = fmaxf(tm1, __shfl_xor_sync(0xffffffffu, tm1, 2));
        const float nm0 = fmaxf(m0, tm0), nm1 = fmaxf(m1, tm1);
        const float al0 = exp2f((m0 - nm0) * SC2);
        const float al1 = exp2f((m1 - nm1) * SC2);
        m0 = nm0; m1 = nm1;

        float rs0 = 0.f, rs1 = 0.f;
        #pragma unroll
        for (int nt = 0; nt < 8; nt++) {
            sa[nt][0] = exp2f((sa[nt][0] - m0) * SC2);
            sa[nt][1] = exp2f((sa[nt][1] - m0) * SC2);
            sa[nt][2] = exp2f((sa[nt][2] - m1) * SC2);
            sa[nt][3] = exp2f((sa[nt][3] - m1) * SC2);
            rs0 += sa[nt][0] + sa[nt][1];
            rs1 += sa[nt][2] + sa[nt][3];
        }
        rs0 += __shfl_xor_sync(0xffffffffu, rs0, 1);
        rs0 += __shfl_xor_sync(0xffffffffu, rs0, 2);
        rs1 += __shfl_xor_sync(0xffffffffu, rs1, 1);
        rs1 += __shfl_xor_sync(0xffffffffu, rs1, 2);
        l0 = l0 * al0 + rs0;
        l1 = l1 * al1 + rs1;

        #pragma unroll
        for (int nd = 0; nd < 8; nd++) {
            ao[nd][0] *= al0; ao[nd][1] *= al0;
            ao[nd][2] *= al1; ao[nd][3] *= al1;
        }

        // P -> fp16 A-fragments
        uint32_t ph[4][4];
        #pragma unroll
        for (int ks = 0; ks < 4; ks++) {
            #pragma unroll
            for (int hf = 0; hf < 2; hf++) {
                const float* s2 = sa[2 * ks + hf];
                ph[ks][0 + 2 * hf] = pack_h2(__float2half(s2[0]), __float2half(s2[1]));
                ph[ks][1 + 2 * hf] = pack_h2(__float2half(s2[2]), __float2half(s2[3]));
            }
        }

        // O += P V
        fl_pv_pass(ao, ph, st + 8192, v_row, v_cb);

        __syncthreads();
    }

    // write O (fp16, stride D_MODEL)
    const float inv0 = 1.0f / l0, inv1 = 1.0f / l1;
    const int g = l >> 2, t2 = (l & 3) * 2;
    const size_t row0 = rowbase + q0 + w * 16 + g;
    #pragma unroll
    for (int nd = 0; nd < 8; nd++) {
        const int col = colbase + nd * 8 + t2;
        store_h2(outh, row0 * D_MODEL + col, ao[nd][0] * inv0, ao[nd][1] * inv0);
        store_h2(outh, (row0 + 8) * D_MODEL + col, ao[nd][2] * inv1, ao[nd][3] * inv1);
    }
}

// ---------------------- unified weight conversion ----------------------------
// All transposes (W [K,N] fp32 -> T [N,K] fp16) + bias concat in ONE launch.
// Tile map: [0,3072)=Wq/Wk/Wv  [3072,4096)=Wo  [4096,8192)=W1  [8192,12288)=W2
// blocks [12288,12300) handle the 3072-elem bias concat.
__global__ __launch_bounds__(256) void conv_all(
    const float* __restrict__ Wq, const float* __restrict__ Wk,
    const float* __restrict__ Wv, const float* __restrict__ Wo,
    const float* __restrict__ W1, const float* __restrict__ W2,
    const float* __restrict__ bq, const float* __restrict__ bk,
    const float* __restrict__ bv,
    __half* __restrict__ wqkv, __half* __restrict__ wo,
    __half* __restrict__ w1, __half* __restrict__ w2,
    float* __restrict__ bqkv)
{
    const int t = blockIdx.x;
    if (t >= 12288) {
        int i = (t - 12288) * 256 + threadIdx.x;
        if (i < NQKV)
            bqkv[i] = (i < 1024) ? bq[i] : (i < 2048) ? bk[i - 1024] : bv[i - 2048];
        return;
    }

    const float* W; __half* T; int K, N, base;
    if (t < 3072) {
        int wsel = t >> 10;
        W = (wsel == 0) ? Wq : (wsel == 1) ? Wk : Wv;
        T = wqkv + (size_t)wsel * 1024 * 1024;
        K = 1024; N = 1024; base = t & 1023;
    } else if (t < 4096) { W = Wo; T = wo; K = 1024; N = 1024; base = t - 3072; }
    else if (t < 8192)   { W = W1; T = w1; K = 1024; N = 4096; base = t - 4096; }
    else                 { W = W2; T = w2; K = 4096; N = 1024; base = t - 8192; }

    const int ntiles = N >> 5;
    const int kt = base / ntiles, nt = base - kt * ntiles;
    const int n0 = nt * 32, k0 = kt * 32;

    __shared__ float tb[32][33];
    const int tx = threadIdx.x & 31, ty8 = threadIdx.x >> 5;
    #pragma unroll
    for (int j = 0; j < 4; j++) {
        int ky = ty8 + j * 8;
        tb[ky][tx] = W[(size_t)(k0 + ky) * N + n0 + tx];
    }
    __syncthreads();
    #pragma unroll
    for (int j = 0; j < 4; j++) {
        int ny = ty8 + j * 8;
        T[(size_t)(n0 + ny) * K + k0 + tx] = __float2half(tb[tx][ny]);
    }
}

// ---------------------------- LayerNorm -> fp16 ------------------------------
__global__ __launch_bounds__(256) void ln_kernel(
    const float* __restrict__ x, const float* __restrict__ scale,
    const float* __restrict__ bias, __half* __restrict__ y)
{
    const int row = blockIdx.x;
    const int tid = threadIdx.x;
    const float* xr = x + (size_t)row * D_MODEL;

    float4 v = *(const float4*)(xr + tid * 4);
    float s  = v.x + v.y + v.z + v.w;
    float sq = v.x*v.x + v.y*v.y + v.z*v.z + v.w*v.w;

    #pragma unroll
    for (int o = 16; o > 0; o >>= 1) {
        s  += __shfl_xor_sync(0xffffffffu, s,  o);
        sq += __shfl_xor_sync(0xffffffffu, sq, o);
    }
    __shared__ float rs[8], rq[8];
    int w = tid >> 5, l = tid & 31;
    if (l == 0) { rs[w] = s; rq[w] = sq; }
    __syncthreads();
    float ts = 0.f, tq = 0.f;
    #pragma unroll
    for (int i = 0; i < 8; i++) { ts += rs[i]; tq += rq[i]; }
    float mean = ts * (1.0f / D_MODEL);
    float var  = tq * (1.0f / D_MODEL) - mean * mean;
    float inv  = rsqrtf(var + 1e-6f);

    int c = tid * 4;
    float o0 = (v.x - mean) * inv * scale[c+0] + bias[c+0];
    float o1 = (v.y - mean) * inv * scale[c+1] + bias[c+1];
    float o2 = (v.z - mean) * inv * scale[c+2] + bias[c+2];
    float o3 = (v.w - mean) * inv * scale[c+3] + bias[c+3];
    size_t idx = (size_t)row * D_MODEL + c;
    store_h2(y, idx, o0, o1);
    store_h2(y, idx + 2, o2, o3);
}

// --------------------------------- launch -----------------------------------
extern "C" void kernel_launch(void* const* d_in, const int* in_sizes, int n_in,
                              void* d_out, int out_size)
{
    const float* x   = (const float*)d_in[0];
    const float* Wq  = (const float*)d_in[1];
    const float* bq  = (const float*)d_in[2];
    const float* Wk  = (const float*)d_in[3];
    const float* bk  = (const float*)d_in[4];
    const float* Wv  = (const float*)d_in[5];
    const float* bv  = (const float*)d_in[6];
    const float* Wo  = (const float*)d_in[7];
    const float* bo  = (const float*)d_in[8];
    const float* W1  = (const float*)d_in[9];
    const float* b1  = (const float*)d_in[10];
    const float* W2  = (const float*)d_in[11];
    const float* b2  = (const float*)d_in[12];
    const float* ln1s = (const float*)d_in[13];
    const float* ln1b = (const float*)d_in[14];
    const float* ln2s = (const float*)d_in[15];
    const float* ln2b = (const float*)d_in[16];
    float* out = (float*)d_out;

    float *x1, *bqkv;
    cudaGetSymbolAddress((void**)&x1,   g_x1);
    cudaGetSymbolAddress((void**)&bqkv, g_bqkv);

    __half *wqkv,*wo,*w1,*w2,*xs,*ff,*qkv;
    cudaGetSymbolAddress((void**)&wqkv, g_wqkvT);
    cudaGetSymbolAddress((void**)&wo,   g_woT);
    cudaGetSymbolAddress((void**)&w1,   g_w1T);
    cudaGetSymbolAddress((void**)&w2,   g_w2T);
    cudaGetSymbolAddress((void**)&xs,   g_xs);
    cudaGetSymbolAddress((void**)&ff,   g_ff);
    cudaGetSymbolAddress((void**)&qkv,  g_qkv);

    constexpr int SMEM128 = STAGES * (A_BYTES + 128 * 128) + 1024;   // 132 KB
    constexpr int SMEM256 = STAGES * (A_BYTES + 256 * 128) + 1024;   // 197.5 KB
    cudaFuncSetAttribute(mma_gemm<1,256>, cudaFuncAttributeMaxDynamicSharedMemorySize, SMEM256);
    cudaFuncSetAttribute(mma_gemm<3,256>, cudaFuncAttributeMaxDynamicSharedMemorySize, SMEM256);
    cudaFuncSetAttribute(mma_gemm<2,128>, cudaFuncAttributeMaxDynamicSharedMemorySize, SMEM128);
    cudaFuncSetAttribute(flash_kernel, cudaFuncAttributeMaxDynamicSharedMemorySize, FL_SMEM);

    // all weight conversions + bias concat: ONE launch
    conv_all<<<12300, 256>>>(Wq, Wk, Wv, Wo, W1, W2, bq, bk, bv,
                             wqkv, wo, w1, w2, bqkv);

    // 1) LN1 -> fp16
    ln_kernel<<<NROWS, 256>>>(x, ln1s, ln1b, xs);

    // 2) fused QKV projection -> qkv [row][3072]  (wide tiles)
    mma_gemm<3,256><<<dim3(NQKV/256, NROWS/128), 256, SMEM256>>>(
        xs, wqkv, bqkv, nullptr, nullptr, qkv, NROWS, NQKV, D_MODEL);

    // 3) flash attention -> xs
    flash_kernel<<<dim3(SEQ/128, NBH), 256, FL_SMEM>>>(qkv, xs);

    // 4) x1 = x + attn @ Wo + bo (fp32)
    mma_gemm<2,128><<<dim3(D_MODEL/128, NROWS/128), 256, SMEM128>>>(
        xs, wo, bo, x, x1, nullptr, NROWS, D_MODEL, D_MODEL);

    // 5) LN2 -> fp16
    ln_kernel<<<NROWS, 256>>>(x1, ln2s, ln2b, xs);

    // 6) ff = relu(h @ W1 + b1) -> fp16  (wide tiles)
    mma_gemm<1,256><<<dim3(D_FF/256, NROWS/128), 256, SMEM256>>>(
        xs, w1, b1, nullptr, nullptr, ff, NROWS, D_FF, D_MODEL);

    // 7) out = x1 + ff @ W2 + b2 (fp32)
    mma_gemm<2,128><<<dim3(D_MODEL/128, NROWS/128), 256, SMEM128>>>(
        ff, w2, b2, x1, out, nullptr, NROWS, D_MODEL, D_FF);
}

// round 14
// speedup vs baseline: 7.9604x; 1.1480x over previous
#include <cuda_runtime.h>
#include <cuda_fp16.h>
#include <cstdint>
#include <math.h>

// ---------------------------------------------------------------------------
// TransformerBlock: single-pass fp16 HMMA GEMMs (2 CTA/SM) + flash (3 CTA/SM).
// B=2, S=2048, D=1024, H=16, Dh=64, FF=4096.
// ---------------------------------------------------------------------------

#define D_MODEL 1024
#define SEQ     2048
#define BATCH   2
#define NHEADS  16
#define HEADDIM 64
#define D_FF    4096
#define NROWS   (BATCH * SEQ)          // 4096
#define NBH     (BATCH * NHEADS)       // 32
#define NQKV    3072
#define QKVLD   3072

// ------------------------- scratch (no allocations) ------------------------
__device__ float g_x1[NROWS * D_MODEL];

// activations fp16
__device__ __half g_xs [NROWS * D_MODEL];
__device__ __half g_ff [(size_t)NROWS * D_FF];
__device__ __half g_qkv[(size_t)NROWS * NQKV];

// weights fp16 (transposed [N,K])
__device__ __half g_wqkvT[NQKV * D_MODEL];
__device__ __half g_woT[D_MODEL * D_MODEL];
__device__ __half g_w1T[D_FF * D_MODEL];
__device__ __half g_w2T[D_MODEL * D_FF];
__device__ float g_bqkv[NQKV];

// ------------------------------- PTX helpers --------------------------------
__device__ __forceinline__ uint32_t smem_u32(const void* p) {
    uint32_t a;
    asm("{ .reg .u64 t; cvta.to.shared.u64 t, %1; cvt.u32.u64 %0, t; }"
        : "=r"(a) : "l"(p));
    return a;
}

#define SMEM_SWZ128(off) ((off) ^ (((off) >> 3) & 0x70))

__device__ __forceinline__ void cp_async16(uint32_t dst, const void* src) {
    asm volatile("cp.async.cg.shared.global [%0], [%1], 16;"
                 :: "r"(dst), "l"(__cvta_generic_to_global(src)) : "memory");
}
#define CP_COMMIT() asm volatile("cp.async.commit_group;" ::: "memory")
#define CP_WAIT2()  asm volatile("cp.async.wait_group 2;" ::: "memory")
#define CP_WAIT1()  asm volatile("cp.async.wait_group 1;" ::: "memory")
#define CP_WAIT0()  asm volatile("cp.async.wait_group 0;" ::: "memory")

__device__ __forceinline__ void ldmatrix_x4(uint32_t* r, uint32_t addr) {
    asm volatile("ldmatrix.sync.aligned.m8n8.x4.shared.b16 {%0,%1,%2,%3}, [%4];"
                 : "=r"(r[0]), "=r"(r[1]), "=r"(r[2]), "=r"(r[3]) : "r"(addr));
}
__device__ __forceinline__ void ldmatrix_x4_t(uint32_t* r, uint32_t addr) {
    asm volatile("ldmatrix.sync.aligned.m8n8.x4.trans.shared.b16 {%0,%1,%2,%3}, [%4];"
                 : "=r"(r[0]), "=r"(r[1]), "=r"(r[2]), "=r"(r[3]) : "r"(addr));
}

__device__ __forceinline__ void mma_f16(float* c, const uint32_t* a, const uint32_t* b) {
    asm volatile(
        "mma.sync.aligned.m16n8k16.row.col.f32.f16.f16.f32 "
        "{%0,%1,%2,%3}, {%4,%5,%6,%7}, {%8,%9}, {%0,%1,%2,%3};"
        : "+f"(c[0]), "+f"(c[1]), "+f"(c[2]), "+f"(c[3])
        : "r"(a[0]), "r"(a[1]), "r"(a[2]), "r"(a[3]), "r"(b[0]), "r"(b[1]));
}

__device__ __forceinline__ uint32_t pack_h2(__half a, __half b) {
    return (uint32_t)__half_as_ushort(a) | ((uint32_t)__half_as_ushort(b) << 16);
}
__device__ __forceinline__ void store_h2(__half* dst, size_t idx, float a, float b) {
    *(uint32_t*)(dst + idx) = pack_h2(__float2half(a), __float2half(b));
}

// ----------------------------- HMMA GEMM ------------------------------------
// C[M,N] = A[M,K] @ B^T[N,K], fp16 single pass. Tile 128x128, 3 stages,
// 2 CTAs/SM. EPI: 1=bias+relu->fp16  2=bias+res->fp32  3=bias->fp16
#define STAGES 3
#define KC     64
#define A_BYTES 16384                  // 128 rows x 128B
#define STAGE_BYTES (2 * A_BYTES)      // A + B
#define SMEM_BYTES  (STAGES * STAGE_BYTES + 1024)   // 99328

__device__ __forceinline__ void load_stage(
    uint32_t st_base,
    const __half* __restrict__ A, const __half* __restrict__ B,
    int bm, int bn, int k0, int K, int tid)
{
    #pragma unroll
    for (int i = 0; i < 8; i++) {
        int id = tid + i * 256;           // 0..2047
        int mat = id >> 10;               // 0=A 1=B
        int r   = (id & 1023) >> 3;
        int c   = id & 7;
        uint32_t off = SMEM_SWZ128((uint32_t)(r * 128 + c * 16));
        const __half* src = (mat == 0) ? A + (size_t)(bm + r) * K + k0 + c * 8
                                       : B + (size_t)(bn + r) * K + k0 + c * 8;
        cp_async16(st_base + mat * A_BYTES + off, src);
    }
}

__device__ __forceinline__ void mma_pass(
    float acc[2][8][4], uint32_t Abase, uint32_t Bbase, int wm, int wn, int l)
{
    const int a_row  = wm * 32 + (l & 7) + ((l >> 3) & 1) * 8;
    const int a_kblk = ((l >> 4) & 1) * 8;
    const int b_row  = wn * 64 + ((l >> 4) & 1) * 8 + (l & 7);
    const int b_kblk = ((l >> 3) & 1) * 8;

    #pragma unroll
    for (int ks = 0; ks < 4; ks++) {
        const int k0 = ks * 16;
        uint32_t a[2][4];
        #pragma unroll
        for (int mt = 0; mt < 2; mt++) {
            uint32_t off = SMEM_SWZ128((uint32_t)((a_row + mt * 16) * 128 + (k0 + a_kblk) * 2));
            ldmatrix_x4(a[mt], Abase + off);
        }
        #pragma unroll
        for (int np = 0; np < 4; np++) {
            uint32_t r[4];
            uint32_t off = SMEM_SWZ128((uint32_t)((b_row + np * 16) * 128 + (k0 + b_kblk) * 2));
            ldmatrix_x4(r, Bbase + off);
            #pragma unroll
            for (int mt = 0; mt < 2; mt++) {
                mma_f16(acc[mt][np * 2 + 0], a[mt], &r[0]);
                mma_f16(acc[mt][np * 2 + 1], a[mt], &r[2]);
            }
        }
    }
}

template<int EPI>
__global__ __launch_bounds__(256, 2) void mma_gemm(
    const __half* __restrict__ A, const __half* __restrict__ B,
    const float* __restrict__ bias, const float* __restrict__ res,
    float* __restrict__ C, __half* __restrict__ Ch,
    int M, int N, int K)
{
    extern __shared__ char dsm[];
    const uint32_t smbase = (smem_u32(dsm) + 1023u) & ~1023u;

    const int tid = threadIdx.x;
    const int wid = tid >> 5;
    const int l   = tid & 31;
    const int wm  = wid & 3;
    const int wn  = wid >> 2;
    const int bm  = blockIdx.y * 128;
    const int bn  = blockIdx.x * 128;
    const int NK  = K / KC;

    float acc[2][8][4] = {};

    #pragma unroll
    for (int kc = 0; kc < STAGES; kc++) {
        load_stage(smbase + kc * STAGE_BYTES, A, B, bm, bn, kc * KC, K, tid);
        CP_COMMIT();
    }

    for (int kc = 0; kc < NK; kc++) {
        const int s = kc % STAGES;
        const uint32_t st = smbase + s * STAGE_BYTES;
        CP_WAIT2();
        __syncthreads();

        mma_pass(acc, st, st + A_BYTES, wm, wn, l);

        __syncthreads();
        if (kc + STAGES < NK)
            load_stage(st, A, B, bm, bn, (kc + STAGES) * KC, K, tid);
        CP_COMMIT();
    }

    const int g = l >> 2;
    const int t2 = (l & 3) * 2;
    #pragma unroll
    for (int mt = 0; mt < 2; mt++) {
        const int r0 = bm + wm * 32 + mt * 16 + g;
        #pragma unroll
        for (int nt = 0; nt < 8; nt++) {
            const int col = bn + wn * 64 + nt * 8 + t2;
            float2 p0 = { acc[mt][nt][0] + bias[col], acc[mt][nt][1] + bias[col + 1] };
            float2 p1 = { acc[mt][nt][2] + bias[col], acc[mt][nt][3] + bias[col + 1] };
            if (EPI == 1) {
                p0.x = fmaxf(p0.x, 0.f); p0.y = fmaxf(p0.y, 0.f);
                p1.x = fmaxf(p1.x, 0.f); p1.y = fmaxf(p1.y, 0.f);
            }
            if (EPI == 2) {
                float2 q0 = *(const float2*)(res + (size_t)r0 * N + col);
                float2 q1 = *(const float2*)(res + (size_t)(r0 + 8) * N + col);
                p0.x += q0.x; p0.y += q0.y;
                p1.x += q1.x; p1.y += q1.y;
                *(float2*)(C + (size_t)r0 * N + col) = p0;
                *(float2*)(C + (size_t)(r0 + 8) * N + col) = p1;
            }
            if (EPI == 1 || EPI == 3) {
                store_h2(Ch, (size_t)r0 * N + col, p0.x, p0.y);
                store_h2(Ch, (size_t)(r0 + 8) * N + col, p1.x, p1.y);
            }
        }
    }
}

// --------------------------- flash attention ---------------------------------
// grid (SEQ/64, NBH); 128 threads; Bq=64, Bk=64; 3 CTAs/SM.
// smem: Q @0 (8K); KV stages @8K: each 16K = K(8K) + V(8K).
#define FL_STAGE 16384
#define FL_SMEM (8192 + 2 * FL_STAGE + 1024)   // 41984
#define FL_TILES (SEQ / 64)

__device__ __forceinline__ void fl_load_kv(
    uint32_t st, const __half* qkv, size_t rowbase, int colbase, int kv0, int tid)
{
    #pragma unroll
    for (int i = 0; i < 8; i++) {
        int id  = tid + i * 128;          // 0..1023
        int mat = id >> 9;                // 0=K 1=V
        int r   = (id >> 3) & 63;
        int c   = id & 7;
        uint32_t off = SMEM_SWZ128((uint32_t)(r * 128 + c * 16));
        int colb = colbase + ((mat == 0) ? 1024 : 2048);
        cp_async16(st + mat * 8192 + off,
                   qkv + (rowbase + kv0 + r) * QKVLD + colb + c * 8);
    }
}

__device__ __forceinline__ void fl_qk_pass(
    float sa[8][4], uint32_t Qb, uint32_t Kb, int a_row, int a_kb, int b_row, int b_kb)
{
    #pragma unroll
    for (int ks = 0; ks < 4; ks++) {
        uint32_t a[4];
        ldmatrix_x4(a, Qb + SMEM_SWZ128((uint32_t)(a_row * 128 + (ks * 16 + a_kb) * 2)));
        #pragma unroll
        for (int nt2 = 0; nt2 < 4; nt2++) {
            uint32_t r[4];
            ldmatrix_x4(r, Kb + SMEM_SWZ128((uint32_t)((nt2 * 16 + b_row) * 128 + (ks * 16 + b_kb) * 2)));
            mma_f16(sa[nt2 * 2 + 0], a, &r[0]);
            mma_f16(sa[nt2 * 2 + 1], a, &r[2]);
        }
    }
}

__device__ __forceinline__ void fl_pv_pass(
    float ao[8][4], const uint32_t pf[4][4], uint32_t Vb, int v_row, int v_cb)
{
    #pragma unroll
    for (int ks = 0; ks < 4; ks++) {
        #pragma unroll
        for (int nd2 = 0; nd2 < 4; nd2++) {
            uint32_t r[4];
            ldmatrix_x4_t(r, Vb + SMEM_SWZ128((uint32_t)((ks * 16 + v_row) * 128 + (nd2 * 16 + v_cb) * 2)));
            mma_f16(ao[nd2 * 2 + 0], pf[ks], &r[0]);
            mma_f16(ao[nd2 * 2 + 1], pf[ks], &r[2]);
        }
    }
}

__global__ __launch_bounds__(128, 3) void flash_kernel(
    const __half* __restrict__ qkv, __half* __restrict__ outh)
{
    extern __shared__ char dsm[];
    const uint32_t sm = (smem_u32(dsm) + 1023u) & ~1023u;

    const int tid = threadIdx.x;
    const int w = tid >> 5, l = tid & 31;
    const int qt = blockIdx.x, bh = blockIdx.y;
    const int b = bh >> 4, h = bh & 15;
    const size_t rowbase = (size_t)b * SEQ;
    const int colbase = h * HEADDIM;
    const int q0 = qt * 64;

    // load Q (64 rows x 128B)
    #pragma unroll
    for (int i = 0; i < 4; i++) {
        int id  = tid + i * 128;
        int r   = (id >> 3) & 63;
        int c   = id & 7;
        uint32_t off = SMEM_SWZ128((uint32_t)(r * 128 + c * 16));
        cp_async16(sm + off, qkv + (rowbase + q0 + r) * QKVLD + colbase + c * 8);
    }
    CP_COMMIT();
    fl_load_kv(sm + 8192, qkv, rowbase, colbase, 0, tid);
    CP_COMMIT();

    const uint32_t Q_s = sm;
    const int a_row = w * 16 + (l & 7) + ((l >> 3) & 1) * 8;
    const int a_kb  = ((l >> 4) & 1) * 8;
    const int b_row = ((l >> 4) & 1) * 8 + (l & 7);
    const int b_kb  = ((l >> 3) & 1) * 8;
    const int v_row = (l & 15);
    const int v_cb  = ((l >> 4) & 1) * 8;

    float m0 = -1e30f, m1 = -1e30f, l0 = 0.f, l1 = 0.f;
    float ao[8][4] = {};
    const float SC2 = 0.18033688011112042f;  // (1/8) * log2(e)

    for (int t = 0; t < FL_TILES; t++) {
        const uint32_t st = sm + 8192 + (uint32_t)(t & 1) * FL_STAGE;
        if (t + 1 < FL_TILES) {
            fl_load_kv(sm + 8192 + (uint32_t)((t + 1) & 1) * FL_STAGE,
                       qkv, rowbase, colbase, (t + 1) * 64, tid);
            CP_COMMIT();
            CP_WAIT1();
        } else {
            CP_WAIT0();
        }
        __syncthreads();

        // S = Q K^T
        float sa[8][4] = {};
        fl_qk_pass(sa, Q_s, st, a_row, a_kb, b_row, b_kb);

        // online softmax
        float tm0 = -1e30f, tm1 = -1e30f;
        #pragma unroll
        for (int nt = 0; nt < 8; nt++) {
            tm0 = fmaxf(tm0, fmaxf(sa[nt][0], sa[nt][1]));
            tm1 = fmaxf(tm1, fmaxf(sa[nt][2], sa[nt][3]));
        }
        tm0 = fmaxf(tm0, __shfl_xor_sync(0xffffffffu, tm0, 1));
        tm0 = fmaxf(tm0, __shfl_xor_sync(0xffffffffu, tm0, 2));
        tm1 = fmaxf(tm1, __shfl_xor_sync(0xffffffffu, tm1, 1));
        tm1 = fmaxf(tm1, __shfl_xor_sync(0xffffffffu, tm1, 2));
        const float nm0 = fmaxf(m0, tm0), nm1 = fmaxf(m1, tm1);
        const float al0 = exp2f((m0 - nm0) * SC2);
        const float al1 = exp2f((m1 - nm1) * SC2);
        m0 = nm0; m1 = nm1;

        float rs0 = 0.f, rs1 = 0.f;
        #pragma unroll
        for (int nt = 0; nt < 8; nt++) {
            sa[nt][0] = exp2f((sa[nt][0] - m0) * SC2);
            sa[nt][1] = exp2f((sa[nt][1] - m0) * SC2);
            sa[nt][2] = exp2f((sa[nt][2] - m1) * SC2);
            sa[nt][3] = exp2f((sa[nt][3] - m1) * SC2);
            rs0 += sa[nt][0] + sa[nt][1];
            rs1 += sa[nt][2] + sa[nt][3];
        }
        rs0 += __shfl_xor_sync(0xffffffffu, rs0, 1);
        rs0 += __shfl_xor_sync(0xffffffffu, rs0, 2);
        rs1 += __shfl_xor_sync(0xffffffffu, rs1, 1);
        rs1 += __shfl_xor_sync(0xffffffffu, rs1, 2);
        l0 = l0 * al0 + rs0;
        l1 = l1 * al1 + rs1;

        #pragma unroll
        for (int nd = 0; nd < 8; nd++) {
            ao[nd][0] *= al0; ao[nd][1] *= al0;
            ao[nd][2] *= al1; ao[nd][3] *= al1;
        }

        // P -> fp16 A-fragments
        uint32_t ph[4][4];
        #pragma unroll
        for (int ks = 0; ks < 4; ks++) {
            #pragma unroll
            for (int hf = 0; hf < 2; hf++) {
                const float* s2 = sa[2 * ks + hf];
                ph[ks][0 + 2 * hf] = pack_h2(__float2half(s2[0]), __float2half(s2[1]));
                ph[ks][1 + 2 * hf] = pack_h2(__float2half(s2[2]), __float2half(s2[3]));
            }
        }

        // O += P V
        fl_pv_pass(ao, ph, st + 8192, v_row, v_cb);

        __syncthreads();
    }

    // write O (fp16, stride D_MODEL)
    const float inv0 = 1.0f / l0, inv1 = 1.0f / l1;
    const int g = l >> 2, t2 = (l & 3) * 2;
    const size_t row0 = rowbase + q0 + w * 16 + g;
    #pragma unroll
    for (int nd = 0; nd < 8; nd++) {
        const int col = colbase + nd * 8 + t2;
        store_h2(outh, row0 * D_MODEL + col, ao[nd][0] * inv0, ao[nd][1] * inv0);
        store_h2(outh, (row0 + 8) * D_MODEL + col, ao[nd][2] * inv1, ao[nd][3] * inv1);
    }
}

// ---------------------- unified weight conversion ----------------------------
__global__ __launch_bounds__(256) void conv_all(
    const float* __restrict__ Wq, const float* __restrict__ Wk,
    const float* __restrict__ Wv, const float* __restrict__ Wo,
    const float* __restrict__ W1, const float* __restrict__ W2,
    const float* __restrict__ bq, const float* __restrict__ bk,
    const float* __restrict__ bv,
    __half* __restrict__ wqkv, __half* __restrict__ wo,
    __half* __restrict__ w1, __half* __restrict__ w2,
    float* __restrict__ bqkv)
{
    const int t = blockIdx.x;
    if (t >= 12288) {
        int i = (t - 12288) * 256 + threadIdx.x;
        if (i < NQKV)
            bqkv[i] = (i < 1024) ? bq[i] : (i < 2048) ? bk[i - 1024] : bv[i - 2048];
        return;
    }

    const float* W; __half* T; int K, N, base;
    if (t < 3072) {
        int wsel = t >> 10;
        W = (wsel == 0) ? Wq : (wsel == 1) ? Wk : Wv;
        T = wqkv + (size_t)wsel * 1024 * 1024;
        K = 1024; N = 1024; base = t & 1023;
    } else if (t < 4096) { W = Wo; T = wo; K = 1024; N = 1024; base = t - 3072; }
    else if (t < 8192)   { W = W1; T = w1; K = 1024; N = 4096; base = t - 4096; }
    else                 { W = W2; T = w2; K = 4096; N = 1024; base = t - 8192; }

    const int ntiles = N >> 5;
    const int kt = base / ntiles, nt = base - kt * ntiles;
    const int n0 = nt * 32, k0 = kt * 32;

    __shared__ float tb[32][33];
    const int tx = threadIdx.x & 31, ty8 = threadIdx.x >> 5;
    #pragma unroll
    for (int j = 0; j < 4; j++) {
        int ky = ty8 + j * 8;
        tb[ky][tx] = W[(size_t)(k0 + ky) * N + n0 + tx];
    }
    __syncthreads();
    #pragma unroll
    for (int j = 0; j < 4; j++) {
        int ny = ty8 + j * 8;
        T[(size_t)(n0 + ny) * K + k0 + tx] = __float2half(tb[tx][ny]);
    }
}

// ---------------------------- LayerNorm -> fp16 ------------------------------
__global__ __launch_bounds__(256) void ln_kernel(
    const float* __restrict__ x, const float* __restrict__ scale,
    const float* __restrict__ bias, __half* __restrict__ y)
{
    const int row = blockIdx.x;
    const int tid = threadIdx.x;
    const float* xr = x + (size_t)row * D_MODEL;

    float4 v = *(const float4*)(xr + tid * 4);
    float s  = v.x + v.y + v.z + v.w;
    float sq = v.x*v.x + v.y*v.y + v.z*v.z + v.w*v.w;

    #pragma unroll
    for (int o = 16; o > 0; o >>= 1) {
        s  += __shfl_xor_sync(0xffffffffu, s,  o);
        sq += __shfl_xor_sync(0xffffffffu, sq, o);
    }
    __shared__ float rs[8], rq[8];
    int w = tid >> 5, l = tid & 31;
    if (l == 0) { rs[w] = s; rq[w] = sq; }
    __syncthreads();
    float ts = 0.f, tq = 0.f;
    #pragma unroll
    for (int i = 0; i < 8; i++) { ts += rs[i]; tq += rq[i]; }
    float mean = ts * (1.0f / D_MODEL);
    float var  = tq * (1.0f / D_MODEL) - mean * mean;
    float inv  = rsqrtf(var + 1e-6f);

    int c = tid * 4;
    float o0 = (v.x - mean) * inv * scale[c+0] + bias[c+0];
    float o1 = (v.y - mean) * inv * scale[c+1] + bias[c+1];
    float o2 = (v.z - mean) * inv * scale[c+2] + bias[c+2];
    float o3 = (v.w - mean) * inv * scale[c+3] + bias[c+3];
    size_t idx = (size_t)row * D_MODEL + c;
    store_h2(y, idx, o0, o1);
    store_h2(y, idx + 2, o2, o3);
}

// --------------------------------- launch -----------------------------------
extern "C" void kernel_launch(void* const* d_in, const int* in_sizes, int n_in,
                              void* d_out, int out_size)
{
    const float* x   = (const float*)d_in[0];
    const float* Wq  = (const float*)d_in[1];
    const float* bq  = (const float*)d_in[2];
    const float* Wk  = (const float*)d_in[3];
    const float* bk  = (const float*)d_in[4];
    const float* Wv  = (const float*)d_in[5];
    const float* bv  = (const float*)d_in[6];
    const float* Wo  = (const float*)d_in[7];
    const float* bo  = (const float*)d_in[8];
    const float* W1  = (const float*)d_in[9];
    const float* b1  = (const float*)d_in[10];
    const float* W2  = (const float*)d_in[11];
    const float* b2  = (const float*)d_in[12];
    const float* ln1s = (const float*)d_in[13];
    const float* ln1b = (const float*)d_in[14];
    const float* ln2s = (const float*)d_in[15];
    const float* ln2b = (const float*)d_in[16];
    float* out = (float*)d_out;

    float *x1, *bqkv;
    cudaGetSymbolAddress((void**)&x1,   g_x1);
    cudaGetSymbolAddress((void**)&bqkv, g_bqkv);

    __half *wqkv,*wo,*w1,*w2,*xs,*ff,*qkv;
    cudaGetSymbolAddress((void**)&wqkv, g_wqkvT);
    cudaGetSymbolAddress((void**)&wo,   g_woT);
    cudaGetSymbolAddress((void**)&w1,   g_w1T);
    cudaGetSymbolAddress((void**)&w2,   g_w2T);
    cudaGetSymbolAddress((void**)&xs,   g_xs);
    cudaGetSymbolAddress((void**)&ff,   g_ff);
    cudaGetSymbolAddress((void**)&qkv,  g_qkv);

    cudaFuncSetAttribute(mma_gemm<1>, cudaFuncAttributeMaxDynamicSharedMemorySize, SMEM_BYTES);
    cudaFuncSetAttribute(mma_gemm<2>, cudaFuncAttributeMaxDynamicSharedMemorySize, SMEM_BYTES);
    cudaFuncSetAttribute(mma_gemm<3>, cudaFuncAttributeMaxDynamicSharedMemorySize, SMEM_BYTES);
    cudaFuncSetAttribute(flash_kernel, cudaFuncAttributeMaxDynamicSharedMemorySize, FL_SMEM);

    // all weight conversions + bias concat: ONE launch
    conv_all<<<12300, 256>>>(Wq, Wk, Wv, Wo, W1, W2, bq, bk, bv,
                             wqkv, wo, w1, w2, bqkv);

    // 1) LN1 -> fp16
    ln_kernel<<<NROWS, 256>>>(x, ln1s, ln1b, xs);

    // 2) fused QKV projection -> qkv [row][3072]
    mma_gemm<3><<<dim3(NQKV/128, NROWS/128), 256, SMEM_BYTES>>>(
        xs, wqkv, bqkv, nullptr, nullptr, qkv, NROWS, NQKV, D_MODEL);

    // 3) flash attention -> xs  (Bq=64, 3 CTAs/SM)
    flash_kernel<<<dim3(SEQ/64, NBH), 128, FL_SMEM>>>(qkv, xs);

    // 4) x1 = x + attn @ Wo + bo (fp32)
    mma_gemm<2><<<dim3(D_MODEL/128, NROWS/128), 256, SMEM_BYTES>>>(
        xs, wo, bo, x, x1, nullptr, NROWS, D_MODEL, D_MODEL);

    // 5) LN2 -> fp16
    ln_kernel<<<NROWS, 256>>>(x1, ln2s, ln2b, xs);

    // 6) ff = relu(h @ W1 + b1) -> fp16
    mma_gemm<1><<<dim3(D_FF/128, NROWS/128), 256, SMEM_BYTES>>>(
        xs, w1, b1, nullptr, nullptr, ff, NROWS, D_FF, D_MODEL);

    // 7) out = x1 + ff @ W2 + b2 (fp32)
    mma_gemm<2><<<dim3(D_MODEL/128, NROWS/128), 256, SMEM_BYTES>>>(
        ff, w2, b2, x1, out, nullptr, NROWS, D_MODEL, D_FF);
}